// round 8
// baseline (speedup 1.0000x reference)
#include <cuda_runtime.h>
#include <cuda_bf16.h>
#include <cstdint>

#define NB     2048
#define NPAR   66048

// Scratch (device globals; allocation is forbidden)
__device__ __align__(16) float g_G [NB * 1024];            // X@Wk precomputed gates
__device__ __align__(16) float g_H [NB * 256];             // LSTM hidden outputs
__device__ __align__(16) __nv_bfloat16 g_Ah[NB * 256];     // X3 hi (bf16 split)
__device__ __align__(16) __nv_bfloat16 g_Al[NB * 256];     // X3 lo
__device__ __align__(16) __nv_bfloat16 g_Bh[(size_t)NPAR * 256]; // W^T hi, K-major [n][k]
__device__ __align__(16) __nv_bfloat16 g_Bl[(size_t)NPAR * 256]; // W^T lo

__device__ __forceinline__ float sigf(float x) { return 1.0f / (1.0f + __expf(-x)); }

__device__ __forceinline__ float2 fma2(float2 a, float2 b, float2 c) {
    unsigned long long A, Bv, C, D;
    asm("mov.b64 %0, {%1,%2};" : "=l"(A)  : "f"(a.x), "f"(a.y));
    asm("mov.b64 %0, {%1,%2};" : "=l"(Bv) : "f"(b.x), "f"(b.y));
    asm("mov.b64 %0, {%1,%2};" : "=l"(C)  : "f"(c.x), "f"(c.y));
    asm("fma.rn.f32x2 %0, %1, %2, %3;" : "=l"(D) : "l"(A), "l"(Bv), "l"(C));
    float2 r;
    asm("mov.b64 {%0,%1}, %2;" : "=f"(r.x), "=f"(r.y) : "l"(D));
    return r;
}

__device__ __forceinline__ unsigned smem_u32(const void* p) {
    unsigned a;
    asm("{ .reg .u64 t; cvta.to.shared.u64 t, %1; cvt.u32.u64 %0, t; }" : "=r"(a) : "l"(p));
    return a;
}

// ---- async-copy / HMMA helpers ---------------------------------------------
#define SWZ(x) ((x) ^ (((x) >> 3) & 0x70))

#define CP_ASYNC16(dst, src) \
    asm volatile("cp.async.cg.shared.global [%0], [%1], 16;" :: "r"(dst), "l"(src) : "memory")
#define CP_COMMIT()  asm volatile("cp.async.commit_group;" ::: "memory")
#define CP_WAIT_ALL() asm volatile("cp.async.wait_all;" ::: "memory")

#define LDSM_X4(r0, r1, r2, r3, addr) \
    asm volatile("ldmatrix.sync.aligned.m8n8.x4.shared.b16 {%0,%1,%2,%3}, [%4];" \
                 : "=r"(r0), "=r"(r1), "=r"(r2), "=r"(r3) : "r"(addr))

#define MMA16816(d, a, b0, b1) \
    asm volatile("mma.sync.aligned.m16n8k16.row.col.f32.bf16.bf16.f32 " \
                 "{%0,%1,%2,%3}, {%4,%5,%6,%7}, {%8,%9}, {%0,%1,%2,%3};" \
                 : "+f"((d)[0]), "+f"((d)[1]), "+f"((d)[2]), "+f"((d)[3]) \
                 : "r"((a)[0]), "r"((a)[1]), "r"((a)[2]), "r"((a)[3]), \
                   "r"(b0), "r"(b1))

// ===== kNop: capture-alignment dummy (makes kB the 4th launch of a call) ====
__global__ void kNop() {}

// ===== Kernel W: split+transpose W_out -> g_Bh/g_Bl K-major =================
__global__ __launch_bounds__(256) void kW(const float* __restrict__ Wout)
{
    __shared__ float sm[32 * 257];
    const int tid = threadIdx.x;
    const int n0  = blockIdx.x * 32;

    #pragma unroll 4
    for (int it = 0; it < 32; it++) {
        const int idx = it * 256 + tid;
        const int k = idx >> 5, j = idx & 31;
        sm[j * 257 + k] = Wout[(size_t)k * NPAR + n0 + j];
    }
    __syncthreads();

    const int j  = tid & 31;
    const int kq = tid >> 5;
    __nv_bfloat16* ph = g_Bh + (size_t)(n0 + j) * 256 + kq * 32;
    __nv_bfloat16* pl = g_Bl + (size_t)(n0 + j) * 256 + kq * 32;
    #pragma unroll
    for (int kk = 0; kk < 32; kk++) {
        const float w = sm[j * 257 + kq * 32 + kk];
        const __nv_bfloat16 hi = __float2bfloat16(w);
        const __nv_bfloat16 lo = __float2bfloat16(w - __bfloat162float(hi));
        ph[kk] = hi;
        pl[kk] = lo;
    }
}

// ===== Kernel A: cond path + dense_in + G = x_in @ Wk. 128 CTAs x 16 rows =====
__global__ __launch_bounds__(256) void kA(
    const float* __restrict__ actions, const float* __restrict__ obs,
    const float* __restrict__ Wci, const float* __restrict__ vci,
    const float* __restrict__ gci, const float* __restrict__ bci,
    const float* __restrict__ Wcl, const float* __restrict__ bcl,
    const float* __restrict__ Win, const float* __restrict__ vin,
    const float* __restrict__ gin, const float* __restrict__ bin,
    const float* __restrict__ Wk)
{
    __shared__ float sm1[16 * 256];
    __shared__ float sm2[16 * 256];
    const int tid = threadIdx.x;
    const int r0  = blockIdx.x * 16;

    { // t1 = actions @ Wci -> sm1[16][64]
        const int j = tid & 63, rr = tid >> 6;
        #pragma unroll
        for (int q = 0; q < 4; q++) {
            const int r = rr + q * 4;
            float acc = 0.f;
            #pragma unroll
            for (int k = 0; k < 16; k++)
                acc += actions[(r0 + r) * 16 + k] * Wci[k * 64 + j];
            sm1[r * 64 + j] = acc;
        }
    }
    __syncthreads();
    { // evonorm(groups=8) -> sm2[16][64]
        const int j = tid & 63, rr = tid >> 6;
        const float v = vci[j], g = gci[j], bb = bci[j];
        #pragma unroll
        for (int q = 0; q < 4; q++) {
            const int r = rr + q * 4;
            const float* row = &sm1[r * 64 + (j & ~7)];
            float s1 = 0.f, s2 = 0.f;
            #pragma unroll
            for (int e = 0; e < 8; e++) { float t = row[e]; s1 += t; s2 += t * t; }
            const float mean = s1 * 0.125f;
            const float var  = s2 * 0.125f - mean * mean;
            const float x = sm1[r * 64 + j];
            sm2[r * 64 + j] = x * sigf(v * x) / sqrtf(var + 1e-5f) * g + bb;
        }
    }
    __syncthreads();
    { // x = a1 @ Wcl + bcl + obs -> sm1[16][64]
        const int j = tid & 63, rr = tid >> 6;
        const float bj = bcl[j];
        float acc[4];
        #pragma unroll
        for (int q = 0; q < 4; q++)
            acc[q] = bj + obs[(r0 + rr + q * 4) * 64 + j];
        for (int k = 0; k < 64; k++) {
            const float w = Wcl[k * 64 + j];
            #pragma unroll
            for (int q = 0; q < 4; q++)
                acc[q] += sm2[(rr + q * 4) * 64 + k] * w;
        }
        #pragma unroll
        for (int q = 0; q < 4; q++)
            sm1[(rr + q * 4) * 64 + j] = acc[q];
    }
    __syncthreads();
    { // t2 = x @ Win -> sm2[16][256]
        const int j = tid;
        float acc[16];
        #pragma unroll
        for (int r = 0; r < 16; r++) acc[r] = 0.f;
        for (int k = 0; k < 64; k++) {
            const float w = Win[k * 256 + j];
            #pragma unroll
            for (int r = 0; r < 16; r++) acc[r] += sm1[r * 64 + k] * w;
        }
        #pragma unroll
        for (int r = 0; r < 16; r++) sm2[r * 256 + j] = acc[r];
    }
    __syncthreads();
    { // evonorm(group size 8) -> sm1[16][256]
        const int j = tid;
        const float v = vin[j], g = gin[j], bb = bin[j];
        for (int r = 0; r < 16; r++) {
            const float* row = &sm2[r * 256 + (j & ~7)];
            float s1 = 0.f, s2 = 0.f;
            #pragma unroll
            for (int e = 0; e < 8; e++) { float t = row[e]; s1 += t; s2 += t * t; }
            const float mean = s1 * 0.125f;
            const float var  = s2 * 0.125f - mean * mean;
            const float x = sm2[r * 256 + j];
            sm1[r * 256 + j] = x * sigf(v * x) / sqrtf(var + 1e-5f) * g + bb;
        }
    }
    __syncthreads();
    { // G = x_in @ Wk  (thread: 4 cols x 16 rows)
        const int c0 = tid * 4;
        float2 acc[16][2];
        #pragma unroll
        for (int r = 0; r < 16; r++) { acc[r][0] = make_float2(0.f,0.f); acc[r][1] = make_float2(0.f,0.f); }
        for (int k = 0; k < 256; k++) {
            const float4 w4 = *(const float4*)&Wk[k * 1024 + c0];
            const float2 wa = make_float2(w4.x, w4.y);
            const float2 wb = make_float2(w4.z, w4.w);
            #pragma unroll
            for (int r = 0; r < 16; r++) {
                const float x = sm1[r * 256 + k];
                const float2 xx = make_float2(x, x);
                acc[r][0] = fma2(wa, xx, acc[r][0]);
                acc[r][1] = fma2(wb, xx, acc[r][1]);
            }
        }
        #pragma unroll
        for (int r = 0; r < 16; r++) {
            float4 o;
            o.x = acc[r][0].x; o.y = acc[r][0].y; o.z = acc[r][1].x; o.w = acc[r][1].y;
            *(float4*)&g_G[(size_t)(r0 + r) * 1024 + c0] = o;
        }
    }
}

// ===== Kernel B: sequential LSTM, 8-CTA cluster, push-based h broadcast =====
// CTA r owns channels [r*32, r*32+32) -> gate columns {g*256 + r*32 + c}.
// Cell fully CTA-local; h pushed to peers via st.shared::cluster + mbarrier.
// GEMV uses plain scalar FFMA (no f32x2 pack/unpack bloat).
__global__ void __launch_bounds__(512, 1) __cluster_dims__(8, 1, 1)
kB(const float* __restrict__ Wr, const float* __restrict__ vl_,
   const float* __restrict__ gl_, const float* __restrict__ bl_)
{
    __shared__ __align__(16) float s_hb[2][256];   // h buffers (remote-written)
    __shared__ __align__(16) float s_z[128];       // local z (this CTA's 128 cols)
    __shared__ __align__(16) float s_hout[32];     // this CTA's fresh h
    __shared__ __align__(8)  unsigned long long s_mbar[2];

    const int tid = threadIdx.x;
    unsigned rank;
    asm("mov.u32 %0, %%cluster_ctarank;" : "=r"(rank));

    const int lcol  = tid >> 2;              // 0..127: g*32 + c
    const int kpart = tid & 3;
    const int gg    = lcol >> 5;             // gate 0..3 (i,f,cc,o)
    const int cc_   = lcol & 31;             // channel-in-CTA
    const int gcol  = gg * 256 + (int)rank * 32 + cc_;
    const int k0    = kpart * 64;

    // register-resident weights: 64 fp32 per thread, as 16 float4
    float4 wv4[16];
    #pragma unroll
    for (int i = 0; i < 16; i++) {
        wv4[i].x = Wr[(size_t)(k0 + 4*i)     * 1024 + gcol];
        wv4[i].y = Wr[(size_t)(k0 + 4*i + 1) * 1024 + gcol];
        wv4[i].z = Wr[(size_t)(k0 + 4*i + 2) * 1024 + gcol];
        wv4[i].w = Wr[(size_t)(k0 + 4*i + 3) * 1024 + gcol];
    }

    // cell params for warp 0 (channel ch = rank*32 + lane)
    float vl = 0.f, gl = 0.f, bl = 0.f, cst = 0.f;
    if (tid < 32) {
        const int ch = (int)rank * 32 + tid;
        vl = vl_[ch]; gl = gl_[ch]; bl = bl_[ch];
    }

    // remote store/arrive addresses: warp w pushes to dest rank w, lane = channel
    unsigned r_h0 = 0, r_h1 = 0, r_b0 = 0, r_b1 = 0;
    if (tid < 256) {
        const unsigned w  = (unsigned)(tid >> 5);
        const unsigned ci = (unsigned)(tid & 31);
        unsigned lh0 = smem_u32(&s_hb[0][rank * 32 + ci]);
        unsigned lh1 = smem_u32(&s_hb[1][rank * 32 + ci]);
        unsigned lb0 = smem_u32(&s_mbar[0]);
        unsigned lb1 = smem_u32(&s_mbar[1]);
        asm("mapa.shared::cluster.u32 %0, %1, %2;" : "=r"(r_h0) : "r"(lh0), "r"(w));
        asm("mapa.shared::cluster.u32 %0, %1, %2;" : "=r"(r_h1) : "r"(lh1), "r"(w));
        asm("mapa.shared::cluster.u32 %0, %1, %2;" : "=r"(r_b0) : "r"(lb0), "r"(w));
        asm("mapa.shared::cluster.u32 %0, %1, %2;" : "=r"(r_b1) : "r"(lb1), "r"(w));
    }

    if (tid == 0) {
        asm volatile("mbarrier.init.shared.b64 [%0], %1;" :: "r"(smem_u32(&s_mbar[0])), "r"(256u) : "memory");
        asm volatile("mbarrier.init.shared.b64 [%0], %1;" :: "r"(smem_u32(&s_mbar[1])), "r"(256u) : "memory");
    }
    if (tid < 256) { s_hb[0][tid] = 0.f; s_hb[1][tid] = 0.f; }
    __syncthreads();
    asm volatile("barrier.cluster.arrive.aligned;" ::: "memory");
    asm volatile("barrier.cluster.wait.aligned;"   ::: "memory");

    // initial broadcast: zeros into buffer 1 (h_{-1} = 0)
    if (tid < 256) {
        asm volatile("st.shared::cluster.f32 [%0], %1;" :: "r"(r_h1), "f"(0.f) : "memory");
        asm volatile("mbarrier.arrive.release.cluster.shared::cluster.b64 _, [%0];"
                     :: "r"(r_b1) : "memory");
    }

    unsigned par[2] = {0u, 0u};
    float gt = (kpart == 0) ? g_G[gcol] : 0.f;   // prefetch step 0

    for (int t = 0; t < NB; t++) {
        const int rb = (t + 1) & 1;        // buffer holding h_{t-1}
        const int wb = t & 1;              // buffer receiving h_t

        { // wait for all h_{t-1} pushes (acquire, cluster scope)
            const unsigned a = smem_u32(&s_mbar[rb]);
            const unsigned ph = par[rb];
            unsigned done;
            asm volatile(
                "{\n\t.reg .pred p;\n\t"
                "mbarrier.try_wait.parity.acquire.cluster.shared::cta.b64 p, [%1], %2;\n\t"
                "selp.b32 %0, 1, 0, p;\n\t}"
                : "=r"(done) : "r"(a), "r"(ph) : "memory");
            if (!done) {
                asm volatile(
                    "{\n\t.reg .pred P1;\n\t"
                    "WLB_%=:\n\t"
                    "mbarrier.try_wait.parity.acquire.cluster.shared::cta.b64 P1, [%0], %1, 0x989680;\n\t"
                    "@P1 bra.uni WDB_%=;\n\t"
                    "bra.uni WLB_%=;\n\t"
                    "WDB_%=:\n\t}"
                    :: "r"(a), "r"(ph) : "memory");
            }
            par[rb] ^= 1u;
        }

        // GEMV partial: plain scalar FFMA, 4 independent chains
        float a0 = 0.f, a1 = 0.f, a2 = 0.f, a3 = 0.f;
        const float4* h4 = (const float4*)(&s_hb[rb][k0]);
        #pragma unroll
        for (int i = 0; i < 16; i++) {
            const float4 h = h4[i];
            a0 = fmaf(wv4[i].x, h.x, a0);
            a1 = fmaf(wv4[i].y, h.y, a1);
            a2 = fmaf(wv4[i].z, h.z, a2);
            a3 = fmaf(wv4[i].w, h.w, a3);
        }
        float sum = (a0 + a1) + (a2 + a3);
        sum += __shfl_xor_sync(0xffffffffu, sum, 1);
        sum += __shfl_xor_sync(0xffffffffu, sum, 2);
        if (kpart == 0) s_z[lcol] = sum + gt;

        // prefetch next step's gate term
        if (kpart == 0 && t + 1 < NB) gt = g_G[(size_t)(t + 1) * 1024 + gcol];

        __syncthreads();

        // cell: warp 0, lane = channel-in-CTA (fully local)
        if (tid < 32) {
            const float zi = s_z[tid];
            const float zf = s_z[32 + tid];
            const float zc = s_z[64 + tid];
            const float zo = s_z[96 + tid];

            float s1 = zc, s2 = zc * zc;
            s1 += __shfl_xor_sync(0xffffffffu, s1, 1);  s2 += __shfl_xor_sync(0xffffffffu, s2, 1);
            s1 += __shfl_xor_sync(0xffffffffu, s1, 2);  s2 += __shfl_xor_sync(0xffffffffu, s2, 2);
            s1 += __shfl_xor_sync(0xffffffffu, s1, 4);  s2 += __shfl_xor_sync(0xffffffffu, s2, 4);
            float mean = s1 * 0.125f;
            float var  = s2 * 0.125f - mean * mean;
            const float ecc = zc * sigf(vl * zc) / sqrtf(var + 1e-5f) * gl + bl;

            cst = sigf(zf) * cst + sigf(zi) * ecc;

            s1 = cst; s2 = cst * cst;
            s1 += __shfl_xor_sync(0xffffffffu, s1, 1);  s2 += __shfl_xor_sync(0xffffffffu, s2, 1);
            s1 += __shfl_xor_sync(0xffffffffu, s1, 2);  s2 += __shfl_xor_sync(0xffffffffu, s2, 2);
            s1 += __shfl_xor_sync(0xffffffffu, s1, 4);  s2 += __shfl_xor_sync(0xffffffffu, s2, 4);
            mean = s1 * 0.125f;
            var  = s2 * 0.125f - mean * mean;
            const float ecn = cst * sigf(vl * cst) / sqrtf(var + 1e-5f) * gl + bl;

            const float h = sigf(zo) * ecn;
            g_H[(size_t)t * 256 + rank * 32 + tid] = h;
            s_hout[tid] = h;
        }
        __syncthreads();

        // push h_t to all 8 CTAs (incl. self): warp w -> dest rank w
        if (tid < 256) {
            const float h = s_hout[tid & 31];
            const unsigned rh = wb ? r_h1 : r_h0;
            const unsigned rb2 = wb ? r_b1 : r_b0;
            asm volatile("st.shared::cluster.f32 [%0], %1;" :: "r"(rh), "f"(h) : "memory");
            asm volatile("mbarrier.arrive.release.cluster.shared::cluster.b64 _, [%0];"
                         :: "r"(rb2) : "memory");
        }
    }

    asm volatile("barrier.cluster.arrive.aligned;" ::: "memory");
    asm volatile("barrier.cluster.wait.aligned;"   ::: "memory");
}

// ===== Kernel C: dense_0 + evonorm -> bf16 hi/lo split (g_Ah/g_Al) ==========
__global__ __launch_bounds__(256) void kC(
    const float* __restrict__ Wd0, const float* __restrict__ vd,
    const float* __restrict__ gd,  const float* __restrict__ bd)
{
    __shared__ float sm1[16 * 256];
    __shared__ float sm2[16 * 256];
    const int tid = threadIdx.x;
    const int r0  = blockIdx.x * 16;

    const float4* src = (const float4*)(g_H + (size_t)r0 * 256);
    for (int i = tid; i < 1024; i += 256)
        ((float4*)sm1)[i] = src[i];
    __syncthreads();

    const int j = tid;
    float acc[16];
    #pragma unroll
    for (int r = 0; r < 16; r++) acc[r] = 0.f;
    for (int k4 = 0; k4 < 64; k4++) {
        const int k = k4 * 4;
        const float w0 = Wd0[(k+0)*256 + j];
        const float w1 = Wd0[(k+1)*256 + j];
        const float w2 = Wd0[(k+2)*256 + j];
        const float w3 = Wd0[(k+3)*256 + j];
        #pragma unroll
        for (int r = 0; r < 16; r++) {
            const float4 x = *(const float4*)&sm1[r * 256 + k];
            acc[r] += x.x*w0 + x.y*w1 + x.z*w2 + x.w*w3;
        }
    }
    #pragma unroll
    for (int r = 0; r < 16; r++) sm2[r * 256 + j] = acc[r];
    __syncthreads();

    const float v = vd[j], g = gd[j], bb = bd[j];
    for (int r = 0; r < 16; r++) {
        const float* row = &sm2[r * 256 + (j & ~7)];
        float s1 = 0.f, s2 = 0.f;
        #pragma unroll
        for (int e = 0; e < 8; e++) { float t = row[e]; s1 += t; s2 += t * t; }
        const float mean = s1 * 0.125f;
        const float var  = s2 * 0.125f - mean * mean;
        const float x = sm2[r * 256 + j];
        const float y = x * sigf(v * x) / sqrtf(var + 1e-5f) * g + bb;
        const __nv_bfloat16 hi = __float2bfloat16(y);
        const __nv_bfloat16 lo = __float2bfloat16(y - __bfloat162float(hi));
        g_Ah[(size_t)(r0 + r) * 256 + j] = hi;
        g_Al[(size_t)(r0 + r) * 256 + j] = lo;
    }
}

// ===== Kernel D: HMMA bf16 3-split GEMM, CTA tile 128x128, serial K chunks ==
#define KD_SMEM 65536

__global__ void __launch_bounds__(256, 2)
kD(const float* __restrict__ bout, float* __restrict__ out)
{
    extern __shared__ __align__(1024) char smem[];
    const uint32_t ST = smem_u32(smem);
    const int tid = threadIdx.x;
    const int wid = tid >> 5, lane = tid & 31;
    const int warp_m = wid & 1;
    const int warp_n = wid >> 1;
    const int n0 = blockIdx.x * 128;
    const int m0 = blockIdx.y * 128;

    const uint32_t a_row = warp_m * 64 + (lane & 15);
    const uint32_t a_kb  = (uint32_t)(lane >> 4) * 16;
    const uint32_t b_row = warp_n * 32 + (lane & 7) + ((lane >> 4) & 1) * 8;
    const uint32_t b_kb  = (uint32_t)((lane >> 3) & 1) * 16;

    float acc[4][4][4];
    #pragma unroll
    for (int i = 0; i < 4; i++)
        #pragma unroll
        for (int j = 0; j < 4; j++)
            #pragma unroll
            for (int q = 0; q < 4; q++) acc[i][j][q] = 0.f;

    for (int kc = 0; kc < 4; kc++) {
        const int koff = kc * 64;
        #pragma unroll
        for (int sp = 0; sp < 2; sp++) {
            const __nv_bfloat16* gA = sp ? g_Al : g_Ah;
            const uint32_t db = ST + sp * 16384;
            #pragma unroll
            for (int i = 0; i < 4; i++) {
                const int g = tid + i * 256;
                const int row = g >> 3, j = g & 7;
                CP_ASYNC16(db + SWZ(row * 128 + j * 16),
                           gA + (size_t)(m0 + row) * 256 + koff + j * 8);
            }
        }
        #pragma unroll
        for (int sp = 0; sp < 2; sp++) {
            const __nv_bfloat16* gB = sp ? g_Bl : g_Bh;
            const uint32_t db = ST + 32768 + sp * 16384;
            #pragma unroll
            for (int i = 0; i < 4; i++) {
                const int g = tid + i * 256;
                const int row = g >> 3, j = g & 7;
                CP_ASYNC16(db + SWZ(row * 128 + j * 16),
                           gB + (size_t)(n0 + row) * 256 + koff + j * 8);
            }
        }
        CP_COMMIT();
        CP_WAIT_ALL();
        __syncthreads();

        #pragma unroll
        for (int split = 0; split < 3; split++) {
            const uint32_t Abase = ST + (split == 2 ? 16384u : 0u);
            const uint32_t Bbase = ST + 32768u + (split == 1 ? 16384u : 0u);
            #pragma unroll
            for (int ks = 0; ks < 4; ks++) {
                const uint32_t kk2 = (uint32_t)ks * 32;
                uint32_t af[4][4];
                #pragma unroll
                for (int mb = 0; mb < 4; mb++) {
                    const uint32_t addr = Abase + SWZ((a_row + mb * 16) * 128 + kk2 + a_kb);
                    LDSM_X4(af[mb][0], af[mb][1], af[mb][2], af[mb][3], addr);
                }
                uint32_t bfr[2][4];
                #pragma unroll
                for (int nb2 = 0; nb2 < 2; nb2++) {
                    const uint32_t addr = Bbase + SWZ((b_row + nb2 * 16) * 128 + kk2 + b_kb);
                    LDSM_X4(bfr[nb2][0], bfr[nb2][1], bfr[nb2][2], bfr[nb2][3], addr);
                }
                #pragma unroll
                for (int mb = 0; mb < 4; mb++) {
                    MMA16816(acc[mb][0], af[mb], bfr[0][0], bfr[0][1]);
                    MMA16816(acc[mb][1], af[mb], bfr[0][2], bfr[0][3]);
                    MMA16816(acc[mb][2], af[mb], bfr[1][0], bfr[1][1]);
                    MMA16816(acc[mb][3], af[mb], bfr[1][2], bfr[1][3]);
                }
            }
        }
        __syncthreads();
    }

    #pragma unroll
    for (int nb = 0; nb < 4; nb++) {
        const int col = n0 + warp_n * 32 + nb * 8 + (lane & 3) * 2;
        const float2 bb = *(const float2*)&bout[col];
        #pragma unroll
        for (int mb = 0; mb < 4; mb++) {
            const int row = m0 + warp_m * 64 + mb * 16 + (lane >> 2);
            float2 v0, v1;
            v0.x = acc[mb][nb][0] + bb.x;  v0.y = acc[mb][nb][1] + bb.y;
            v1.x = acc[mb][nb][2] + bb.x;  v1.y = acc[mb][nb][3] + bb.y;
            *(float2*)&out[(size_t)row * NPAR + col]       = v0;
            *(float2*)&out[(size_t)(row + 8) * NPAR + col] = v1;
        }
    }
}

// ============================================================================
extern "C" void kernel_launch(void* const* d_in, const int* in_sizes, int n_in,
                              void* d_out, int out_size)
{
    const float* actions = (const float*)d_in[0];
    const float* obs     = (const float*)d_in[1];
    const float* Wci     = (const float*)d_in[2];
    const float* vci     = (const float*)d_in[3];
    const float* gci     = (const float*)d_in[4];
    const float* bci     = (const float*)d_in[5];
    const float* Wcl     = (const float*)d_in[6];
    const float* bcl     = (const float*)d_in[7];
    const float* Win     = (const float*)d_in[8];
    const float* vin     = (const float*)d_in[9];
    const float* gin     = (const float*)d_in[10];
    const float* bin     = (const float*)d_in[11];
    const float* Wk      = (const float*)d_in[12];
    const float* Wr      = (const float*)d_in[13];
    const float* vl      = (const float*)d_in[14];
    const float* gl      = (const float*)d_in[15];
    const float* bl      = (const float*)d_in[16];
    const float* Wd0     = (const float*)d_in[17];
    const float* vd0     = (const float*)d_in[18];
    const float* gd0     = (const float*)d_in[19];
    const float* bd0     = (const float*)d_in[20];
    const float* Wout    = (const float*)d_in[21];
    const float* bout    = (const float*)d_in[22];
    float* out = (float*)d_out;

    kW<<<NPAR / 32, 256>>>(Wout);
    kA<<<128, 256>>>(actions, obs, Wci, vci, gci, bci, Wcl, bcl,
                     Win, vin, gin, bin, Wk);
    kNop<<<1, 32>>>();   // capture-alignment: makes kB the 4th launch
    kB<<<8, 512>>>(Wr, vl, gl, bl);
    kC<<<128, 256>>>(Wd0, vd0, gd0, bd0);

    cudaFuncSetAttribute(kD, cudaFuncAttributeMaxDynamicSharedMemorySize, KD_SMEM);
    dim3 gD(NPAR / 128, NB / 128);
    kD<<<gD, 256, KD_SMEM>>>(bout, out);
}

// round 9
// speedup vs baseline: 1.8744x; 1.8744x over previous
#include <cuda_runtime.h>
#include <cuda_bf16.h>
#include <cstdint>

#define NB     2048
#define NPAR   66048

// Scratch (device globals; allocation is forbidden)
__device__ __align__(16) float g_G [NB * 1024];            // X@Wk precomputed gates
__device__ __align__(16) float g_H [NB * 256];             // LSTM hidden outputs
__device__ __align__(16) __nv_bfloat16 g_Ah[NB * 256];     // X3 hi (bf16 split)
__device__ __align__(16) __nv_bfloat16 g_Al[NB * 256];     // X3 lo
__device__ __align__(16) __nv_bfloat16 g_Bh[(size_t)NPAR * 256]; // W^T hi, K-major [n][k]
__device__ __align__(16) __nv_bfloat16 g_Bl[(size_t)NPAR * 256]; // W^T lo

__device__ __forceinline__ float sigf(float x) { return 1.0f / (1.0f + __expf(-x)); }

__device__ __forceinline__ float2 fma2(float2 a, float2 b, float2 c) {
    unsigned long long A, Bv, C, D;
    asm("mov.b64 %0, {%1,%2};" : "=l"(A)  : "f"(a.x), "f"(a.y));
    asm("mov.b64 %0, {%1,%2};" : "=l"(Bv) : "f"(b.x), "f"(b.y));
    asm("mov.b64 %0, {%1,%2};" : "=l"(C)  : "f"(c.x), "f"(c.y));
    asm("fma.rn.f32x2 %0, %1, %2, %3;" : "=l"(D) : "l"(A), "l"(Bv), "l"(C));
    float2 r;
    asm("mov.b64 {%0,%1}, %2;" : "=f"(r.x), "=f"(r.y) : "l"(D));
    return r;
}

__device__ __forceinline__ unsigned smem_u32(const void* p) {
    unsigned a;
    asm("{ .reg .u64 t; cvta.to.shared.u64 t, %1; cvt.u32.u64 %0, t; }" : "=r"(a) : "l"(p));
    return a;
}

// ---- async-copy / HMMA helpers ---------------------------------------------
#define SWZ(x) ((x) ^ (((x) >> 3) & 0x70))

#define CP_ASYNC16(dst, src) \
    asm volatile("cp.async.cg.shared.global [%0], [%1], 16;" :: "r"(dst), "l"(src) : "memory")
#define CP_COMMIT()  asm volatile("cp.async.commit_group;" ::: "memory")
#define CP_WAIT_ALL() asm volatile("cp.async.wait_all;" ::: "memory")

#define LDSM_X4(r0, r1, r2, r3, addr) \
    asm volatile("ldmatrix.sync.aligned.m8n8.x4.shared.b16 {%0,%1,%2,%3}, [%4];" \
                 : "=r"(r0), "=r"(r1), "=r"(r2), "=r"(r3) : "r"(addr))

#define MMA16816(d, a, b0, b1) \
    asm volatile("mma.sync.aligned.m16n8k16.row.col.f32.bf16.bf16.f32 " \
                 "{%0,%1,%2,%3}, {%4,%5,%6,%7}, {%8,%9}, {%0,%1,%2,%3};" \
                 : "+f"((d)[0]), "+f"((d)[1]), "+f"((d)[2]), "+f"((d)[3]) \
                 : "r"((a)[0]), "r"((a)[1]), "r"((a)[2]), "r"((a)[3]), \
                   "r"(b0), "r"(b1))

// ===== Kernel W: split+transpose W_out -> g_Bh/g_Bl K-major =================
__global__ __launch_bounds__(256) void kW(const float* __restrict__ Wout)
{
    __shared__ float sm[32 * 257];
    const int tid = threadIdx.x;
    const int n0  = blockIdx.x * 32;

    #pragma unroll 4
    for (int it = 0; it < 32; it++) {
        const int idx = it * 256 + tid;
        const int k = idx >> 5, j = idx & 31;
        sm[j * 257 + k] = Wout[(size_t)k * NPAR + n0 + j];
    }
    __syncthreads();

    const int j  = tid & 31;
    const int kq = tid >> 5;
    __nv_bfloat16* ph = g_Bh + (size_t)(n0 + j) * 256 + kq * 32;
    __nv_bfloat16* pl = g_Bl + (size_t)(n0 + j) * 256 + kq * 32;
    #pragma unroll
    for (int kk = 0; kk < 32; kk++) {
        const float w = sm[j * 257 + kq * 32 + kk];
        const __nv_bfloat16 hi = __float2bfloat16(w);
        const __nv_bfloat16 lo = __float2bfloat16(w - __bfloat162float(hi));
        ph[kk] = hi;
        pl[kk] = lo;
    }
}

// ===== Kernel A: cond path + dense_in + G = x_in @ Wk. 128 CTAs x 16 rows =====
__global__ __launch_bounds__(256) void kA(
    const float* __restrict__ actions, const float* __restrict__ obs,
    const float* __restrict__ Wci, const float* __restrict__ vci,
    const float* __restrict__ gci, const float* __restrict__ bci,
    const float* __restrict__ Wcl, const float* __restrict__ bcl,
    const float* __restrict__ Win, const float* __restrict__ vin,
    const float* __restrict__ gin, const float* __restrict__ bin,
    const float* __restrict__ Wk)
{
    __shared__ float sm1[16 * 256];
    __shared__ float sm2[16 * 256];
    const int tid = threadIdx.x;
    const int r0  = blockIdx.x * 16;

    { // t1 = actions @ Wci -> sm1[16][64]
        const int j = tid & 63, rr = tid >> 6;
        #pragma unroll
        for (int q = 0; q < 4; q++) {
            const int r = rr + q * 4;
            float acc = 0.f;
            #pragma unroll
            for (int k = 0; k < 16; k++)
                acc += actions[(r0 + r) * 16 + k] * Wci[k * 64 + j];
            sm1[r * 64 + j] = acc;
        }
    }
    __syncthreads();
    { // evonorm(groups=8) -> sm2[16][64]
        const int j = tid & 63, rr = tid >> 6;
        const float v = vci[j], g = gci[j], bb = bci[j];
        #pragma unroll
        for (int q = 0; q < 4; q++) {
            const int r = rr + q * 4;
            const float* row = &sm1[r * 64 + (j & ~7)];
            float s1 = 0.f, s2 = 0.f;
            #pragma unroll
            for (int e = 0; e < 8; e++) { float t = row[e]; s1 += t; s2 += t * t; }
            const float mean = s1 * 0.125f;
            const float var  = s2 * 0.125f - mean * mean;
            const float x = sm1[r * 64 + j];
            sm2[r * 64 + j] = x * sigf(v * x) / sqrtf(var + 1e-5f) * g + bb;
        }
    }
    __syncthreads();
    { // x = a1 @ Wcl + bcl + obs -> sm1[16][64]
        const int j = tid & 63, rr = tid >> 6;
        const float bj = bcl[j];
        float acc[4];
        #pragma unroll
        for (int q = 0; q < 4; q++)
            acc[q] = bj + obs[(r0 + rr + q * 4) * 64 + j];
        for (int k = 0; k < 64; k++) {
            const float w = Wcl[k * 64 + j];
            #pragma unroll
            for (int q = 0; q < 4; q++)
                acc[q] += sm2[(rr + q * 4) * 64 + k] * w;
        }
        #pragma unroll
        for (int q = 0; q < 4; q++)
            sm1[(rr + q * 4) * 64 + j] = acc[q];
    }
    __syncthreads();
    { // t2 = x @ Win -> sm2[16][256]
        const int j = tid;
        float acc[16];
        #pragma unroll
        for (int r = 0; r < 16; r++) acc[r] = 0.f;
        for (int k = 0; k < 64; k++) {
            const float w = Win[k * 256 + j];
            #pragma unroll
            for (int r = 0; r < 16; r++) acc[r] += sm1[r * 64 + k] * w;
        }
        #pragma unroll
        for (int r = 0; r < 16; r++) sm2[r * 256 + j] = acc[r];
    }
    __syncthreads();
    { // evonorm(group size 8) -> sm1[16][256]
        const int j = tid;
        const float v = vin[j], g = gin[j], bb = bin[j];
        for (int r = 0; r < 16; r++) {
            const float* row = &sm2[r * 256 + (j & ~7)];
            float s1 = 0.f, s2 = 0.f;
            #pragma unroll
            for (int e = 0; e < 8; e++) { float t = row[e]; s1 += t; s2 += t * t; }
            const float mean = s1 * 0.125f;
            const float var  = s2 * 0.125f - mean * mean;
            const float x = sm2[r * 256 + j];
            sm1[r * 256 + j] = x * sigf(v * x) / sqrtf(var + 1e-5f) * g + bb;
        }
    }
    __syncthreads();
    { // G = x_in @ Wk  (thread: 4 cols x 16 rows)
        const int c0 = tid * 4;
        float2 acc[16][2];
        #pragma unroll
        for (int r = 0; r < 16; r++) { acc[r][0] = make_float2(0.f,0.f); acc[r][1] = make_float2(0.f,0.f); }
        for (int k = 0; k < 256; k++) {
            const float4 w4 = *(const float4*)&Wk[k * 1024 + c0];
            const float2 wa = make_float2(w4.x, w4.y);
            const float2 wb = make_float2(w4.z, w4.w);
            #pragma unroll
            for (int r = 0; r < 16; r++) {
                const float x = sm1[r * 256 + k];
                const float2 xx = make_float2(x, x);
                acc[r][0] = fma2(wa, xx, acc[r][0]);
                acc[r][1] = fma2(wb, xx, acc[r][1]);
            }
        }
        #pragma unroll
        for (int r = 0; r < 16; r++) {
            float4 o;
            o.x = acc[r][0].x; o.y = acc[r][0].y; o.z = acc[r][1].x; o.w = acc[r][1].y;
            *(float4*)&g_G[(size_t)(r0 + r) * 1024 + c0] = o;
        }
    }
}

// ===== Kernel B: sequential LSTM, 8-CTA cluster =============================
// Thread (g, kw): g = col-group (8 cols), kw = k-window (8 k's).
// GEMV: 2-phase smem reduce. h broadcast: warp0 lanes 0-7 push 32 h as 8x
// st.shared::cluster.v4 to dest CTA (lane = dest) + ONE release-arrive each.
// mbarrier expected arrivals = 8 (one per source CTA).
__global__ void __launch_bounds__(512, 1) __cluster_dims__(8, 1, 1)
kB(const float* __restrict__ Wr, const float* __restrict__ vl_,
   const float* __restrict__ gl_, const float* __restrict__ bl_)
{
    __shared__ __align__(16) float s_hb[2][256];    // h buffers (remote-written)
    __shared__ __align__(16) float s_part[32 * 128]; // GEMV partials, 16KB
    __shared__ __align__(16) float s_z[128];
    __shared__ __align__(16) float s_hout[32];
    __shared__ __align__(8)  unsigned long long s_mbar[2];

    const int tid = threadIdx.x;
    unsigned rank;
    asm("mov.u32 %0, %%cluster_ctarank;" : "=r"(rank));

    const int g   = tid & 15;        // col-group: cols [g*8, g*8+8)
    const int kw  = tid >> 4;        // k-window:  k    [kw*8, kw*8+8)
    const int gg  = g >> 2;          // gate 0..3
    const int cc0 = (g & 3) * 8;     // channel base within this CTA's 32
    const int gcol0 = gg * 256 + (int)rank * 32 + cc0;   // global col of c=0

    // register-resident weights: w[j][c], 64 fp32 per thread
    float w[8][8];
    #pragma unroll
    for (int j = 0; j < 8; j++)
        #pragma unroll
        for (int c = 0; c < 8; c++)
            w[j][c] = Wr[(size_t)(kw * 8 + j) * 1024 + gcol0 + c];

    // cell params for warp 0 (channel ch = rank*32 + lane)
    float vl = 0.f, gl = 0.f, bl = 0.f, cst = 0.f;
    if (tid < 32) {
        const int ch = (int)rank * 32 + tid;
        vl = vl_[ch]; gl = gl_[ch]; bl = bl_[ch];
    }

    // push addresses for warp0 lanes 0-7 (lane = dest CTA)
    unsigned r_h0 = 0, r_h1 = 0, r_b0 = 0, r_b1 = 0;
    if (tid < 8) {
        const unsigned d = (unsigned)tid;
        unsigned lh0 = smem_u32(&s_hb[0][rank * 32]);
        unsigned lh1 = smem_u32(&s_hb[1][rank * 32]);
        unsigned lb0 = smem_u32(&s_mbar[0]);
        unsigned lb1 = smem_u32(&s_mbar[1]);
        asm("mapa.shared::cluster.u32 %0, %1, %2;" : "=r"(r_h0) : "r"(lh0), "r"(d));
        asm("mapa.shared::cluster.u32 %0, %1, %2;" : "=r"(r_h1) : "r"(lh1), "r"(d));
        asm("mapa.shared::cluster.u32 %0, %1, %2;" : "=r"(r_b0) : "r"(lb0), "r"(d));
        asm("mapa.shared::cluster.u32 %0, %1, %2;" : "=r"(r_b1) : "r"(lb1), "r"(d));
    }

    if (tid == 0) {
        asm volatile("mbarrier.init.shared.b64 [%0], %1;" :: "r"(smem_u32(&s_mbar[0])), "r"(8u) : "memory");
        asm volatile("mbarrier.init.shared.b64 [%0], %1;" :: "r"(smem_u32(&s_mbar[1])), "r"(8u) : "memory");
    }
    if (tid < 256) { s_hb[0][tid] = 0.f; s_hb[1][tid] = 0.f; }
    __syncthreads();
    asm volatile("barrier.cluster.arrive.aligned;" ::: "memory");
    asm volatile("barrier.cluster.wait.aligned;"   ::: "memory");

    // initial push: zeros (h_{-1}) into buffer 1
    if (tid < 8) {
        #pragma unroll
        for (int i = 0; i < 8; i++)
            asm volatile("st.shared::cluster.v4.f32 [%0], {%1,%1,%1,%1};"
                         :: "r"(r_h1 + i * 16), "f"(0.f) : "memory");
        asm volatile("mbarrier.arrive.release.cluster.shared::cluster.b64 _, [%0];"
                     :: "r"(r_b1) : "memory");
    }

    unsigned par0 = 0u, par1 = 0u;

    // prefetch gate term for step 0 (phase-2 threads)
    const int gcol2 = (tid >> 5) * 256 + (int)rank * 32 + (tid & 31);
    float gt = (tid < 128) ? g_G[gcol2] : 0.f;

    for (int t = 0; t < NB; t++) {
        const int rb = (t + 1) & 1;      // buffer holding h_{t-1}
        const int wb = t & 1;            // buffer receiving h_t

        { // wait for all 8 source-CTA pushes of h_{t-1}
            const unsigned a = smem_u32(&s_mbar[rb]);
            const unsigned ph = rb ? par1 : par0;
            unsigned done;
            asm volatile(
                "{\n\t.reg .pred p;\n\t"
                "mbarrier.try_wait.parity.acquire.cluster.shared::cta.b64 p, [%1], %2;\n\t"
                "selp.b32 %0, 1, 0, p;\n\t}"
                : "=r"(done) : "r"(a), "r"(ph) : "memory");
            if (!done) {
                asm volatile(
                    "{\n\t.reg .pred P1;\n\t"
                    "WLB_%=:\n\t"
                    "mbarrier.try_wait.parity.acquire.cluster.shared::cta.b64 P1, [%0], %1, 0x989680;\n\t"
                    "@P1 bra.uni WDB_%=;\n\t"
                    "bra.uni WLB_%=;\n\t"
                    "WDB_%=:\n\t}"
                    :: "r"(a), "r"(ph) : "memory");
            }
            if (rb) par1 ^= 1u; else par0 ^= 1u;
        }

        // ---- GEMV phase 1: 8 cols x 8 k per thread ----
        {
            const float4 ha = *(const float4*)(&s_hb[rb][kw * 8]);
            const float4 hbv = *(const float4*)(&s_hb[rb][kw * 8 + 4]);
            float acc[8];
            #pragma unroll
            for (int c = 0; c < 8; c++)
                acc[c] = w[0][c] * ha.x;
            #pragma unroll
            for (int c = 0; c < 8; c++) acc[c] = fmaf(w[1][c], ha.y, acc[c]);
            #pragma unroll
            for (int c = 0; c < 8; c++) acc[c] = fmaf(w[2][c], ha.z, acc[c]);
            #pragma unroll
            for (int c = 0; c < 8; c++) acc[c] = fmaf(w[3][c], ha.w, acc[c]);
            #pragma unroll
            for (int c = 0; c < 8; c++) acc[c] = fmaf(w[4][c], hbv.x, acc[c]);
            #pragma unroll
            for (int c = 0; c < 8; c++) acc[c] = fmaf(w[5][c], hbv.y, acc[c]);
            #pragma unroll
            for (int c = 0; c < 8; c++) acc[c] = fmaf(w[6][c], hbv.z, acc[c]);
            #pragma unroll
            for (int c = 0; c < 8; c++) acc[c] = fmaf(w[7][c], hbv.w, acc[c]);
            float4 p0; p0.x = acc[0]; p0.y = acc[1]; p0.z = acc[2]; p0.w = acc[3];
            float4 p1; p1.x = acc[4]; p1.y = acc[5]; p1.z = acc[6]; p1.w = acc[7];
            *(float4*)&s_part[kw * 128 + g * 8]     = p0;
            *(float4*)&s_part[kw * 128 + g * 8 + 4] = p1;
        }
        __syncthreads();

        // ---- GEMV phase 2: reduce 32 partials per column ----
        if (tid < 128) {
            float s = gt;
            #pragma unroll
            for (int k2 = 0; k2 < 32; k2++)
                s += s_part[k2 * 128 + tid];
            s_z[tid] = s;
            if (t + 1 < NB) gt = g_G[(size_t)(t + 1) * 1024 + gcol2];
        }
        __syncthreads();

        // ---- cell: warp 0, lane = channel-in-CTA (fully local) ----
        if (tid < 32) {
            const float zi = s_z[tid];
            const float zf = s_z[32 + tid];
            const float zc = s_z[64 + tid];
            const float zo = s_z[96 + tid];

            float s1 = zc, s2 = zc * zc;
            s1 += __shfl_xor_sync(0xffffffffu, s1, 1);  s2 += __shfl_xor_sync(0xffffffffu, s2, 1);
            s1 += __shfl_xor_sync(0xffffffffu, s1, 2);  s2 += __shfl_xor_sync(0xffffffffu, s2, 2);
            s1 += __shfl_xor_sync(0xffffffffu, s1, 4);  s2 += __shfl_xor_sync(0xffffffffu, s2, 4);
            float mean = s1 * 0.125f;
            float var  = s2 * 0.125f - mean * mean;
            const float ecc = zc * sigf(vl * zc) / sqrtf(var + 1e-5f) * gl + bl;

            cst = sigf(zf) * cst + sigf(zi) * ecc;

            s1 = cst; s2 = cst * cst;
            s1 += __shfl_xor_sync(0xffffffffu, s1, 1);  s2 += __shfl_xor_sync(0xffffffffu, s2, 1);
            s1 += __shfl_xor_sync(0xffffffffu, s1, 2);  s2 += __shfl_xor_sync(0xffffffffu, s2, 2);
            s1 += __shfl_xor_sync(0xffffffffu, s1, 4);  s2 += __shfl_xor_sync(0xffffffffu, s2, 4);
            mean = s1 * 0.125f;
            var  = s2 * 0.125f - mean * mean;
            const float ecn = cst * sigf(vl * cst) / sqrtf(var + 1e-5f) * gl + bl;

            const float h = sigf(zo) * ecn;
            g_H[(size_t)t * 256 + rank * 32 + tid] = h;
            s_hout[tid] = h;
            __syncwarp();

            // push h_t: lane d -> dest CTA d (8 x st.v4 + 1 release-arrive)
            if (tid < 8) {
                const unsigned rh  = wb ? r_h1 : r_h0;
                const unsigned rbb = wb ? r_b1 : r_b0;
                #pragma unroll
                for (int i = 0; i < 8; i++) {
                    const float4 v = *(const float4*)&s_hout[i * 4];
                    asm volatile("st.shared::cluster.v4.f32 [%0], {%1,%2,%3,%4};"
                                 :: "r"(rh + i * 16), "f"(v.x), "f"(v.y), "f"(v.z), "f"(v.w)
                                 : "memory");
                }
                asm volatile("mbarrier.arrive.release.cluster.shared::cluster.b64 _, [%0];"
                             :: "r"(rbb) : "memory");
            }
        }
    }

    asm volatile("barrier.cluster.arrive.aligned;" ::: "memory");
    asm volatile("barrier.cluster.wait.aligned;"   ::: "memory");
}

// ===== Kernel C: dense_0 + evonorm -> bf16 hi/lo split (g_Ah/g_Al) ==========
__global__ __launch_bounds__(256) void kC(
    const float* __restrict__ Wd0, const float* __restrict__ vd,
    const float* __restrict__ gd,  const float* __restrict__ bd)
{
    __shared__ float sm1[16 * 256];
    __shared__ float sm2[16 * 256];
    const int tid = threadIdx.x;
    const int r0  = blockIdx.x * 16;

    const float4* src = (const float4*)(g_H + (size_t)r0 * 256);
    for (int i = tid; i < 1024; i += 256)
        ((float4*)sm1)[i] = src[i];
    __syncthreads();

    const int j = tid;
    float acc[16];
    #pragma unroll
    for (int r = 0; r < 16; r++) acc[r] = 0.f;
    for (int k4 = 0; k4 < 64; k4++) {
        const int k = k4 * 4;
        const float w0 = Wd0[(k+0)*256 + j];
        const float w1 = Wd0[(k+1)*256 + j];
        const float w2 = Wd0[(k+2)*256 + j];
        const float w3 = Wd0[(k+3)*256 + j];
        #pragma unroll
        for (int r = 0; r < 16; r++) {
            const float4 x = *(const float4*)&sm1[r * 256 + k];
            acc[r] += x.x*w0 + x.y*w1 + x.z*w2 + x.w*w3;
        }
    }
    #pragma unroll
    for (int r = 0; r < 16; r++) sm2[r * 256 + j] = acc[r];
    __syncthreads();

    const float v = vd[j], g = gd[j], bb = bd[j];
    for (int r = 0; r < 16; r++) {
        const float* row = &sm2[r * 256 + (j & ~7)];
        float s1 = 0.f, s2 = 0.f;
        #pragma unroll
        for (int e = 0; e < 8; e++) { float t = row[e]; s1 += t; s2 += t * t; }
        const float mean = s1 * 0.125f;
        const float var  = s2 * 0.125f - mean * mean;
        const float x = sm2[r * 256 + j];
        const float y = x * sigf(v * x) / sqrtf(var + 1e-5f) * g + bb;
        const __nv_bfloat16 hi = __float2bfloat16(y);
        const __nv_bfloat16 lo = __float2bfloat16(y - __bfloat162float(hi));
        g_Ah[(size_t)(r0 + r) * 256 + j] = hi;
        g_Al[(size_t)(r0 + r) * 256 + j] = lo;
    }
}

// ===== Kernel D: HMMA bf16 3-split GEMM, CTA tile 128x128, serial K chunks ==
#define KD_SMEM 65536

__global__ void __launch_bounds__(256, 2)
kD(const float* __restrict__ bout, float* __restrict__ out)
{
    extern __shared__ __align__(1024) char smem[];
    const uint32_t ST = smem_u32(smem);
    const int tid = threadIdx.x;
    const int wid = tid >> 5, lane = tid & 31;
    const int warp_m = wid & 1;
    const int warp_n = wid >> 1;
    const int n0 = blockIdx.x * 128;
    const int m0 = blockIdx.y * 128;

    const uint32_t a_row = warp_m * 64 + (lane & 15);
    const uint32_t a_kb  = (uint32_t)(lane >> 4) * 16;
    const uint32_t b_row = warp_n * 32 + (lane & 7) + ((lane >> 4) & 1) * 8;
    const uint32_t b_kb  = (uint32_t)((lane >> 3) & 1) * 16;

    float acc[4][4][4];
    #pragma unroll
    for (int i = 0; i < 4; i++)
        #pragma unroll
        for (int j = 0; j < 4; j++)
            #pragma unroll
            for (int q = 0; q < 4; q++) acc[i][j][q] = 0.f;

    for (int kc = 0; kc < 4; kc++) {
        const int koff = kc * 64;
        #pragma unroll
        for (int sp = 0; sp < 2; sp++) {
            const __nv_bfloat16* gA = sp ? g_Al : g_Ah;
            const uint32_t db = ST + sp * 16384;
            #pragma unroll
            for (int i = 0; i < 4; i++) {
                const int g = tid + i * 256;
                const int row = g >> 3, j = g & 7;
                CP_ASYNC16(db + SWZ(row * 128 + j * 16),
                           gA + (size_t)(m0 + row) * 256 + koff + j * 8);
            }
        }
        #pragma unroll
        for (int sp = 0; sp < 2; sp++) {
            const __nv_bfloat16* gB = sp ? g_Bl : g_Bh;
            const uint32_t db = ST + 32768 + sp * 16384;
            #pragma unroll
            for (int i = 0; i < 4; i++) {
                const int g = tid + i * 256;
                const int row = g >> 3, j = g & 7;
                CP_ASYNC16(db + SWZ(row * 128 + j * 16),
                           gB + (size_t)(n0 + row) * 256 + koff + j * 8);
            }
        }
        CP_COMMIT();
        CP_WAIT_ALL();
        __syncthreads();

        #pragma unroll
        for (int split = 0; split < 3; split++) {
            const uint32_t Abase = ST + (split == 2 ? 16384u : 0u);
            const uint32_t Bbase = ST + 32768u + (split == 1 ? 16384u : 0u);
            #pragma unroll
            for (int ks = 0; ks < 4; ks++) {
                const uint32_t kk2 = (uint32_t)ks * 32;
                uint32_t af[4][4];
                #pragma unroll
                for (int mb = 0; mb < 4; mb++) {
                    const uint32_t addr = Abase + SWZ((a_row + mb * 16) * 128 + kk2 + a_kb);
                    LDSM_X4(af[mb][0], af[mb][1], af[mb][2], af[mb][3], addr);
                }
                uint32_t bfr[2][4];
                #pragma unroll
                for (int nb2 = 0; nb2 < 2; nb2++) {
                    const uint32_t addr = Bbase + SWZ((b_row + nb2 * 16) * 128 + kk2 + b_kb);
                    LDSM_X4(bfr[nb2][0], bfr[nb2][1], bfr[nb2][2], bfr[nb2][3], addr);
                }
                #pragma unroll
                for (int mb = 0; mb < 4; mb++) {
                    MMA16816(acc[mb][0], af[mb], bfr[0][0], bfr[0][1]);
                    MMA16816(acc[mb][1], af[mb], bfr[0][2], bfr[0][3]);
                    MMA16816(acc[mb][2], af[mb], bfr[1][0], bfr[1][1]);
                    MMA16816(acc[mb][3], af[mb], bfr[1][2], bfr[1][3]);
                }
            }
        }
        __syncthreads();
    }

    #pragma unroll
    for (int nb = 0; nb < 4; nb++) {
        const int col = n0 + warp_n * 32 + nb * 8 + (lane & 3) * 2;
        const float2 bb = *(const float2*)&bout[col];
        #pragma unroll
        for (int mb = 0; mb < 4; mb++) {
            const int row = m0 + warp_m * 64 + mb * 16 + (lane >> 2);
            float2 v0, v1;
            v0.x = acc[mb][nb][0] + bb.x;  v0.y = acc[mb][nb][1] + bb.y;
            v1.x = acc[mb][nb][2] + bb.x;  v1.y = acc[mb][nb][3] + bb.y;
            *(float2*)&out[(size_t)row * NPAR + col]       = v0;
            *(float2*)&out[(size_t)(row + 8) * NPAR + col] = v1;
        }
    }
}

// ============================================================================
extern "C" void kernel_launch(void* const* d_in, const int* in_sizes, int n_in,
                              void* d_out, int out_size)
{
    const float* actions = (const float*)d_in[0];
    const float* obs     = (const float*)d_in[1];
    const float* Wci     = (const float*)d_in[2];
    const float* vci     = (const float*)d_in[3];
    const float* gci     = (const float*)d_in[4];
    const float* bci     = (const float*)d_in[5];
    const float* Wcl     = (const float*)d_in[6];
    const float* bcl     = (const float*)d_in[7];
    const float* Win     = (const float*)d_in[8];
    const float* vin     = (const float*)d_in[9];
    const float* gin     = (const float*)d_in[10];
    const float* bin     = (const float*)d_in[11];
    const float* Wk      = (const float*)d_in[12];
    const float* Wr      = (const float*)d_in[13];
    const float* vl      = (const float*)d_in[14];
    const float* gl      = (const float*)d_in[15];
    const float* bl      = (const float*)d_in[16];
    const float* Wd0     = (const float*)d_in[17];
    const float* vd0     = (const float*)d_in[18];
    const float* gd0     = (const float*)d_in[19];
    const float* bd0     = (const float*)d_in[20];
    const float* Wout    = (const float*)d_in[21];
    const float* bout    = (const float*)d_in[22];
    float* out = (float*)d_out;

    kW<<<NPAR / 32, 256>>>(Wout);
    kA<<<128, 256>>>(actions, obs, Wci, vci, gci, bci, Wcl, bcl,
                     Win, vin, gin, bin, Wk);
    kB<<<8, 512>>>(Wr, vl, gl, bl);
    kC<<<128, 256>>>(Wd0, vd0, gd0, bd0);

    cudaFuncSetAttribute(kD, cudaFuncAttributeMaxDynamicSharedMemorySize, KD_SMEM);
    dim3 gD(NPAR / 128, NB / 128);
    kD<<<gD, 256, KD_SMEM>>>(bout, out);
}

// round 10
// speedup vs baseline: 2.0577x; 1.0978x over previous
#include <cuda_runtime.h>
#include <cuda_bf16.h>
#include <cstdint>

#define NB     2048
#define NPAR   66048

// Scratch (device globals; allocation is forbidden)
__device__ __align__(16) float g_G [NB * 1024];            // X@Wk precomputed gates
__device__ __align__(16) float g_H [NB * 256];             // LSTM hidden outputs
__device__ __align__(16) __nv_bfloat16 g_Ah[NB * 256];     // X3 hi (bf16 split)
__device__ __align__(16) __nv_bfloat16 g_Al[NB * 256];     // X3 lo
__device__ __align__(16) __nv_bfloat16 g_Bh[(size_t)NPAR * 256]; // W^T hi, K-major [n][k]
__device__ __align__(16) __nv_bfloat16 g_Bl[(size_t)NPAR * 256]; // W^T lo

__device__ __forceinline__ float sigf(float x) {
    return __frcp_rn(1.0f + __expf(-x));
}

__device__ __forceinline__ float2 fma2(float2 a, float2 b, float2 c) {
    unsigned long long A, Bv, C, D;
    asm("mov.b64 %0, {%1,%2};" : "=l"(A)  : "f"(a.x), "f"(a.y));
    asm("mov.b64 %0, {%1,%2};" : "=l"(Bv) : "f"(b.x), "f"(b.y));
    asm("mov.b64 %0, {%1,%2};" : "=l"(C)  : "f"(c.x), "f"(c.y));
    asm("fma.rn.f32x2 %0, %1, %2, %3;" : "=l"(D) : "l"(A), "l"(Bv), "l"(C));
    float2 r;
    asm("mov.b64 {%0,%1}, %2;" : "=f"(r.x), "=f"(r.y) : "l"(D));
    return r;
}

__device__ __forceinline__ unsigned smem_u32(const void* p) {
    unsigned a;
    asm("{ .reg .u64 t; cvta.to.shared.u64 t, %1; cvt.u32.u64 %0, t; }" : "=r"(a) : "l"(p));
    return a;
}

// ---- async-copy / HMMA helpers ---------------------------------------------
#define SWZ(x) ((x) ^ (((x) >> 3) & 0x70))

#define CP_ASYNC16(dst, src) \
    asm volatile("cp.async.cg.shared.global [%0], [%1], 16;" :: "r"(dst), "l"(src) : "memory")
#define CP_COMMIT()  asm volatile("cp.async.commit_group;" ::: "memory")
#define CP_WAIT_ALL() asm volatile("cp.async.wait_all;" ::: "memory")

#define LDSM_X4(r0, r1, r2, r3, addr) \
    asm volatile("ldmatrix.sync.aligned.m8n8.x4.shared.b16 {%0,%1,%2,%3}, [%4];" \
                 : "=r"(r0), "=r"(r1), "=r"(r2), "=r"(r3) : "r"(addr))

#define MMA16816(d, a, b0, b1) \
    asm volatile("mma.sync.aligned.m16n8k16.row.col.f32.bf16.bf16.f32 " \
                 "{%0,%1,%2,%3}, {%4,%5,%6,%7}, {%8,%9}, {%0,%1,%2,%3};" \
                 : "+f"((d)[0]), "+f"((d)[1]), "+f"((d)[2]), "+f"((d)[3]) \
                 : "r"((a)[0]), "r"((a)[1]), "r"((a)[2]), "r"((a)[3]), \
                   "r"(b0), "r"(b1))

// ===== Kernel W: split+transpose W_out -> g_Bh/g_Bl K-major =================
__global__ __launch_bounds__(256) void kW(const float* __restrict__ Wout)
{
    __shared__ float sm[32 * 257];
    const int tid = threadIdx.x;
    const int n0  = blockIdx.x * 32;

    #pragma unroll 4
    for (int it = 0; it < 32; it++) {
        const int idx = it * 256 + tid;
        const int k = idx >> 5, j = idx & 31;
        sm[j * 257 + k] = Wout[(size_t)k * NPAR + n0 + j];
    }
    __syncthreads();

    const int j  = tid & 31;
    const int kq = tid >> 5;
    __nv_bfloat16* ph = g_Bh + (size_t)(n0 + j) * 256 + kq * 32;
    __nv_bfloat16* pl = g_Bl + (size_t)(n0 + j) * 256 + kq * 32;
    #pragma unroll
    for (int kk = 0; kk < 32; kk++) {
        const float w = sm[j * 257 + kq * 32 + kk];
        const __nv_bfloat16 hi = __float2bfloat16(w);
        const __nv_bfloat16 lo = __float2bfloat16(w - __bfloat162float(hi));
        ph[kk] = hi;
        pl[kk] = lo;
    }
}

// ===== Kernel A: cond path + dense_in + G = x_in @ Wk. 128 CTAs x 16 rows =====
__global__ __launch_bounds__(256) void kA(
    const float* __restrict__ actions, const float* __restrict__ obs,
    const float* __restrict__ Wci, const float* __restrict__ vci,
    const float* __restrict__ gci, const float* __restrict__ bci,
    const float* __restrict__ Wcl, const float* __restrict__ bcl,
    const float* __restrict__ Win, const float* __restrict__ vin,
    const float* __restrict__ gin, const float* __restrict__ bin,
    const float* __restrict__ Wk)
{
    __shared__ float sm1[16 * 256];
    __shared__ float sm2[16 * 256];
    const int tid = threadIdx.x;
    const int r0  = blockIdx.x * 16;

    { // t1 = actions @ Wci -> sm1[16][64]
        const int j = tid & 63, rr = tid >> 6;
        #pragma unroll
        for (int q = 0; q < 4; q++) {
            const int r = rr + q * 4;
            float acc = 0.f;
            #pragma unroll
            for (int k = 0; k < 16; k++)
                acc += actions[(r0 + r) * 16 + k] * Wci[k * 64 + j];
            sm1[r * 64 + j] = acc;
        }
    }
    __syncthreads();
    { // evonorm(groups=8) -> sm2[16][64]
        const int j = tid & 63, rr = tid >> 6;
        const float v = vci[j], g = gci[j], bb = bci[j];
        #pragma unroll
        for (int q = 0; q < 4; q++) {
            const int r = rr + q * 4;
            const float* row = &sm1[r * 64 + (j & ~7)];
            float s1 = 0.f, s2 = 0.f;
            #pragma unroll
            for (int e = 0; e < 8; e++) { float t = row[e]; s1 += t; s2 += t * t; }
            const float mean = s1 * 0.125f;
            const float var  = s2 * 0.125f - mean * mean;
            const float x = sm1[r * 64 + j];
            sm2[r * 64 + j] = x * sigf(v * x) * rsqrtf(var + 1e-5f) * g + bb;
        }
    }
    __syncthreads();
    { // x = a1 @ Wcl + bcl + obs -> sm1[16][64]
        const int j = tid & 63, rr = tid >> 6;
        const float bj = bcl[j];
        float acc[4];
        #pragma unroll
        for (int q = 0; q < 4; q++)
            acc[q] = bj + obs[(r0 + rr + q * 4) * 64 + j];
        for (int k = 0; k < 64; k++) {
            const float w = Wcl[k * 64 + j];
            #pragma unroll
            for (int q = 0; q < 4; q++)
                acc[q] += sm2[(rr + q * 4) * 64 + k] * w;
        }
        #pragma unroll
        for (int q = 0; q < 4; q++)
            sm1[(rr + q * 4) * 64 + j] = acc[q];
    }
    __syncthreads();
    { // t2 = x @ Win -> sm2[16][256]
        const int j = tid;
        float acc[16];
        #pragma unroll
        for (int r = 0; r < 16; r++) acc[r] = 0.f;
        for (int k = 0; k < 64; k++) {
            const float w = Win[k * 256 + j];
            #pragma unroll
            for (int r = 0; r < 16; r++) acc[r] += sm1[r * 64 + k] * w;
        }
        #pragma unroll
        for (int r = 0; r < 16; r++) sm2[r * 256 + j] = acc[r];
    }
    __syncthreads();
    { // evonorm(group size 8) -> sm1[16][256]
        const int j = tid;
        const float v = vin[j], g = gin[j], bb = bin[j];
        for (int r = 0; r < 16; r++) {
            const float* row = &sm2[r * 256 + (j & ~7)];
            float s1 = 0.f, s2 = 0.f;
            #pragma unroll
            for (int e = 0; e < 8; e++) { float t = row[e]; s1 += t; s2 += t * t; }
            const float mean = s1 * 0.125f;
            const float var  = s2 * 0.125f - mean * mean;
            const float x = sm2[r * 256 + j];
            sm1[r * 256 + j] = x * sigf(v * x) * rsqrtf(var + 1e-5f) * g + bb;
        }
    }
    __syncthreads();
    { // G = x_in @ Wk  (thread: 4 cols x 16 rows)
        const int c0 = tid * 4;
        float2 acc[16][2];
        #pragma unroll
        for (int r = 0; r < 16; r++) { acc[r][0] = make_float2(0.f,0.f); acc[r][1] = make_float2(0.f,0.f); }
        for (int k = 0; k < 256; k++) {
            const float4 w4 = *(const float4*)&Wk[k * 1024 + c0];
            const float2 wa = make_float2(w4.x, w4.y);
            const float2 wb = make_float2(w4.z, w4.w);
            #pragma unroll
            for (int r = 0; r < 16; r++) {
                const float x = sm1[r * 256 + k];
                const float2 xx = make_float2(x, x);
                acc[r][0] = fma2(wa, xx, acc[r][0]);
                acc[r][1] = fma2(wb, xx, acc[r][1]);
            }
        }
        #pragma unroll
        for (int r = 0; r < 16; r++) {
            float4 o;
            o.x = acc[r][0].x; o.y = acc[r][0].y; o.z = acc[r][1].x; o.w = acc[r][1].y;
            *(float4*)&g_G[(size_t)(r0 + r) * 1024 + c0] = o;
        }
    }
}

// ===== Kernel B: sequential LSTM, 8-CTA cluster =============================
// Thread (g, kw): g = col-group (4 cols), kw = k-window (16 k's).
// GEMV: 2-phase smem reduce (16 partials). Push: warp0 lanes 0-7, one
// release-arrive per source CTA (mbarrier expected = 8). Cell: no precise
// divides on the chain (rcp/rsqrt approx).
__global__ void __launch_bounds__(512, 1) __cluster_dims__(8, 1, 1)
kB(const float* __restrict__ Wr, const float* __restrict__ vl_,
   const float* __restrict__ gl_, const float* __restrict__ bl_)
{
    __shared__ __align__(16) float s_hb[2][256];     // h buffers (remote-written)
    __shared__ __align__(16) float s_part[16 * 128]; // GEMV partials, 8KB
    __shared__ __align__(16) float s_z[128];
    __shared__ __align__(16) float s_hout[32];
    __shared__ __align__(8)  unsigned long long s_mbar[2];

    const int tid = threadIdx.x;
    unsigned rank;
    asm("mov.u32 %0, %%cluster_ctarank;" : "=r"(rank));

    const int g   = tid & 31;        // col-group: cols [g*4, g*4+4)
    const int kw  = tid >> 5;        // k-window:  k    [kw*16, kw*16+16)
    const int gg  = g >> 3;          // gate 0..3
    const int cc0 = (g & 7) * 4;     // channel base within this CTA's 32
    const int gcol0 = gg * 256 + (int)rank * 32 + cc0;   // global col of c=0

    // register-resident weights: w[j][c], 64 fp32 per thread
    float w[16][4];
    #pragma unroll
    for (int j = 0; j < 16; j++)
        #pragma unroll
        for (int c = 0; c < 4; c++)
            w[j][c] = Wr[(size_t)(kw * 16 + j) * 1024 + gcol0 + c];

    // cell params for warp 0 (channel ch = rank*32 + lane)
    float vl = 0.f, gl = 0.f, bl = 0.f, cst = 0.f;
    if (tid < 32) {
        const int ch = (int)rank * 32 + tid;
        vl = vl_[ch]; gl = gl_[ch]; bl = bl_[ch];
    }

    // push addresses for warp0 lanes 0-7 (lane = dest CTA)
    unsigned r_h0 = 0, r_h1 = 0, r_b0 = 0, r_b1 = 0;
    if (tid < 8) {
        const unsigned d = (unsigned)tid;
        unsigned lh0 = smem_u32(&s_hb[0][rank * 32]);
        unsigned lh1 = smem_u32(&s_hb[1][rank * 32]);
        unsigned lb0 = smem_u32(&s_mbar[0]);
        unsigned lb1 = smem_u32(&s_mbar[1]);
        asm("mapa.shared::cluster.u32 %0, %1, %2;" : "=r"(r_h0) : "r"(lh0), "r"(d));
        asm("mapa.shared::cluster.u32 %0, %1, %2;" : "=r"(r_h1) : "r"(lh1), "r"(d));
        asm("mapa.shared::cluster.u32 %0, %1, %2;" : "=r"(r_b0) : "r"(lb0), "r"(d));
        asm("mapa.shared::cluster.u32 %0, %1, %2;" : "=r"(r_b1) : "r"(lb1), "r"(d));
    }

    if (tid == 0) {
        asm volatile("mbarrier.init.shared.b64 [%0], %1;" :: "r"(smem_u32(&s_mbar[0])), "r"(8u) : "memory");
        asm volatile("mbarrier.init.shared.b64 [%0], %1;" :: "r"(smem_u32(&s_mbar[1])), "r"(8u) : "memory");
    }
    if (tid < 256) { s_hb[0][tid] = 0.f; s_hb[1][tid] = 0.f; }
    __syncthreads();
    asm volatile("barrier.cluster.arrive.aligned;" ::: "memory");
    asm volatile("barrier.cluster.wait.aligned;"   ::: "memory");

    // initial push: zeros (h_{-1}) into buffer 1
    if (tid < 8) {
        #pragma unroll
        for (int i = 0; i < 8; i++)
            asm volatile("st.shared::cluster.v4.f32 [%0], {%1,%1,%1,%1};"
                         :: "r"(r_h1 + i * 16), "f"(0.f) : "memory");
        asm volatile("mbarrier.arrive.release.cluster.shared::cluster.b64 _, [%0];"
                     :: "r"(r_b1) : "memory");
    }

    unsigned par0 = 0u, par1 = 0u;

    // prefetch gate term for step 0 (phase-2 threads)
    const int gcol2 = (tid >> 5) * 256 + (int)rank * 32 + (tid & 31);
    float gt = (tid < 128) ? g_G[gcol2] : 0.f;

    for (int t = 0; t < NB; t++) {
        const int rb = (t + 1) & 1;      // buffer holding h_{t-1}
        const int wb = t & 1;            // buffer receiving h_t

        { // wait for all 8 source-CTA pushes of h_{t-1}
            const unsigned a = smem_u32(&s_mbar[rb]);
            const unsigned ph = rb ? par1 : par0;
            unsigned done;
            asm volatile(
                "{\n\t.reg .pred p;\n\t"
                "mbarrier.try_wait.parity.acquire.cluster.shared::cta.b64 p, [%1], %2;\n\t"
                "selp.b32 %0, 1, 0, p;\n\t}"
                : "=r"(done) : "r"(a), "r"(ph) : "memory");
            if (!done) {
                asm volatile(
                    "{\n\t.reg .pred P1;\n\t"
                    "WLB_%=:\n\t"
                    "mbarrier.try_wait.parity.acquire.cluster.shared::cta.b64 P1, [%0], %1, 0x989680;\n\t"
                    "@P1 bra.uni WDB_%=;\n\t"
                    "bra.uni WLB_%=;\n\t"
                    "WDB_%=:\n\t}"
                    :: "r"(a), "r"(ph) : "memory");
            }
            if (rb) par1 ^= 1u; else par0 ^= 1u;
        }

        // ---- GEMV phase 1: 4 cols x 16 k per thread ----
        {
            const float4* hv = (const float4*)(&s_hb[rb][kw * 16]);
            const float4 h0 = hv[0], h1 = hv[1], h2 = hv[2], h3 = hv[3];
            float a0, a1, a2, a3;
            a0 = w[0][0] * h0.x;  a1 = w[0][1] * h0.x;
            a2 = w[0][2] * h0.x;  a3 = w[0][3] * h0.x;
            #define KSTEP(j, hval) \
                a0 = fmaf(w[j][0], hval, a0); a1 = fmaf(w[j][1], hval, a1); \
                a2 = fmaf(w[j][2], hval, a2); a3 = fmaf(w[j][3], hval, a3);
            KSTEP(1,  h0.y) KSTEP(2,  h0.z) KSTEP(3,  h0.w)
            KSTEP(4,  h1.x) KSTEP(5,  h1.y) KSTEP(6,  h1.z) KSTEP(7,  h1.w)
            KSTEP(8,  h2.x) KSTEP(9,  h2.y) KSTEP(10, h2.z) KSTEP(11, h2.w)
            KSTEP(12, h3.x) KSTEP(13, h3.y) KSTEP(14, h3.z) KSTEP(15, h3.w)
            #undef KSTEP
            float4 p; p.x = a0; p.y = a1; p.z = a2; p.w = a3;
            *(float4*)&s_part[kw * 128 + g * 4] = p;
        }
        __syncthreads();

        // ---- GEMV phase 2: reduce 16 partials per column ----
        if (tid < 128) {
            float s = gt;
            #pragma unroll
            for (int k2 = 0; k2 < 16; k2++)
                s += s_part[k2 * 128 + tid];
            s_z[tid] = s;
            if (t + 1 < NB) gt = g_G[(size_t)(t + 1) * 1024 + gcol2];
        }
        __syncthreads();

        // ---- cell: warp 0, lane = channel-in-CTA (fully local) ----
        if (tid < 32) {
            const float zi = s_z[tid];
            const float zf = s_z[32 + tid];
            const float zc = s_z[64 + tid];
            const float zo = s_z[96 + tid];

            float s1 = zc, s2 = zc * zc;
            s1 += __shfl_xor_sync(0xffffffffu, s1, 1);  s2 += __shfl_xor_sync(0xffffffffu, s2, 1);
            s1 += __shfl_xor_sync(0xffffffffu, s1, 2);  s2 += __shfl_xor_sync(0xffffffffu, s2, 2);
            s1 += __shfl_xor_sync(0xffffffffu, s1, 4);  s2 += __shfl_xor_sync(0xffffffffu, s2, 4);
            float mean = s1 * 0.125f;
            float var  = s2 * 0.125f - mean * mean;
            const float ecc = zc * sigf(vl * zc) * rsqrtf(var + 1e-5f) * gl + bl;

            cst = sigf(zf) * cst + sigf(zi) * ecc;

            s1 = cst; s2 = cst * cst;
            s1 += __shfl_xor_sync(0xffffffffu, s1, 1);  s2 += __shfl_xor_sync(0xffffffffu, s2, 1);
            s1 += __shfl_xor_sync(0xffffffffu, s1, 2);  s2 += __shfl_xor_sync(0xffffffffu, s2, 2);
            s1 += __shfl_xor_sync(0xffffffffu, s1, 4);  s2 += __shfl_xor_sync(0xffffffffu, s2, 4);
            mean = s1 * 0.125f;
            var  = s2 * 0.125f - mean * mean;
            const float ecn = cst * sigf(vl * cst) * rsqrtf(var + 1e-5f) * gl + bl;

            const float h = sigf(zo) * ecn;
            g_H[(size_t)t * 256 + rank * 32 + tid] = h;
            s_hout[tid] = h;
            __syncwarp();

            // push h_t: lane d -> dest CTA d (8 x st.v4 + 1 release-arrive)
            if (tid < 8) {
                const unsigned rh  = wb ? r_h1 : r_h0;
                const unsigned rbb = wb ? r_b1 : r_b0;
                #pragma unroll
                for (int i = 0; i < 8; i++) {
                    const float4 v = *(const float4*)&s_hout[i * 4];
                    asm volatile("st.shared::cluster.v4.f32 [%0], {%1,%2,%3,%4};"
                                 :: "r"(rh + i * 16), "f"(v.x), "f"(v.y), "f"(v.z), "f"(v.w)
                                 : "memory");
                }
                asm volatile("mbarrier.arrive.release.cluster.shared::cluster.b64 _, [%0];"
                             :: "r"(rbb) : "memory");
            }
        }
    }

    asm volatile("barrier.cluster.arrive.aligned;" ::: "memory");
    asm volatile("barrier.cluster.wait.aligned;"   ::: "memory");
}

// ===== Kernel C: dense_0 + evonorm -> bf16 hi/lo split (g_Ah/g_Al) ==========
__global__ __launch_bounds__(256) void kC(
    const float* __restrict__ Wd0, const float* __restrict__ vd,
    const float* __restrict__ gd,  const float* __restrict__ bd)
{
    __shared__ float sm1[16 * 256];
    __shared__ float sm2[16 * 256];
    const int tid = threadIdx.x;
    const int r0  = blockIdx.x * 16;

    const float4* src = (const float4*)(g_H + (size_t)r0 * 256);
    for (int i = tid; i < 1024; i += 256)
        ((float4*)sm1)[i] = src[i];
    __syncthreads();

    const int j = tid;
    float acc[16];
    #pragma unroll
    for (int r = 0; r < 16; r++) acc[r] = 0.f;
    for (int k4 = 0; k4 < 64; k4++) {
        const int k = k4 * 4;
        const float w0 = Wd0[(k+0)*256 + j];
        const float w1 = Wd0[(k+1)*256 + j];
        const float w2 = Wd0[(k+2)*256 + j];
        const float w3 = Wd0[(k+3)*256 + j];
        #pragma unroll
        for (int r = 0; r < 16; r++) {
            const float4 x = *(const float4*)&sm1[r * 256 + k];
            acc[r] += x.x*w0 + x.y*w1 + x.z*w2 + x.w*w3;
        }
    }
    #pragma unroll
    for (int r = 0; r < 16; r++) sm2[r * 256 + j] = acc[r];
    __syncthreads();

    const float v = vd[j], g = gd[j], bb = bd[j];
    for (int r = 0; r < 16; r++) {
        const float* row = &sm2[r * 256 + (j & ~7)];
        float s1 = 0.f, s2 = 0.f;
        #pragma unroll
        for (int e = 0; e < 8; e++) { float t = row[e]; s1 += t; s2 += t * t; }
        const float mean = s1 * 0.125f;
        const float var  = s2 * 0.125f - mean * mean;
        const float x = sm2[r * 256 + j];
        const float y = x * sigf(v * x) * rsqrtf(var + 1e-5f) * g + bb;
        const __nv_bfloat16 hi = __float2bfloat16(y);
        const __nv_bfloat16 lo = __float2bfloat16(y - __bfloat162float(hi));
        g_Ah[(size_t)(r0 + r) * 256 + j] = hi;
        g_Al[(size_t)(r0 + r) * 256 + j] = lo;
    }
}

// ===== Kernel D: HMMA bf16 3-split GEMM, CTA tile 128x128, serial K chunks ==
#define KD_SMEM 65536

__global__ void __launch_bounds__(256, 2)
kD(const float* __restrict__ bout, float* __restrict__ out)
{
    extern __shared__ __align__(1024) char smem[];
    const uint32_t ST = smem_u32(smem);
    const int tid = threadIdx.x;
    const int wid = tid >> 5, lane = tid & 31;
    const int warp_m = wid & 1;
    const int warp_n = wid >> 1;
    const int n0 = blockIdx.x * 128;
    const int m0 = blockIdx.y * 128;

    const uint32_t a_row = warp_m * 64 + (lane & 15);
    const uint32_t a_kb  = (uint32_t)(lane >> 4) * 16;
    const uint32_t b_row = warp_n * 32 + (lane & 7) + ((lane >> 4) & 1) * 8;
    const uint32_t b_kb  = (uint32_t)((lane >> 3) & 1) * 16;

    float acc[4][4][4];
    #pragma unroll
    for (int i = 0; i < 4; i++)
        #pragma unroll
        for (int j = 0; j < 4; j++)
            #pragma unroll
            for (int q = 0; q < 4; q++) acc[i][j][q] = 0.f;

    for (int kc = 0; kc < 4; kc++) {
        const int koff = kc * 64;
        #pragma unroll
        for (int sp = 0; sp < 2; sp++) {
            const __nv_bfloat16* gA = sp ? g_Al : g_Ah;
            const uint32_t db = ST + sp * 16384;
            #pragma unroll
            for (int i = 0; i < 4; i++) {
                const int g = tid + i * 256;
                const int row = g >> 3, j = g & 7;
                CP_ASYNC16(db + SWZ(row * 128 + j * 16),
                           gA + (size_t)(m0 + row) * 256 + koff + j * 8);
            }
        }
        #pragma unroll
        for (int sp = 0; sp < 2; sp++) {
            const __nv_bfloat16* gB = sp ? g_Bl : g_Bh;
            const uint32_t db = ST + 32768 + sp * 16384;
            #pragma unroll
            for (int i = 0; i < 4; i++) {
                const int g = tid + i * 256;
                const int row = g >> 3, j = g & 7;
                CP_ASYNC16(db + SWZ(row * 128 + j * 16),
                           gB + (size_t)(n0 + row) * 256 + koff + j * 8);
            }
        }
        CP_COMMIT();
        CP_WAIT_ALL();
        __syncthreads();

        #pragma unroll
        for (int split = 0; split < 3; split++) {
            const uint32_t Abase = ST + (split == 2 ? 16384u : 0u);
            const uint32_t Bbase = ST + 32768u + (split == 1 ? 16384u : 0u);
            #pragma unroll
            for (int ks = 0; ks < 4; ks++) {
                const uint32_t kk2 = (uint32_t)ks * 32;
                uint32_t af[4][4];
                #pragma unroll
                for (int mb = 0; mb < 4; mb++) {
                    const uint32_t addr = Abase + SWZ((a_row + mb * 16) * 128 + kk2 + a_kb);
                    LDSM_X4(af[mb][0], af[mb][1], af[mb][2], af[mb][3], addr);
                }
                uint32_t bfr[2][4];
                #pragma unroll
                for (int nb2 = 0; nb2 < 2; nb2++) {
                    const uint32_t addr = Bbase + SWZ((b_row + nb2 * 16) * 128 + kk2 + b_kb);
                    LDSM_X4(bfr[nb2][0], bfr[nb2][1], bfr[nb2][2], bfr[nb2][3], addr);
                }
                #pragma unroll
                for (int mb = 0; mb < 4; mb++) {
                    MMA16816(acc[mb][0], af[mb], bfr[0][0], bfr[0][1]);
                    MMA16816(acc[mb][1], af[mb], bfr[0][2], bfr[0][3]);
                    MMA16816(acc[mb][2], af[mb], bfr[1][0], bfr[1][1]);
                    MMA16816(acc[mb][3], af[mb], bfr[1][2], bfr[1][3]);
                }
            }
        }
        __syncthreads();
    }

    #pragma unroll
    for (int nb = 0; nb < 4; nb++) {
        const int col = n0 + warp_n * 32 + nb * 8 + (lane & 3) * 2;
        const float2 bb = *(const float2*)&bout[col];
        #pragma unroll
        for (int mb = 0; mb < 4; mb++) {
            const int row = m0 + warp_m * 64 + mb * 16 + (lane >> 2);
            float2 v0, v1;
            v0.x = acc[mb][nb][0] + bb.x;  v0.y = acc[mb][nb][1] + bb.y;
            v1.x = acc[mb][nb][2] + bb.x;  v1.y = acc[mb][nb][3] + bb.y;
            *(float2*)&out[(size_t)row * NPAR + col]       = v0;
            *(float2*)&out[(size_t)(row + 8) * NPAR + col] = v1;
        }
    }
}

// ============================================================================
extern "C" void kernel_launch(void* const* d_in, const int* in_sizes, int n_in,
                              void* d_out, int out_size)
{
    const float* actions = (const float*)d_in[0];
    const float* obs     = (const float*)d_in[1];
    const float* Wci     = (const float*)d_in[2];
    const float* vci     = (const float*)d_in[3];
    const float* gci     = (const float*)d_in[4];
    const float* bci     = (const float*)d_in[5];
    const float* Wcl     = (const float*)d_in[6];
    const float* bcl     = (const float*)d_in[7];
    const float* Win     = (const float*)d_in[8];
    const float* vin     = (const float*)d_in[9];
    const float* gin     = (const float*)d_in[10];
    const float* bin     = (const float*)d_in[11];
    const float* Wk      = (const float*)d_in[12];
    const float* Wr      = (const float*)d_in[13];
    const float* vl      = (const float*)d_in[14];
    const float* gl      = (const float*)d_in[15];
    const float* bl      = (const float*)d_in[16];
    const float* Wd0     = (const float*)d_in[17];
    const float* vd0     = (const float*)d_in[18];
    const float* gd0     = (const float*)d_in[19];
    const float* bd0     = (const float*)d_in[20];
    const float* Wout    = (const float*)d_in[21];
    const float* bout    = (const float*)d_in[22];
    float* out = (float*)d_out;

    kW<<<NPAR / 32, 256>>>(Wout);
    kA<<<128, 256>>>(actions, obs, Wci, vci, gci, bci, Wcl, bcl,
                     Win, vin, gin, bin, Wk);
    kB<<<8, 512>>>(Wr, vl, gl, bl);
    kC<<<128, 256>>>(Wd0, vd0, gd0, bd0);

    cudaFuncSetAttribute(kD, cudaFuncAttributeMaxDynamicSharedMemorySize, KD_SMEM);
    dim3 gD(NPAR / 128, NB / 128);
    kD<<<gD, 256, KD_SMEM>>>(bout, out);
}

// round 11
// speedup vs baseline: 2.0639x; 1.0030x over previous
#include <cuda_runtime.h>
#include <cuda_bf16.h>
#include <cstdint>

#define NB     2048
#define NPAR   66048

// Scratch (device globals; allocation is forbidden)
__device__ __align__(16) float g_G [NB * 1024];            // X@Wk precomputed gates
__device__ __align__(16) float g_H [NB * 256];             // LSTM hidden outputs
__device__ __align__(16) __nv_bfloat16 g_Ah[NB * 256];     // X3 hi (bf16 split)
__device__ __align__(16) __nv_bfloat16 g_Al[NB * 256];     // X3 lo
__device__ __align__(16) __nv_bfloat16 g_Bh[(size_t)NPAR * 256]; // W^T hi, K-major [n][k]
__device__ __align__(16) __nv_bfloat16 g_Bl[(size_t)NPAR * 256]; // W^T lo

__device__ __forceinline__ float sigf(float x) {
    return __frcp_rn(1.0f + __expf(-x));
}

__device__ __forceinline__ float2 fma2(float2 a, float2 b, float2 c) {
    unsigned long long A, Bv, C, D;
    asm("mov.b64 %0, {%1,%2};" : "=l"(A)  : "f"(a.x), "f"(a.y));
    asm("mov.b64 %0, {%1,%2};" : "=l"(Bv) : "f"(b.x), "f"(b.y));
    asm("mov.b64 %0, {%1,%2};" : "=l"(C)  : "f"(c.x), "f"(c.y));
    asm("fma.rn.f32x2 %0, %1, %2, %3;" : "=l"(D) : "l"(A), "l"(Bv), "l"(C));
    float2 r;
    asm("mov.b64 {%0,%1}, %2;" : "=f"(r.x), "=f"(r.y) : "l"(D));
    return r;
}

__device__ __forceinline__ unsigned smem_u32(const void* p) {
    unsigned a;
    asm("{ .reg .u64 t; cvta.to.shared.u64 t, %1; cvt.u32.u64 %0, t; }" : "=r"(a) : "l"(p));
    return a;
}

// ---- async-copy / HMMA helpers ---------------------------------------------
#define SWZ(x) ((x) ^ (((x) >> 3) & 0x70))

#define CP_ASYNC16(dst, src) \
    asm volatile("cp.async.cg.shared.global [%0], [%1], 16;" :: "r"(dst), "l"(src) : "memory")
#define CP_COMMIT()  asm volatile("cp.async.commit_group;" ::: "memory")
#define CP_WAIT_ALL() asm volatile("cp.async.wait_all;" ::: "memory")

#define LDSM_X4(r0, r1, r2, r3, addr) \
    asm volatile("ldmatrix.sync.aligned.m8n8.x4.shared.b16 {%0,%1,%2,%3}, [%4];" \
                 : "=r"(r0), "=r"(r1), "=r"(r2), "=r"(r3) : "r"(addr))

#define MMA16816(d, a, b0, b1) \
    asm volatile("mma.sync.aligned.m16n8k16.row.col.f32.bf16.bf16.f32 " \
                 "{%0,%1,%2,%3}, {%4,%5,%6,%7}, {%8,%9}, {%0,%1,%2,%3};" \
                 : "+f"((d)[0]), "+f"((d)[1]), "+f"((d)[2]), "+f"((d)[3]) \
                 : "r"((a)[0]), "r"((a)[1]), "r"((a)[2]), "r"((a)[3]), \
                   "r"(b0), "r"(b1))

// ===== Kernel WA: fused kW (blocks 0..2063) + kA (blocks 2064..2191) ========
// kW part: split+transpose W_out -> g_Bh/g_Bl K-major.
// kA part: cond path + dense_in + G = x_in @ Wk (16 batch rows per block).
#define KWA_NW (NPAR / 32)   // 2064

__global__ __launch_bounds__(256) void kWA(
    const float* __restrict__ Wout,
    const float* __restrict__ actions, const float* __restrict__ obs,
    const float* __restrict__ Wci, const float* __restrict__ vci,
    const float* __restrict__ gci, const float* __restrict__ bci,
    const float* __restrict__ Wcl, const float* __restrict__ bcl,
    const float* __restrict__ Win, const float* __restrict__ vin,
    const float* __restrict__ gin, const float* __restrict__ bin,
    const float* __restrict__ Wk)
{
    __shared__ float sm1[16 * 256];
    __shared__ float sm2[16 * 256];
    const int tid = threadIdx.x;

    if (blockIdx.x < KWA_NW) {
        // ------- kW part: transpose+split a 256k x 32n block -------
        float* sm = sm1;   // needs 32*257 = 8224 floats; sm1+sm2 = 8192... use both
        // 32*257 = 8224 > 4096; sm1 is 4096 floats. Use a flat view across both:
        // sm1 and sm2 are adjacent declarations but adjacency isn't guaranteed;
        // instead use stride 256 (no padding) + XOR swizzle to avoid conflicts.
        const int n0 = blockIdx.x * 32;
        // load: sm[j*256 + k] with k-major writes, XOR-swizzled bank rotation
        #pragma unroll 4
        for (int it = 0; it < 32; it++) {
            const int idx = it * 256 + tid;
            const int k = idx >> 5, j = idx & 31;
            sm[j * 256 + (k ^ j)] = Wout[(size_t)k * NPAR + n0 + j];
        }
        __syncthreads();
        const int j  = tid & 31;
        const int kq = tid >> 5;
        __nv_bfloat16* ph = g_Bh + (size_t)(n0 + j) * 256 + kq * 32;
        __nv_bfloat16* pl = g_Bl + (size_t)(n0 + j) * 256 + kq * 32;
        #pragma unroll
        for (int kk = 0; kk < 32; kk++) {
            const float w = sm[j * 256 + ((kq * 32 + kk) ^ j)];
            const __nv_bfloat16 hi = __float2bfloat16(w);
            const __nv_bfloat16 lo = __float2bfloat16(w - __bfloat162float(hi));
            ph[kk] = hi;
            pl[kk] = lo;
        }
        return;
    }

    // ------- kA part -------
    const int r0 = (blockIdx.x - KWA_NW) * 16;

    { // t1 = actions @ Wci -> sm1[16][64]
        const int j = tid & 63, rr = tid >> 6;
        #pragma unroll
        for (int q = 0; q < 4; q++) {
            const int r = rr + q * 4;
            float acc = 0.f;
            #pragma unroll
            for (int k = 0; k < 16; k++)
                acc += actions[(r0 + r) * 16 + k] * Wci[k * 64 + j];
            sm1[r * 64 + j] = acc;
        }
    }
    __syncthreads();
    { // evonorm(groups=8) -> sm2[16][64]
        const int j = tid & 63, rr = tid >> 6;
        const float v = vci[j], g = gci[j], bb = bci[j];
        #pragma unroll
        for (int q = 0; q < 4; q++) {
            const int r = rr + q * 4;
            const float* row = &sm1[r * 64 + (j & ~7)];
            float s1 = 0.f, s2 = 0.f;
            #pragma unroll
            for (int e = 0; e < 8; e++) { float t = row[e]; s1 += t; s2 += t * t; }
            const float mean = s1 * 0.125f;
            const float var  = s2 * 0.125f - mean * mean;
            const float x = sm1[r * 64 + j];
            sm2[r * 64 + j] = x * sigf(v * x) * rsqrtf(var + 1e-5f) * g + bb;
        }
    }
    __syncthreads();
    { // x = a1 @ Wcl + bcl + obs -> sm1[16][64]
        const int j = tid & 63, rr = tid >> 6;
        const float bj = bcl[j];
        float acc[4];
        #pragma unroll
        for (int q = 0; q < 4; q++)
            acc[q] = bj + obs[(r0 + rr + q * 4) * 64 + j];
        for (int k = 0; k < 64; k++) {
            const float w = Wcl[k * 64 + j];
            #pragma unroll
            for (int q = 0; q < 4; q++)
                acc[q] += sm2[(rr + q * 4) * 64 + k] * w;
        }
        #pragma unroll
        for (int q = 0; q < 4; q++)
            sm1[(rr + q * 4) * 64 + j] = acc[q];
    }
    __syncthreads();
    { // t2 = x @ Win -> sm2[16][256]
        const int j = tid;
        float acc[16];
        #pragma unroll
        for (int r = 0; r < 16; r++) acc[r] = 0.f;
        for (int k = 0; k < 64; k++) {
            const float w = Win[k * 256 + j];
            #pragma unroll
            for (int r = 0; r < 16; r++) acc[r] += sm1[r * 64 + k] * w;
        }
        #pragma unroll
        for (int r = 0; r < 16; r++) sm2[r * 256 + j] = acc[r];
    }
    __syncthreads();
    { // evonorm(group size 8) -> sm1[16][256]
        const int j = tid;
        const float v = vin[j], g = gin[j], bb = bin[j];
        for (int r = 0; r < 16; r++) {
            const float* row = &sm2[r * 256 + (j & ~7)];
            float s1 = 0.f, s2 = 0.f;
            #pragma unroll
            for (int e = 0; e < 8; e++) { float t = row[e]; s1 += t; s2 += t * t; }
            const float mean = s1 * 0.125f;
            const float var  = s2 * 0.125f - mean * mean;
            const float x = sm2[r * 256 + j];
            sm1[r * 256 + j] = x * sigf(v * x) * rsqrtf(var + 1e-5f) * g + bb;
        }
    }
    __syncthreads();
    { // G = x_in @ Wk  (thread: 4 cols x 16 rows)
        const int c0 = tid * 4;
        float2 acc[16][2];
        #pragma unroll
        for (int r = 0; r < 16; r++) { acc[r][0] = make_float2(0.f,0.f); acc[r][1] = make_float2(0.f,0.f); }
        for (int k = 0; k < 256; k++) {
            const float4 w4 = *(const float4*)&Wk[k * 1024 + c0];
            const float2 wa = make_float2(w4.x, w4.y);
            const float2 wb = make_float2(w4.z, w4.w);
            #pragma unroll
            for (int r = 0; r < 16; r++) {
                const float x = sm1[r * 256 + k];
                const float2 xx = make_float2(x, x);
                acc[r][0] = fma2(wa, xx, acc[r][0]);
                acc[r][1] = fma2(wb, xx, acc[r][1]);
            }
        }
        #pragma unroll
        for (int r = 0; r < 16; r++) {
            float4 o;
            o.x = acc[r][0].x; o.y = acc[r][0].y; o.z = acc[r][1].x; o.w = acc[r][1].y;
            *(float4*)&g_G[(size_t)(r0 + r) * 1024 + c0] = o;
        }
    }
}

// ===== Kernel B: sequential LSTM, 8-CTA cluster =============================
// Thread (g, kw): g = col-group (4 cols), kw = k-window (16 k's).
// s_part double-buffered by step parity; warps 4-15 skip the phase2/cell
// barrier (bar.sync 1 among warps 0-3 only) and park at the next iteration's
// __syncthreads. Phase2 reduces 16 partials with an explicit pairwise tree.
__global__ void __launch_bounds__(512, 1) __cluster_dims__(8, 1, 1)
kB(const float* __restrict__ Wr, const float* __restrict__ vl_,
   const float* __restrict__ gl_, const float* __restrict__ bl_)
{
    __shared__ __align__(16) float s_hb[2][256];        // h buffers (remote-written)
    __shared__ __align__(16) float s_part[2][16 * 128]; // GEMV partials, 2x8KB
    __shared__ __align__(16) float s_z[128];
    __shared__ __align__(16) float s_hout[32];
    __shared__ __align__(8)  unsigned long long s_mbar[2];

    const int tid = threadIdx.x;
    unsigned rank;
    asm("mov.u32 %0, %%cluster_ctarank;" : "=r"(rank));

    const int g   = tid & 31;        // col-group: cols [g*4, g*4+4)
    const int kw  = tid >> 5;        // k-window:  k    [kw*16, kw*16+16)
    const int gg  = g >> 3;          // gate 0..3
    const int cc0 = (g & 7) * 4;     // channel base within this CTA's 32
    const int gcol0 = gg * 256 + (int)rank * 32 + cc0;   // global col of c=0

    // register-resident weights: w[j][c], 64 fp32 per thread
    float w[16][4];
    #pragma unroll
    for (int j = 0; j < 16; j++)
        #pragma unroll
        for (int c = 0; c < 4; c++)
            w[j][c] = Wr[(size_t)(kw * 16 + j) * 1024 + gcol0 + c];

    // cell params for warp 0 (channel ch = rank*32 + lane)
    float vl = 0.f, gl = 0.f, bl = 0.f, cst = 0.f;
    if (tid < 32) {
        const int ch = (int)rank * 32 + tid;
        vl = vl_[ch]; gl = gl_[ch]; bl = bl_[ch];
    }

    // push addresses for warp0 lanes 0-7 (lane = dest CTA)
    unsigned r_h0 = 0, r_h1 = 0, r_b0 = 0, r_b1 = 0;
    if (tid < 8) {
        const unsigned d = (unsigned)tid;
        unsigned lh0 = smem_u32(&s_hb[0][rank * 32]);
        unsigned lh1 = smem_u32(&s_hb[1][rank * 32]);
        unsigned lb0 = smem_u32(&s_mbar[0]);
        unsigned lb1 = smem_u32(&s_mbar[1]);
        asm("mapa.shared::cluster.u32 %0, %1, %2;" : "=r"(r_h0) : "r"(lh0), "r"(d));
        asm("mapa.shared::cluster.u32 %0, %1, %2;" : "=r"(r_h1) : "r"(lh1), "r"(d));
        asm("mapa.shared::cluster.u32 %0, %1, %2;" : "=r"(r_b0) : "r"(lb0), "r"(d));
        asm("mapa.shared::cluster.u32 %0, %1, %2;" : "=r"(r_b1) : "r"(lb1), "r"(d));
    }

    if (tid == 0) {
        asm volatile("mbarrier.init.shared.b64 [%0], %1;" :: "r"(smem_u32(&s_mbar[0])), "r"(8u) : "memory");
        asm volatile("mbarrier.init.shared.b64 [%0], %1;" :: "r"(smem_u32(&s_mbar[1])), "r"(8u) : "memory");
    }
    if (tid < 256) { s_hb[0][tid] = 0.f; s_hb[1][tid] = 0.f; }
    __syncthreads();
    asm volatile("barrier.cluster.arrive.aligned;" ::: "memory");
    asm volatile("barrier.cluster.wait.aligned;"   ::: "memory");

    // initial push: zeros (h_{-1}) into buffer 1
    if (tid < 8) {
        #pragma unroll
        for (int i = 0; i < 8; i++)
            asm volatile("st.shared::cluster.v4.f32 [%0], {%1,%1,%1,%1};"
                         :: "r"(r_h1 + i * 16), "f"(0.f) : "memory");
        asm volatile("mbarrier.arrive.release.cluster.shared::cluster.b64 _, [%0];"
                     :: "r"(r_b1) : "memory");
    }

    unsigned par0 = 0u, par1 = 0u;

    // prefetch gate term for step 0 (phase-2 threads)
    const int gcol2 = (tid >> 5) * 256 + (int)rank * 32 + (tid & 31);
    float gt = (tid < 128) ? g_G[gcol2] : 0.f;

    for (int t = 0; t < NB; t++) {
        const int rb = (t + 1) & 1;      // buffer holding h_{t-1}
        const int wb = t & 1;            // buffer receiving h_t
        const int pp = t & 1;            // s_part parity

        { // wait for all 8 source-CTA pushes of h_{t-1}
            const unsigned a = smem_u32(&s_mbar[rb]);
            const unsigned ph = rb ? par1 : par0;
            unsigned done;
            asm volatile(
                "{\n\t.reg .pred p;\n\t"
                "mbarrier.try_wait.parity.acquire.cluster.shared::cta.b64 p, [%1], %2;\n\t"
                "selp.b32 %0, 1, 0, p;\n\t}"
                : "=r"(done) : "r"(a), "r"(ph) : "memory");
            if (!done) {
                asm volatile(
                    "{\n\t.reg .pred P1;\n\t"
                    "WLB_%=:\n\t"
                    "mbarrier.try_wait.parity.acquire.cluster.shared::cta.b64 P1, [%0], %1, 0x989680;\n\t"
                    "@P1 bra.uni WDB_%=;\n\t"
                    "bra.uni WLB_%=;\n\t"
                    "WDB_%=:\n\t}"
                    :: "r"(a), "r"(ph) : "memory");
            }
            if (rb) par1 ^= 1u; else par0 ^= 1u;
        }

        // ---- GEMV phase 1: 4 cols x 16 k per thread -> s_part[pp] ----
        {
            const float4* hv = (const float4*)(&s_hb[rb][kw * 16]);
            const float4 h0 = hv[0], h1 = hv[1], h2 = hv[2], h3 = hv[3];
            float a0, a1, a2, a3;
            a0 = w[0][0] * h0.x;  a1 = w[0][1] * h0.x;
            a2 = w[0][2] * h0.x;  a3 = w[0][3] * h0.x;
            #define KSTEP(j, hval) \
                a0 = fmaf(w[j][0], hval, a0); a1 = fmaf(w[j][1], hval, a1); \
                a2 = fmaf(w[j][2], hval, a2); a3 = fmaf(w[j][3], hval, a3);
            KSTEP(1,  h0.y) KSTEP(2,  h0.z) KSTEP(3,  h0.w)
            KSTEP(4,  h1.x) KSTEP(5,  h1.y) KSTEP(6,  h1.z) KSTEP(7,  h1.w)
            KSTEP(8,  h2.x) KSTEP(9,  h2.y) KSTEP(10, h2.z) KSTEP(11, h2.w)
            KSTEP(12, h3.x) KSTEP(13, h3.y) KSTEP(14, h3.z) KSTEP(15, h3.w)
            #undef KSTEP
            float4 p; p.x = a0; p.y = a1; p.z = a2; p.w = a3;
            *(float4*)&s_part[pp][kw * 128 + g * 4] = p;
        }
        __syncthreads();   // all 512: partials of step t visible

        // ---- phase2 + cell: warps 0-3 only; warps 4-15 go to next wait ----
        if (tid < 128) {
            float v[16];
            #pragma unroll
            for (int k2 = 0; k2 < 16; k2++)
                v[k2] = s_part[pp][k2 * 128 + tid];
            const float s =
                (((v[0] + v[1]) + (v[2] + v[3])) + ((v[4] + v[5]) + (v[6] + v[7]))) +
                (((v[8] + v[9]) + (v[10] + v[11])) + ((v[12] + v[13]) + (v[14] + v[15]))) + gt;
            s_z[tid] = s;
            if (t + 1 < NB) gt = g_G[(size_t)(t + 1) * 1024 + gcol2];

            asm volatile("bar.sync 1, 128;" ::: "memory");

            if (tid < 32) {
                const float zi = s_z[tid];
                const float zf = s_z[32 + tid];
                const float zc = s_z[64 + tid];
                const float zo = s_z[96 + tid];

                float s1 = zc, s2 = zc * zc;
                s1 += __shfl_xor_sync(0xffffffffu, s1, 1);  s2 += __shfl_xor_sync(0xffffffffu, s2, 1);
                s1 += __shfl_xor_sync(0xffffffffu, s1, 2);  s2 += __shfl_xor_sync(0xffffffffu, s2, 2);
                s1 += __shfl_xor_sync(0xffffffffu, s1, 4);  s2 += __shfl_xor_sync(0xffffffffu, s2, 4);
                float mean = s1 * 0.125f;
                float var  = s2 * 0.125f - mean * mean;
                const float ecc = zc * sigf(vl * zc) * rsqrtf(var + 1e-5f) * gl + bl;

                cst = sigf(zf) * cst + sigf(zi) * ecc;

                s1 = cst; s2 = cst * cst;
                s1 += __shfl_xor_sync(0xffffffffu, s1, 1);  s2 += __shfl_xor_sync(0xffffffffu, s2, 1);
                s1 += __shfl_xor_sync(0xffffffffu, s1, 2);  s2 += __shfl_xor_sync(0xffffffffu, s2, 2);
                s1 += __shfl_xor_sync(0xffffffffu, s1, 4);  s2 += __shfl_xor_sync(0xffffffffu, s2, 4);
                mean = s1 * 0.125f;
                var  = s2 * 0.125f - mean * mean;
                const float ecn = cst * sigf(vl * cst) * rsqrtf(var + 1e-5f) * gl + bl;

                const float h = sigf(zo) * ecn;
                s_hout[tid] = h;
                __syncwarp();

                // push h_t: lane d -> dest CTA d (8 x st.v4 + 1 release-arrive)
                if (tid < 8) {
                    const unsigned rh  = wb ? r_h1 : r_h0;
                    const unsigned rbb = wb ? r_b1 : r_b0;
                    #pragma unroll
                    for (int i = 0; i < 8; i++) {
                        const float4 hv4 = *(const float4*)&s_hout[i * 4];
                        asm volatile("st.shared::cluster.v4.f32 [%0], {%1,%2,%3,%4};"
                                     :: "r"(rh + i * 16), "f"(hv4.x), "f"(hv4.y), "f"(hv4.z), "f"(hv4.w)
                                     : "memory");
                    }
                    asm volatile("mbarrier.arrive.release.cluster.shared::cluster.b64 _, [%0];"
                                 :: "r"(rbb) : "memory");
                }
                g_H[(size_t)t * 256 + rank * 32 + tid] = h;
            }
        }
    }

    asm volatile("barrier.cluster.arrive.aligned;" ::: "memory");
    asm volatile("barrier.cluster.wait.aligned;"   ::: "memory");
}

// ===== Kernel C: dense_0 + evonorm -> bf16 hi/lo split (g_Ah/g_Al) ==========
__global__ __launch_bounds__(256) void kC(
    const float* __restrict__ Wd0, const float* __restrict__ vd,
    const float* __restrict__ gd,  const float* __restrict__ bd)
{
    __shared__ float sm1[16 * 256];
    __shared__ float sm2[16 * 256];
    const int tid = threadIdx.x;
    const int r0  = blockIdx.x * 16;

    const float4* src = (const float4*)(g_H + (size_t)r0 * 256);
    for (int i = tid; i < 1024; i += 256)
        ((float4*)sm1)[i] = src[i];
    __syncthreads();

    const int j = tid;
    float acc[16];
    #pragma unroll
    for (int r = 0; r < 16; r++) acc[r] = 0.f;
    for (int k4 = 0; k4 < 64; k4++) {
        const int k = k4 * 4;
        const float w0 = Wd0[(k+0)*256 + j];
        const float w1 = Wd0[(k+1)*256 + j];
        const float w2 = Wd0[(k+2)*256 + j];
        const float w3 = Wd0[(k+3)*256 + j];
        #pragma unroll
        for (int r = 0; r < 16; r++) {
            const float4 x = *(const float4*)&sm1[r * 256 + k];
            acc[r] += x.x*w0 + x.y*w1 + x.z*w2 + x.w*w3;
        }
    }
    #pragma unroll
    for (int r = 0; r < 16; r++) sm2[r * 256 + j] = acc[r];
    __syncthreads();

    const float v = vd[j], g = gd[j], bb = bd[j];
    for (int r = 0; r < 16; r++) {
        const float* row = &sm2[r * 256 + (j & ~7)];
        float s1 = 0.f, s2 = 0.f;
        #pragma unroll
        for (int e = 0; e < 8; e++) { float t = row[e]; s1 += t; s2 += t * t; }
        const float mean = s1 * 0.125f;
        const float var  = s2 * 0.125f - mean * mean;
        const float x = sm2[r * 256 + j];
        const float y = x * sigf(v * x) * rsqrtf(var + 1e-5f) * g + bb;
        const __nv_bfloat16 hi = __float2bfloat16(y);
        const __nv_bfloat16 lo = __float2bfloat16(y - __bfloat162float(hi));
        g_Ah[(size_t)(r0 + r) * 256 + j] = hi;
        g_Al[(size_t)(r0 + r) * 256 + j] = lo;
    }
}

// ===== Kernel D: HMMA bf16 3-split GEMM, CTA tile 128x128, serial K chunks ==
#define KD_SMEM 65536

__global__ void __launch_bounds__(256, 2)
kD(const float* __restrict__ bout, float* __restrict__ out)
{
    extern __shared__ __align__(1024) char smem[];
    const uint32_t ST = smem_u32(smem);
    const int tid = threadIdx.x;
    const int wid = tid >> 5, lane = tid & 31;
    const int warp_m = wid & 1;
    const int warp_n = wid >> 1;
    const int n0 = blockIdx.x * 128;
    const int m0 = blockIdx.y * 128;

    const uint32_t a_row = warp_m * 64 + (lane & 15);
    const uint32_t a_kb  = (uint32_t)(lane >> 4) * 16;
    const uint32_t b_row = warp_n * 32 + (lane & 7) + ((lane >> 4) & 1) * 8;
    const uint32_t b_kb  = (uint32_t)((lane >> 3) & 1) * 16;

    float acc[4][4][4];
    #pragma unroll
    for (int i = 0; i < 4; i++)
        #pragma unroll
        for (int j = 0; j < 4; j++)
            #pragma unroll
            for (int q = 0; q < 4; q++) acc[i][j][q] = 0.f;

    for (int kc = 0; kc < 4; kc++) {
        const int koff = kc * 64;
        #pragma unroll
        for (int sp = 0; sp < 2; sp++) {
            const __nv_bfloat16* gA = sp ? g_Al : g_Ah;
            const uint32_t db = ST + sp * 16384;
            #pragma unroll
            for (int i = 0; i < 4; i++) {
                const int g = tid + i * 256;
                const int row = g >> 3, j = g & 7;
                CP_ASYNC16(db + SWZ(row * 128 + j * 16),
                           gA + (size_t)(m0 + row) * 256 + koff + j * 8);
            }
        }
        #pragma unroll
        for (int sp = 0; sp < 2; sp++) {
            const __nv_bfloat16* gB = sp ? g_Bl : g_Bh;
            const uint32_t db = ST + 32768 + sp * 16384;
            #pragma unroll
            for (int i = 0; i < 4; i++) {
                const int g = tid + i * 256;
                const int row = g >> 3, j = g & 7;
                CP_ASYNC16(db + SWZ(row * 128 + j * 16),
                           gB + (size_t)(n0 + row) * 256 + koff + j * 8);
            }
        }
        CP_COMMIT();
        CP_WAIT_ALL();
        __syncthreads();

        #pragma unroll
        for (int split = 0; split < 3; split++) {
            const uint32_t Abase = ST + (split == 2 ? 16384u : 0u);
            const uint32_t Bbase = ST + 32768u + (split == 1 ? 16384u : 0u);
            #pragma unroll
            for (int ks = 0; ks < 4; ks++) {
                const uint32_t kk2 = (uint32_t)ks * 32;
                uint32_t af[4][4];
                #pragma unroll
                for (int mb = 0; mb < 4; mb++) {
                    const uint32_t addr = Abase + SWZ((a_row + mb * 16) * 128 + kk2 + a_kb);
                    LDSM_X4(af[mb][0], af[mb][1], af[mb][2], af[mb][3], addr);
                }
                uint32_t bfr[2][4];
                #pragma unroll
                for (int nb2 = 0; nb2 < 2; nb2++) {
                    const uint32_t addr = Bbase + SWZ((b_row + nb2 * 16) * 128 + kk2 + b_kb);
                    LDSM_X4(bfr[nb2][0], bfr[nb2][1], bfr[nb2][2], bfr[nb2][3], addr);
                }
                #pragma unroll
                for (int mb = 0; mb < 4; mb++) {
                    MMA16816(acc[mb][0], af[mb], bfr[0][0], bfr[0][1]);
                    MMA16816(acc[mb][1], af[mb], bfr[0][2], bfr[0][3]);
                    MMA16816(acc[mb][2], af[mb], bfr[1][0], bfr[1][1]);
                    MMA16816(acc[mb][3], af[mb], bfr[1][2], bfr[1][3]);
                }
            }
        }
        __syncthreads();
    }

    #pragma unroll
    for (int nb = 0; nb < 4; nb++) {
        const int col = n0 + warp_n * 32 + nb * 8 + (lane & 3) * 2;
        const float2 bb = *(const float2*)&bout[col];
        #pragma unroll
        for (int mb = 0; mb < 4; mb++) {
            const int row = m0 + warp_m * 64 + mb * 16 + (lane >> 2);
            float2 v0, v1;
            v0.x = acc[mb][nb][0] + bb.x;  v0.y = acc[mb][nb][1] + bb.y;
            v1.x = acc[mb][nb][2] + bb.x;  v1.y = acc[mb][nb][3] + bb.y;
            *(float2*)&out[(size_t)row * NPAR + col]       = v0;
            *(float2*)&out[(size_t)(row + 8) * NPAR + col] = v1;
        }
    }
}

// ============================================================================
extern "C" void kernel_launch(void* const* d_in, const int* in_sizes, int n_in,
                              void* d_out, int out_size)
{
    const float* actions = (const float*)d_in[0];
    const float* obs     = (const float*)d_in[1];
    const float* Wci     = (const float*)d_in[2];
    const float* vci     = (const float*)d_in[3];
    const float* gci     = (const float*)d_in[4];
    const float* bci     = (const float*)d_in[5];
    const float* Wcl     = (const float*)d_in[6];
    const float* bcl     = (const float*)d_in[7];
    const float* Win     = (const float*)d_in[8];
    const float* vin     = (const float*)d_in[9];
    const float* gin     = (const float*)d_in[10];
    const float* bin     = (const float*)d_in[11];
    const float* Wk      = (const float*)d_in[12];
    const float* Wr      = (const float*)d_in[13];
    const float* vl      = (const float*)d_in[14];
    const float* gl      = (const float*)d_in[15];
    const float* bl      = (const float*)d_in[16];
    const float* Wd0     = (const float*)d_in[17];
    const float* vd0     = (const float*)d_in[18];
    const float* gd0     = (const float*)d_in[19];
    const float* bd0     = (const float*)d_in[20];
    const float* Wout    = (const float*)d_in[21];
    const float* bout    = (const float*)d_in[22];
    float* out = (float*)d_out;

    kWA<<<KWA_NW + 128, 256>>>(Wout, actions, obs, Wci, vci, gci, bci, Wcl, bcl,
                               Win, vin, gin, bin, Wk);
    kB<<<8, 512>>>(Wr, vl, gl, bl);
    kC<<<128, 256>>>(Wd0, vd0, gd0, bd0);

    cudaFuncSetAttribute(kD, cudaFuncAttributeMaxDynamicSharedMemorySize, KD_SMEM);
    dim3 gD(NPAR / 128, NB / 128);
    kD<<<gD, 256, KD_SMEM>>>(bout, out);
}

// round 12
// speedup vs baseline: 2.0654x; 1.0007x over previous
#include <cuda_runtime.h>
#include <cuda_bf16.h>
#include <cstdint>

#define NB     2048
#define NPAR   66048

// Scratch (device globals; allocation is forbidden)
__device__ __align__(16) float g_G [NB * 1024];            // X@Wk precomputed gates
__device__ __align__(16) float g_H [NB * 256];             // LSTM hidden outputs
__device__ __align__(16) __nv_bfloat16 g_Ah[NB * 256];     // X3 hi (bf16 split)
__device__ __align__(16) __nv_bfloat16 g_Al[NB * 256];     // X3 lo
__device__ __align__(16) __nv_bfloat16 g_Bh[(size_t)NPAR * 256]; // W^T hi, K-major [n][k]
__device__ __align__(16) __nv_bfloat16 g_Bl[(size_t)NPAR * 256]; // W^T lo

__device__ __forceinline__ float sigf(float x) {
    return __frcp_rn(1.0f + __expf(-x));
}

__device__ __forceinline__ float2 fma2(float2 a, float2 b, float2 c) {
    unsigned long long A, Bv, C, D;
    asm("mov.b64 %0, {%1,%2};" : "=l"(A)  : "f"(a.x), "f"(a.y));
    asm("mov.b64 %0, {%1,%2};" : "=l"(Bv) : "f"(b.x), "f"(b.y));
    asm("mov.b64 %0, {%1,%2};" : "=l"(C)  : "f"(c.x), "f"(c.y));
    asm("fma.rn.f32x2 %0, %1, %2, %3;" : "=l"(D) : "l"(A), "l"(Bv), "l"(C));
    float2 r;
    asm("mov.b64 {%0,%1}, %2;" : "=f"(r.x), "=f"(r.y) : "l"(D));
    return r;
}

// mov-free packed dual FMA: all operands already u64 register pairs
__device__ __forceinline__ unsigned long long fma2u(
    unsigned long long a, unsigned long long b, unsigned long long c) {
    unsigned long long d;
    asm("fma.rn.f32x2 %0, %1, %2, %3;" : "=l"(d) : "l"(a), "l"(b), "l"(c));
    return d;
}

__device__ __forceinline__ unsigned smem_u32(const void* p) {
    unsigned a;
    asm("{ .reg .u64 t; cvta.to.shared.u64 t, %1; cvt.u32.u64 %0, t; }" : "=r"(a) : "l"(p));
    return a;
}

// ---- async-copy / HMMA helpers ---------------------------------------------
#define SWZ(x) ((x) ^ (((x) >> 3) & 0x70))

#define CP_ASYNC16(dst, src) \
    asm volatile("cp.async.cg.shared.global [%0], [%1], 16;" :: "r"(dst), "l"(src) : "memory")
#define CP_COMMIT()  asm volatile("cp.async.commit_group;" ::: "memory")
#define CP_WAIT_ALL() asm volatile("cp.async.wait_all;" ::: "memory")

#define LDSM_X4(r0, r1, r2, r3, addr) \
    asm volatile("ldmatrix.sync.aligned.m8n8.x4.shared.b16 {%0,%1,%2,%3}, [%4];" \
                 : "=r"(r0), "=r"(r1), "=r"(r2), "=r"(r3) : "r"(addr))

#define MMA16816(d, a, b0, b1) \
    asm volatile("mma.sync.aligned.m16n8k16.row.col.f32.bf16.bf16.f32 " \
                 "{%0,%1,%2,%3}, {%4,%5,%6,%7}, {%8,%9}, {%0,%1,%2,%3};" \
                 : "+f"((d)[0]), "+f"((d)[1]), "+f"((d)[2]), "+f"((d)[3]) \
                 : "r"((a)[0]), "r"((a)[1]), "r"((a)[2]), "r"((a)[3]), \
                   "r"(b0), "r"(b1))

// ===== Kernel WA: fused kW (blocks 0..2063) + kA (blocks 2064..2191) ========
#define KWA_NW (NPAR / 32)   // 2064

__global__ __launch_bounds__(256) void kWA(
    const float* __restrict__ Wout,
    const float* __restrict__ actions, const float* __restrict__ obs,
    const float* __restrict__ Wci, const float* __restrict__ vci,
    const float* __restrict__ gci, const float* __restrict__ bci,
    const float* __restrict__ Wcl, const float* __restrict__ bcl,
    const float* __restrict__ Win, const float* __restrict__ vin,
    const float* __restrict__ gin, const float* __restrict__ bin,
    const float* __restrict__ Wk)
{
    __shared__ float sm1[16 * 256];
    __shared__ float sm2[16 * 256];
    const int tid = threadIdx.x;

    if (blockIdx.x < KWA_NW) {
        // ------- kW part: transpose+split a 256k x 32n block -------
        float* sm = sm1;
        const int n0 = blockIdx.x * 32;
        #pragma unroll 4
        for (int it = 0; it < 32; it++) {
            const int idx = it * 256 + tid;
            const int k = idx >> 5, j = idx & 31;
            sm[j * 256 + (k ^ j)] = Wout[(size_t)k * NPAR + n0 + j];
        }
        __syncthreads();
        const int j  = tid & 31;
        const int kq = tid >> 5;
        __nv_bfloat16* ph = g_Bh + (size_t)(n0 + j) * 256 + kq * 32;
        __nv_bfloat16* pl = g_Bl + (size_t)(n0 + j) * 256 + kq * 32;
        #pragma unroll
        for (int kk = 0; kk < 32; kk++) {
            const float w = sm[j * 256 + ((kq * 32 + kk) ^ j)];
            const __nv_bfloat16 hi = __float2bfloat16(w);
            const __nv_bfloat16 lo = __float2bfloat16(w - __bfloat162float(hi));
            ph[kk] = hi;
            pl[kk] = lo;
        }
        return;
    }

    // ------- kA part -------
    const int r0 = (blockIdx.x - KWA_NW) * 16;

    { // t1 = actions @ Wci -> sm1[16][64]
        const int j = tid & 63, rr = tid >> 6;
        #pragma unroll
        for (int q = 0; q < 4; q++) {
            const int r = rr + q * 4;
            float acc = 0.f;
            #pragma unroll
            for (int k = 0; k < 16; k++)
                acc += actions[(r0 + r) * 16 + k] * Wci[k * 64 + j];
            sm1[r * 64 + j] = acc;
        }
    }
    __syncthreads();
    { // evonorm(groups=8) -> sm2[16][64]
        const int j = tid & 63, rr = tid >> 6;
        const float v = vci[j], g = gci[j], bb = bci[j];
        #pragma unroll
        for (int q = 0; q < 4; q++) {
            const int r = rr + q * 4;
            const float* row = &sm1[r * 64 + (j & ~7)];
            float s1 = 0.f, s2 = 0.f;
            #pragma unroll
            for (int e = 0; e < 8; e++) { float t = row[e]; s1 += t; s2 += t * t; }
            const float mean = s1 * 0.125f;
            const float var  = s2 * 0.125f - mean * mean;
            const float x = sm1[r * 64 + j];
            sm2[r * 64 + j] = x * sigf(v * x) * rsqrtf(var + 1e-5f) * g + bb;
        }
    }
    __syncthreads();
    { // x = a1 @ Wcl + bcl + obs -> sm1[16][64]
        const int j = tid & 63, rr = tid >> 6;
        const float bj = bcl[j];
        float acc[4];
        #pragma unroll
        for (int q = 0; q < 4; q++)
            acc[q] = bj + obs[(r0 + rr + q * 4) * 64 + j];
        for (int k = 0; k < 64; k++) {
            const float w = Wcl[k * 64 + j];
            #pragma unroll
            for (int q = 0; q < 4; q++)
                acc[q] += sm2[(rr + q * 4) * 64 + k] * w;
        }
        #pragma unroll
        for (int q = 0; q < 4; q++)
            sm1[(rr + q * 4) * 64 + j] = acc[q];
    }
    __syncthreads();
    { // t2 = x @ Win -> sm2[16][256]
        const int j = tid;
        float acc[16];
        #pragma unroll
        for (int r = 0; r < 16; r++) acc[r] = 0.f;
        for (int k = 0; k < 64; k++) {
            const float w = Win[k * 256 + j];
            #pragma unroll
            for (int r = 0; r < 16; r++) acc[r] += sm1[r * 64 + k] * w;
        }
        #pragma unroll
        for (int r = 0; r < 16; r++) sm2[r * 256 + j] = acc[r];
    }
    __syncthreads();
    { // evonorm(group size 8) -> sm1[16][256]
        const int j = tid;
        const float v = vin[j], g = gin[j], bb = bin[j];
        for (int r = 0; r < 16; r++) {
            const float* row = &sm2[r * 256 + (j & ~7)];
            float s1 = 0.f, s2 = 0.f;
            #pragma unroll
            for (int e = 0; e < 8; e++) { float t = row[e]; s1 += t; s2 += t * t; }
            const float mean = s1 * 0.125f;
            const float var  = s2 * 0.125f - mean * mean;
            const float x = sm2[r * 256 + j];
            sm1[r * 256 + j] = x * sigf(v * x) * rsqrtf(var + 1e-5f) * g + bb;
        }
    }
    __syncthreads();
    { // G = x_in @ Wk  (thread: 4 cols x 16 rows)
        const int c0 = tid * 4;
        float2 acc[16][2];
        #pragma unroll
        for (int r = 0; r < 16; r++) { acc[r][0] = make_float2(0.f,0.f); acc[r][1] = make_float2(0.f,0.f); }
        for (int k = 0; k < 256; k++) {
            const float4 w4 = *(const float4*)&Wk[k * 1024 + c0];
            const float2 wa = make_float2(w4.x, w4.y);
            const float2 wb = make_float2(w4.z, w4.w);
            #pragma unroll
            for (int r = 0; r < 16; r++) {
                const float x = sm1[r * 256 + k];
                const float2 xx = make_float2(x, x);
                acc[r][0] = fma2(wa, xx, acc[r][0]);
                acc[r][1] = fma2(wb, xx, acc[r][1]);
            }
        }
        #pragma unroll
        for (int r = 0; r < 16; r++) {
            float4 o;
            o.x = acc[r][0].x; o.y = acc[r][0].y; o.z = acc[r][1].x; o.w = acc[r][1].y;
            *(float4*)&g_G[(size_t)(r0 + r) * 1024 + c0] = o;
        }
    }
}

// ===== Kernel B: sequential LSTM, 8-CTA cluster =============================
// Thread (g, kw): g = col-group (4 cols), kw = k-window (16 k's).
// GEMV phase1 uses mov-free packed f32x2 FMA: weights pre-packed as u64
// k-pairs, h loaded as b64, accumulators u64. Phase2: pairwise tree over 16
// partials (warps 0-3 only, bar.sync 1). Push: warp0 lanes 0-7, one
// release-arrive per source CTA.
__global__ void __launch_bounds__(512, 1) __cluster_dims__(8, 1, 1)
kB(const float* __restrict__ Wr, const float* __restrict__ vl_,
   const float* __restrict__ gl_, const float* __restrict__ bl_)
{
    __shared__ __align__(16) float s_hb[2][256];        // h buffers (remote-written)
    __shared__ __align__(16) float s_part[2][16 * 128]; // GEMV partials, 2x8KB
    __shared__ __align__(16) float s_z[128];
    __shared__ __align__(16) float s_hout[32];
    __shared__ __align__(8)  unsigned long long s_mbar[2];

    const int tid = threadIdx.x;
    unsigned rank;
    asm("mov.u32 %0, %%cluster_ctarank;" : "=r"(rank));

    const int g   = tid & 31;        // col-group: cols [g*4, g*4+4)
    const int kw  = tid >> 5;        // k-window:  k    [kw*16, kw*16+16)
    const int gg  = g >> 3;          // gate 0..3
    const int cc0 = (g & 7) * 4;     // channel base within this CTA's 32
    const int gcol0 = gg * 256 + (int)rank * 32 + cc0;   // global col of c=0
    const int k0    = kw * 16;

    // register-resident weights, packed as (k, k+1) pairs per column: u64
    unsigned long long wv[4][8];
    #pragma unroll
    for (int p = 0; p < 8; p++) {
        #pragma unroll
        for (int c = 0; c < 4; c++) {
            const float w0 = Wr[(size_t)(k0 + 2*p)     * 1024 + gcol0 + c];
            const float w1 = Wr[(size_t)(k0 + 2*p + 1) * 1024 + gcol0 + c];
            asm("mov.b64 %0, {%1,%2};" : "=l"(wv[c][p]) : "f"(w0), "f"(w1));
        }
    }

    // cell params for warp 0 (channel ch = rank*32 + lane)
    float vl = 0.f, gl = 0.f, bl = 0.f, cst = 0.f;
    if (tid < 32) {
        const int ch = (int)rank * 32 + tid;
        vl = vl_[ch]; gl = gl_[ch]; bl = bl_[ch];
    }

    // push addresses for warp0 lanes 0-7 (lane = dest CTA)
    unsigned r_h0 = 0, r_h1 = 0, r_b0 = 0, r_b1 = 0;
    if (tid < 8) {
        const unsigned d = (unsigned)tid;
        unsigned lh0 = smem_u32(&s_hb[0][rank * 32]);
        unsigned lh1 = smem_u32(&s_hb[1][rank * 32]);
        unsigned lb0 = smem_u32(&s_mbar[0]);
        unsigned lb1 = smem_u32(&s_mbar[1]);
        asm("mapa.shared::cluster.u32 %0, %1, %2;" : "=r"(r_h0) : "r"(lh0), "r"(d));
        asm("mapa.shared::cluster.u32 %0, %1, %2;" : "=r"(r_h1) : "r"(lh1), "r"(d));
        asm("mapa.shared::cluster.u32 %0, %1, %2;" : "=r"(r_b0) : "r"(lb0), "r"(d));
        asm("mapa.shared::cluster.u32 %0, %1, %2;" : "=r"(r_b1) : "r"(lb1), "r"(d));
    }

    if (tid == 0) {
        asm volatile("mbarrier.init.shared.b64 [%0], %1;" :: "r"(smem_u32(&s_mbar[0])), "r"(8u) : "memory");
        asm volatile("mbarrier.init.shared.b64 [%0], %1;" :: "r"(smem_u32(&s_mbar[1])), "r"(8u) : "memory");
    }
    if (tid < 256) { s_hb[0][tid] = 0.f; s_hb[1][tid] = 0.f; }
    __syncthreads();
    asm volatile("barrier.cluster.arrive.aligned;" ::: "memory");
    asm volatile("barrier.cluster.wait.aligned;"   ::: "memory");

    // initial push: zeros (h_{-1}) into buffer 1
    if (tid < 8) {
        #pragma unroll
        for (int i = 0; i < 8; i++)
            asm volatile("st.shared::cluster.v4.f32 [%0], {%1,%1,%1,%1};"
                         :: "r"(r_h1 + i * 16), "f"(0.f) : "memory");
        asm volatile("mbarrier.arrive.release.cluster.shared::cluster.b64 _, [%0];"
                     :: "r"(r_b1) : "memory");
    }

    unsigned par0 = 0u, par1 = 0u;

    // prefetch gate term for step 0 (phase-2 threads)
    const int gcol2 = (tid >> 5) * 256 + (int)rank * 32 + (tid & 31);
    float gt = (tid < 128) ? g_G[gcol2] : 0.f;

    for (int t = 0; t < NB; t++) {
        const int rb = (t + 1) & 1;      // buffer holding h_{t-1}
        const int wb = t & 1;            // buffer receiving h_t
        const int pp = t & 1;            // s_part parity

        { // wait for all 8 source-CTA pushes of h_{t-1}
            const unsigned a = smem_u32(&s_mbar[rb]);
            const unsigned ph = rb ? par1 : par0;
            unsigned done;
            asm volatile(
                "{\n\t.reg .pred p;\n\t"
                "mbarrier.try_wait.parity.acquire.cluster.shared::cta.b64 p, [%1], %2;\n\t"
                "selp.b32 %0, 1, 0, p;\n\t}"
                : "=r"(done) : "r"(a), "r"(ph) : "memory");
            if (!done) {
                asm volatile(
                    "{\n\t.reg .pred P1;\n\t"
                    "WLB_%=:\n\t"
                    "mbarrier.try_wait.parity.acquire.cluster.shared::cta.b64 P1, [%0], %1, 0x989680;\n\t"
                    "@P1 bra.uni WDB_%=;\n\t"
                    "bra.uni WLB_%=;\n\t"
                    "WDB_%=:\n\t}"
                    :: "r"(a), "r"(ph) : "memory");
            }
            if (rb) par1 ^= 1u; else par0 ^= 1u;
        }

        // ---- GEMV phase 1: 4 cols x 16 k per thread, packed f32x2 ----
        {
            const unsigned long long* hp =
                (const unsigned long long*)&s_hb[rb][k0];
            unsigned long long a0 = 0ULL, a1 = 0ULL, a2 = 0ULL, a3 = 0ULL;
            #pragma unroll
            for (int p = 0; p < 8; p++) {
                const unsigned long long h2 = hp[p];
                a0 = fma2u(wv[0][p], h2, a0);
                a1 = fma2u(wv[1][p], h2, a1);
                a2 = fma2u(wv[2][p], h2, a2);
                a3 = fma2u(wv[3][p], h2, a3);
            }
            float2 f0, f1, f2, f3;
            asm("mov.b64 {%0,%1}, %2;" : "=f"(f0.x), "=f"(f0.y) : "l"(a0));
            asm("mov.b64 {%0,%1}, %2;" : "=f"(f1.x), "=f"(f1.y) : "l"(a1));
            asm("mov.b64 {%0,%1}, %2;" : "=f"(f2.x), "=f"(f2.y) : "l"(a2));
            asm("mov.b64 {%0,%1}, %2;" : "=f"(f3.x), "=f"(f3.y) : "l"(a3));
            float4 p4;
            p4.x = f0.x + f0.y; p4.y = f1.x + f1.y;
            p4.z = f2.x + f2.y; p4.w = f3.x + f3.y;
            *(float4*)&s_part[pp][kw * 128 + g * 4] = p4;
        }
        __syncthreads();   // all 512: partials of step t visible

        // ---- phase2 + cell: warps 0-3 only; warps 4-15 go to next wait ----
        if (tid < 128) {
            float v[16];
            #pragma unroll
            for (int k2 = 0; k2 < 16; k2++)
                v[k2] = s_part[pp][k2 * 128 + tid];
            const float s =
                (((v[0] + v[1]) + (v[2] + v[3])) + ((v[4] + v[5]) + (v[6] + v[7]))) +
                (((v[8] + v[9]) + (v[10] + v[11])) + ((v[12] + v[13]) + (v[14] + v[15]))) + gt;
            s_z[tid] = s;
            if (t + 1 < NB) gt = g_G[(size_t)(t + 1) * 1024 + gcol2];

            asm volatile("bar.sync 1, 128;" ::: "memory");

            if (tid < 32) {
                const float zi = s_z[tid];
                const float zf = s_z[32 + tid];
                const float zc = s_z[64 + tid];
                const float zo = s_z[96 + tid];

                float s1 = zc, s2 = zc * zc;
                s1 += __shfl_xor_sync(0xffffffffu, s1, 1);  s2 += __shfl_xor_sync(0xffffffffu, s2, 1);
                s1 += __shfl_xor_sync(0xffffffffu, s1, 2);  s2 += __shfl_xor_sync(0xffffffffu, s2, 2);
                s1 += __shfl_xor_sync(0xffffffffu, s1, 4);  s2 += __shfl_xor_sync(0xffffffffu, s2, 4);
                float mean = s1 * 0.125f;
                float var  = s2 * 0.125f - mean * mean;
                const float ecc = zc * sigf(vl * zc) * rsqrtf(var + 1e-5f) * gl + bl;

                cst = sigf(zf) * cst + sigf(zi) * ecc;

                s1 = cst; s2 = cst * cst;
                s1 += __shfl_xor_sync(0xffffffffu, s1, 1);  s2 += __shfl_xor_sync(0xffffffffu, s2, 1);
                s1 += __shfl_xor_sync(0xffffffffu, s1, 2);  s2 += __shfl_xor_sync(0xffffffffu, s2, 2);
                s1 += __shfl_xor_sync(0xffffffffu, s1, 4);  s2 += __shfl_xor_sync(0xffffffffu, s2, 4);
                mean = s1 * 0.125f;
                var  = s2 * 0.125f - mean * mean;
                const float ecn = cst * sigf(vl * cst) * rsqrtf(var + 1e-5f) * gl + bl;

                const float h = sigf(zo) * ecn;
                s_hout[tid] = h;
                __syncwarp();

                // push h_t: lane d -> dest CTA d (8 x st.v4 + 1 release-arrive)
                if (tid < 8) {
                    const unsigned rh  = wb ? r_h1 : r_h0;
                    const unsigned rbb = wb ? r_b1 : r_b0;
                    #pragma unroll
                    for (int i = 0; i < 8; i++) {
                        const float4 hv4 = *(const float4*)&s_hout[i * 4];
                        asm volatile("st.shared::cluster.v4.f32 [%0], {%1,%2,%3,%4};"
                                     :: "r"(rh + i * 16), "f"(hv4.x), "f"(hv4.y), "f"(hv4.z), "f"(hv4.w)
                                     : "memory");
                    }
                    asm volatile("mbarrier.arrive.release.cluster.shared::cluster.b64 _, [%0];"
                                 :: "r"(rbb) : "memory");
                }
                g_H[(size_t)t * 256 + rank * 32 + tid] = h;
            }
        }
    }

    asm volatile("barrier.cluster.arrive.aligned;" ::: "memory");
    asm volatile("barrier.cluster.wait.aligned;"   ::: "memory");
}

// ===== Kernel C: dense_0 + evonorm -> bf16 hi/lo split (g_Ah/g_Al) ==========
__global__ __launch_bounds__(256) void kC(
    const float* __restrict__ Wd0, const float* __restrict__ vd,
    const float* __restrict__ gd,  const float* __restrict__ bd)
{
    __shared__ float sm1[16 * 256];
    __shared__ float sm2[16 * 256];
    const int tid = threadIdx.x;
    const int r0  = blockIdx.x * 16;

    const float4* src = (const float4*)(g_H + (size_t)r0 * 256);
    for (int i = tid; i < 1024; i += 256)
        ((float4*)sm1)[i] = src[i];
    __syncthreads();

    const int j = tid;
    float acc[16];
    #pragma unroll
    for (int r = 0; r < 16; r++) acc[r] = 0.f;
    for (int k4 = 0; k4 < 64; k4++) {
        const int k = k4 * 4;
        const float w0 = Wd0[(k+0)*256 + j];
        const float w1 = Wd0[(k+1)*256 + j];
        const float w2 = Wd0[(k+2)*256 + j];
        const float w3 = Wd0[(k+3)*256 + j];
        #pragma unroll
        for (int r = 0; r < 16; r++) {
            const float4 x = *(const float4*)&sm1[r * 256 + k];
            acc[r] += x.x*w0 + x.y*w1 + x.z*w2 + x.w*w3;
        }
    }
    #pragma unroll
    for (int r = 0; r < 16; r++) sm2[r * 256 + j] = acc[r];
    __syncthreads();

    const float v = vd[j], g = gd[j], bb = bd[j];
    for (int r = 0; r < 16; r++) {
        const float* row = &sm2[r * 256 + (j & ~7)];
        float s1 = 0.f, s2 = 0.f;
        #pragma unroll
        for (int e = 0; e < 8; e++) { float t = row[e]; s1 += t; s2 += t * t; }
        const float mean = s1 * 0.125f;
        const float var  = s2 * 0.125f - mean * mean;
        const float x = sm2[r * 256 + j];
        const float y = x * sigf(v * x) * rsqrtf(var + 1e-5f) * g + bb;
        const __nv_bfloat16 hi = __float2bfloat16(y);
        const __nv_bfloat16 lo = __float2bfloat16(y - __bfloat162float(hi));
        g_Ah[(size_t)(r0 + r) * 256 + j] = hi;
        g_Al[(size_t)(r0 + r) * 256 + j] = lo;
    }
}

// ===== Kernel D: HMMA bf16 3-split GEMM, CTA tile 128x128, serial K chunks ==
#define KD_SMEM 65536

__global__ void __launch_bounds__(256, 2)
kD(const float* __restrict__ bout, float* __restrict__ out)
{
    extern __shared__ __align__(1024) char smem[];
    const uint32_t ST = smem_u32(smem);
    const int tid = threadIdx.x;
    const int wid = tid >> 5, lane = tid & 31;
    const int warp_m = wid & 1;
    const int warp_n = wid >> 1;
    const int n0 = blockIdx.x * 128;
    const int m0 = blockIdx.y * 128;

    const uint32_t a_row = warp_m * 64 + (lane & 15);
    const uint32_t a_kb  = (uint32_t)(lane >> 4) * 16;
    const uint32_t b_row = warp_n * 32 + (lane & 7) + ((lane >> 4) & 1) * 8;
    const uint32_t b_kb  = (uint32_t)((lane >> 3) & 1) * 16;

    float acc[4][4][4];
    #pragma unroll
    for (int i = 0; i < 4; i++)
        #pragma unroll
        for (int j = 0; j < 4; j++)
            #pragma unroll
            for (int q = 0; q < 4; q++) acc[i][j][q] = 0.f;

    for (int kc = 0; kc < 4; kc++) {
        const int koff = kc * 64;
        #pragma unroll
        for (int sp = 0; sp < 2; sp++) {
            const __nv_bfloat16* gA = sp ? g_Al : g_Ah;
            const uint32_t db = ST + sp * 16384;
            #pragma unroll
            for (int i = 0; i < 4; i++) {
                const int g = tid + i * 256;
                const int row = g >> 3, j = g & 7;
                CP_ASYNC16(db + SWZ(row * 128 + j * 16),
                           gA + (size_t)(m0 + row) * 256 + koff + j * 8);
            }
        }
        #pragma unroll
        for (int sp = 0; sp < 2; sp++) {
            const __nv_bfloat16* gB = sp ? g_Bl : g_Bh;
            const uint32_t db = ST + 32768 + sp * 16384;
            #pragma unroll
            for (int i = 0; i < 4; i++) {
                const int g = tid + i * 256;
                const int row = g >> 3, j = g & 7;
                CP_ASYNC16(db + SWZ(row * 128 + j * 16),
                           gB + (size_t)(n0 + row) * 256 + koff + j * 8);
            }
        }
        CP_COMMIT();
        CP_WAIT_ALL();
        __syncthreads();

        #pragma unroll
        for (int split = 0; split < 3; split++) {
            const uint32_t Abase = ST + (split == 2 ? 16384u : 0u);
            const uint32_t Bbase = ST + 32768u + (split == 1 ? 16384u : 0u);
            #pragma unroll
            for (int ks = 0; ks < 4; ks++) {
                const uint32_t kk2 = (uint32_t)ks * 32;
                uint32_t af[4][4];
                #pragma unroll
                for (int mb = 0; mb < 4; mb++) {
                    const uint32_t addr = Abase + SWZ((a_row + mb * 16) * 128 + kk2 + a_kb);
                    LDSM_X4(af[mb][0], af[mb][1], af[mb][2], af[mb][3], addr);
                }
                uint32_t bfr[2][4];
                #pragma unroll
                for (int nb2 = 0; nb2 < 2; nb2++) {
                    const uint32_t addr = Bbase + SWZ((b_row + nb2 * 16) * 128 + kk2 + b_kb);
                    LDSM_X4(bfr[nb2][0], bfr[nb2][1], bfr[nb2][2], bfr[nb2][3], addr);
                }
                #pragma unroll
                for (int mb = 0; mb < 4; mb++) {
                    MMA16816(acc[mb][0], af[mb], bfr[0][0], bfr[0][1]);
                    MMA16816(acc[mb][1], af[mb], bfr[0][2], bfr[0][3]);
                    MMA16816(acc[mb][2], af[mb], bfr[1][0], bfr[1][1]);
                    MMA16816(acc[mb][3], af[mb], bfr[1][2], bfr[1][3]);
                }
            }
        }
        __syncthreads();
    }

    #pragma unroll
    for (int nb = 0; nb < 4; nb++) {
        const int col = n0 + warp_n * 32 + nb * 8 + (lane & 3) * 2;
        const float2 bb = *(const float2*)&bout[col];
        #pragma unroll
        for (int mb = 0; mb < 4; mb++) {
            const int row = m0 + warp_m * 64 + mb * 16 + (lane >> 2);
            float2 v0, v1;
            v0.x = acc[mb][nb][0] + bb.x;  v0.y = acc[mb][nb][1] + bb.y;
            v1.x = acc[mb][nb][2] + bb.x;  v1.y = acc[mb][nb][3] + bb.y;
            *(float2*)&out[(size_t)row * NPAR + col]       = v0;
            *(float2*)&out[(size_t)(row + 8) * NPAR + col] = v1;
        }
    }
}

// ============================================================================
extern "C" void kernel_launch(void* const* d_in, const int* in_sizes, int n_in,
                              void* d_out, int out_size)
{
    const float* actions = (const float*)d_in[0];
    const float* obs     = (const float*)d_in[1];
    const float* Wci     = (const float*)d_in[2];
    const float* vci     = (const float*)d_in[3];
    const float* gci     = (const float*)d_in[4];
    const float* bci     = (const float*)d_in[5];
    const float* Wcl     = (const float*)d_in[6];
    const float* bcl     = (const float*)d_in[7];
    const float* Win     = (const float*)d_in[8];
    const float* vin     = (const float*)d_in[9];
    const float* gin     = (const float*)d_in[10];
    const float* bin     = (const float*)d_in[11];
    const float* Wk      = (const float*)d_in[12];
    const float* Wr      = (const float*)d_in[13];
    const float* vl      = (const float*)d_in[14];
    const float* gl      = (const float*)d_in[15];
    const float* bl      = (const float*)d_in[16];
    const float* Wd0     = (const float*)d_in[17];
    const float* vd0     = (const float*)d_in[18];
    const float* gd0     = (const float*)d_in[19];
    const float* bd0     = (const float*)d_in[20];
    const float* Wout    = (const float*)d_in[21];
    const float* bout    = (const float*)d_in[22];
    float* out = (float*)d_out;

    kWA<<<KWA_NW + 128, 256>>>(Wout, actions, obs, Wci, vci, gci, bci, Wcl, bcl,
                               Win, vin, gin, bin, Wk);
    kB<<<8, 512>>>(Wr, vl, gl, bl);
    kC<<<128, 256>>>(Wd0, vd0, gd0, bd0);

    cudaFuncSetAttribute(kD, cudaFuncAttributeMaxDynamicSharedMemorySize, KD_SMEM);
    dim3 gD(NPAR / 128, NB / 128);
    kD<<<gD, 256, KD_SMEM>>>(bout, out);
}

// round 13
// speedup vs baseline: 2.2159x; 1.0729x over previous
#include <cuda_runtime.h>
#include <cuda_bf16.h>
#include <cstdint>

#define NB     2048
#define NPAR   66048

// Scratch (device globals; allocation is forbidden)
__device__ __align__(16) float g_G [NB * 1024];            // X@Wk precomputed gates
__device__ __align__(16) float g_H [NB * 256];             // LSTM hidden outputs
__device__ __align__(16) __nv_bfloat16 g_Ah[NB * 256];     // X3 hi (bf16 split)
__device__ __align__(16) __nv_bfloat16 g_Al[NB * 256];     // X3 lo
__device__ __align__(16) __nv_bfloat16 g_Bh[(size_t)NPAR * 256]; // W^T hi, K-major [n][k]
__device__ __align__(16) __nv_bfloat16 g_Bl[(size_t)NPAR * 256]; // W^T lo

__device__ __forceinline__ float sigf(float x) {
    return __frcp_rn(1.0f + __expf(-x));
}

__device__ __forceinline__ float2 fma2(float2 a, float2 b, float2 c) {
    unsigned long long A, Bv, C, D;
    asm("mov.b64 %0, {%1,%2};" : "=l"(A)  : "f"(a.x), "f"(a.y));
    asm("mov.b64 %0, {%1,%2};" : "=l"(Bv) : "f"(b.x), "f"(b.y));
    asm("mov.b64 %0, {%1,%2};" : "=l"(C)  : "f"(c.x), "f"(c.y));
    asm("fma.rn.f32x2 %0, %1, %2, %3;" : "=l"(D) : "l"(A), "l"(Bv), "l"(C));
    float2 r;
    asm("mov.b64 {%0,%1}, %2;" : "=f"(r.x), "=f"(r.y) : "l"(D));
    return r;
}

// mov-free packed dual FMA: all operands already u64 register pairs
__device__ __forceinline__ unsigned long long fma2u(
    unsigned long long a, unsigned long long b, unsigned long long c) {
    unsigned long long d;
    asm("fma.rn.f32x2 %0, %1, %2, %3;" : "=l"(d) : "l"(a), "l"(b), "l"(c));
    return d;
}

__device__ __forceinline__ unsigned smem_u32(const void* p) {
    unsigned a;
    asm("{ .reg .u64 t; cvta.to.shared.u64 t, %1; cvt.u32.u64 %0, t; }" : "=r"(a) : "l"(p));
    return a;
}

// ---- async-copy / HMMA helpers ---------------------------------------------
#define SWZ(x) ((x) ^ (((x) >> 3) & 0x70))

#define CP_ASYNC16(dst, src) \
    asm volatile("cp.async.cg.shared.global [%0], [%1], 16;" :: "r"(dst), "l"(src) : "memory")
#define CP_COMMIT()  asm volatile("cp.async.commit_group;" ::: "memory")
#define CP_WAIT1()   asm volatile("cp.async.wait_group 1;" ::: "memory")
#define CP_WAIT0()   asm volatile("cp.async.wait_group 0;" ::: "memory")

#define LDSM_X4(r0, r1, r2, r3, addr) \
    asm volatile("ldmatrix.sync.aligned.m8n8.x4.shared.b16 {%0,%1,%2,%3}, [%4];" \
                 : "=r"(r0), "=r"(r1), "=r"(r2), "=r"(r3) : "r"(addr))

#define MMA16816(d, a, b0, b1) \
    asm volatile("mma.sync.aligned.m16n8k16.row.col.f32.bf16.bf16.f32 " \
                 "{%0,%1,%2,%3}, {%4,%5,%6,%7}, {%8,%9}, {%0,%1,%2,%3};" \
                 : "+f"((d)[0]), "+f"((d)[1]), "+f"((d)[2]), "+f"((d)[3]) \
                 : "r"((a)[0]), "r"((a)[1]), "r"((a)[2]), "r"((a)[3]), \
                   "r"(b0), "r"(b1))

// ===== Kernel WA: fused kW (blocks 0..2063) + kA (blocks 2064..2191) ========
#define KWA_NW (NPAR / 32)   // 2064

__global__ __launch_bounds__(256) void kWA(
    const float* __restrict__ Wout,
    const float* __restrict__ actions, const float* __restrict__ obs,
    const float* __restrict__ Wci, const float* __restrict__ vci,
    const float* __restrict__ gci, const float* __restrict__ bci,
    const float* __restrict__ Wcl, const float* __restrict__ bcl,
    const float* __restrict__ Win, const float* __restrict__ vin,
    const float* __restrict__ gin, const float* __restrict__ bin,
    const float* __restrict__ Wk)
{
    __shared__ float sm1[16 * 256];
    __shared__ float sm2[16 * 256];
    const int tid = threadIdx.x;

    if (blockIdx.x < KWA_NW) {
        // ------- kW part: transpose+split a 256k x 32n block -------
        float* sm = sm1;
        const int n0 = blockIdx.x * 32;
        #pragma unroll 4
        for (int it = 0; it < 32; it++) {
            const int idx = it * 256 + tid;
            const int k = idx >> 5, j = idx & 31;
            sm[j * 256 + (k ^ j)] = Wout[(size_t)k * NPAR + n0 + j];
        }
        __syncthreads();
        const int j  = tid & 31;
        const int kq = tid >> 5;
        __nv_bfloat16* ph = g_Bh + (size_t)(n0 + j) * 256 + kq * 32;
        __nv_bfloat16* pl = g_Bl + (size_t)(n0 + j) * 256 + kq * 32;
        #pragma unroll
        for (int kk = 0; kk < 32; kk++) {
            const float w = sm[j * 256 + ((kq * 32 + kk) ^ j)];
            const __nv_bfloat16 hi = __float2bfloat16(w);
            const __nv_bfloat16 lo = __float2bfloat16(w - __bfloat162float(hi));
            ph[kk] = hi;
            pl[kk] = lo;
        }
        return;
    }

    // ------- kA part -------
    const int r0 = (blockIdx.x - KWA_NW) * 16;

    { // t1 = actions @ Wci -> sm1[16][64]
        const int j = tid & 63, rr = tid >> 6;
        #pragma unroll
        for (int q = 0; q < 4; q++) {
            const int r = rr + q * 4;
            float acc = 0.f;
            #pragma unroll
            for (int k = 0; k < 16; k++)
                acc += actions[(r0 + r) * 16 + k] * Wci[k * 64 + j];
            sm1[r * 64 + j] = acc;
        }
    }
    __syncthreads();
    { // evonorm(groups=8) -> sm2[16][64]
        const int j = tid & 63, rr = tid >> 6;
        const float v = vci[j], g = gci[j], bb = bci[j];
        #pragma unroll
        for (int q = 0; q < 4; q++) {
            const int r = rr + q * 4;
            const float* row = &sm1[r * 64 + (j & ~7)];
            float s1 = 0.f, s2 = 0.f;
            #pragma unroll
            for (int e = 0; e < 8; e++) { float t = row[e]; s1 += t; s2 += t * t; }
            const float mean = s1 * 0.125f;
            const float var  = s2 * 0.125f - mean * mean;
            const float x = sm1[r * 64 + j];
            sm2[r * 64 + j] = x * sigf(v * x) * rsqrtf(var + 1e-5f) * g + bb;
        }
    }
    __syncthreads();
    { // x = a1 @ Wcl + bcl + obs -> sm1[16][64]
        const int j = tid & 63, rr = tid >> 6;
        const float bj = bcl[j];
        float acc[4];
        #pragma unroll
        for (int q = 0; q < 4; q++)
            acc[q] = bj + obs[(r0 + rr + q * 4) * 64 + j];
        for (int k = 0; k < 64; k++) {
            const float w = Wcl[k * 64 + j];
            #pragma unroll
            for (int q = 0; q < 4; q++)
                acc[q] += sm2[(rr + q * 4) * 64 + k] * w;
        }
        #pragma unroll
        for (int q = 0; q < 4; q++)
            sm1[(rr + q * 4) * 64 + j] = acc[q];
    }
    __syncthreads();
    { // t2 = x @ Win -> sm2[16][256]
        const int j = tid;
        float acc[16];
        #pragma unroll
        for (int r = 0; r < 16; r++) acc[r] = 0.f;
        for (int k = 0; k < 64; k++) {
            const float w = Win[k * 256 + j];
            #pragma unroll
            for (int r = 0; r < 16; r++) acc[r] += sm1[r * 64 + k] * w;
        }
        #pragma unroll
        for (int r = 0; r < 16; r++) sm2[r * 256 + j] = acc[r];
    }
    __syncthreads();
    { // evonorm(group size 8) -> sm1[16][256]
        const int j = tid;
        const float v = vin[j], g = gin[j], bb = bin[j];
        for (int r = 0; r < 16; r++) {
            const float* row = &sm2[r * 256 + (j & ~7)];
            float s1 = 0.f, s2 = 0.f;
            #pragma unroll
            for (int e = 0; e < 8; e++) { float t = row[e]; s1 += t; s2 += t * t; }
            const float mean = s1 * 0.125f;
            const float var  = s2 * 0.125f - mean * mean;
            const float x = sm2[r * 256 + j];
            sm1[r * 256 + j] = x * sigf(v * x) * rsqrtf(var + 1e-5f) * g + bb;
        }
    }
    __syncthreads();
    { // G = x_in @ Wk  (thread: 4 cols x 16 rows)
        const int c0 = tid * 4;
        float2 acc[16][2];
        #pragma unroll
        for (int r = 0; r < 16; r++) { acc[r][0] = make_float2(0.f,0.f); acc[r][1] = make_float2(0.f,0.f); }
        for (int k = 0; k < 256; k++) {
            const float4 w4 = *(const float4*)&Wk[k * 1024 + c0];
            const float2 wa = make_float2(w4.x, w4.y);
            const float2 wb = make_float2(w4.z, w4.w);
            #pragma unroll
            for (int r = 0; r < 16; r++) {
                const float x = sm1[r * 256 + k];
                const float2 xx = make_float2(x, x);
                acc[r][0] = fma2(wa, xx, acc[r][0]);
                acc[r][1] = fma2(wb, xx, acc[r][1]);
            }
        }
        #pragma unroll
        for (int r = 0; r < 16; r++) {
            float4 o;
            o.x = acc[r][0].x; o.y = acc[r][0].y; o.z = acc[r][1].x; o.w = acc[r][1].y;
            *(float4*)&g_G[(size_t)(r0 + r) * 1024 + c0] = o;
        }
    }
}

// ===== Kernel B: sequential LSTM, 8-CTA cluster =============================
__global__ void __launch_bounds__(512, 1) __cluster_dims__(8, 1, 1)
kB(const float* __restrict__ Wr, const float* __restrict__ vl_,
   const float* __restrict__ gl_, const float* __restrict__ bl_)
{
    __shared__ __align__(16) float s_hb[2][256];        // h buffers (remote-written)
    __shared__ __align__(16) float s_part[2][16 * 128]; // GEMV partials, 2x8KB
    __shared__ __align__(16) float s_z[128];
    __shared__ __align__(16) float s_hout[32];
    __shared__ __align__(8)  unsigned long long s_mbar[2];

    const int tid = threadIdx.x;
    unsigned rank;
    asm("mov.u32 %0, %%cluster_ctarank;" : "=r"(rank));

    const int g   = tid & 31;        // col-group: cols [g*4, g*4+4)
    const int kw  = tid >> 5;        // k-window:  k    [kw*16, kw*16+16)
    const int gg  = g >> 3;          // gate 0..3
    const int cc0 = (g & 7) * 4;     // channel base within this CTA's 32
    const int gcol0 = gg * 256 + (int)rank * 32 + cc0;   // global col of c=0
    const int k0    = kw * 16;

    // register-resident weights, packed as (k, k+1) pairs per column: u64
    unsigned long long wv[4][8];
    #pragma unroll
    for (int p = 0; p < 8; p++) {
        #pragma unroll
        for (int c = 0; c < 4; c++) {
            const float w0 = Wr[(size_t)(k0 + 2*p)     * 1024 + gcol0 + c];
            const float w1 = Wr[(size_t)(k0 + 2*p + 1) * 1024 + gcol0 + c];
            asm("mov.b64 %0, {%1,%2};" : "=l"(wv[c][p]) : "f"(w0), "f"(w1));
        }
    }

    // cell params for warp 0 (channel ch = rank*32 + lane)
    float vl = 0.f, gl = 0.f, bl = 0.f, cst = 0.f;
    if (tid < 32) {
        const int ch = (int)rank * 32 + tid;
        vl = vl_[ch]; gl = gl_[ch]; bl = bl_[ch];
    }

    // push addresses for warp0 lanes 0-7 (lane = dest CTA)
    unsigned r_h0 = 0, r_h1 = 0, r_b0 = 0, r_b1 = 0;
    if (tid < 8) {
        const unsigned d = (unsigned)tid;
        unsigned lh0 = smem_u32(&s_hb[0][rank * 32]);
        unsigned lh1 = smem_u32(&s_hb[1][rank * 32]);
        unsigned lb0 = smem_u32(&s_mbar[0]);
        unsigned lb1 = smem_u32(&s_mbar[1]);
        asm("mapa.shared::cluster.u32 %0, %1, %2;" : "=r"(r_h0) : "r"(lh0), "r"(d));
        asm("mapa.shared::cluster.u32 %0, %1, %2;" : "=r"(r_h1) : "r"(lh1), "r"(d));
        asm("mapa.shared::cluster.u32 %0, %1, %2;" : "=r"(r_b0) : "r"(lb0), "r"(d));
        asm("mapa.shared::cluster.u32 %0, %1, %2;" : "=r"(r_b1) : "r"(lb1), "r"(d));
    }

    if (tid == 0) {
        asm volatile("mbarrier.init.shared.b64 [%0], %1;" :: "r"(smem_u32(&s_mbar[0])), "r"(8u) : "memory");
        asm volatile("mbarrier.init.shared.b64 [%0], %1;" :: "r"(smem_u32(&s_mbar[1])), "r"(8u) : "memory");
    }
    if (tid < 256) { s_hb[0][tid] = 0.f; s_hb[1][tid] = 0.f; }
    __syncthreads();
    asm volatile("barrier.cluster.arrive.aligned;" ::: "memory");
    asm volatile("barrier.cluster.wait.aligned;"   ::: "memory");

    // initial push: zeros (h_{-1}) into buffer 1
    if (tid < 8) {
        #pragma unroll
        for (int i = 0; i < 8; i++)
            asm volatile("st.shared::cluster.v4.f32 [%0], {%1,%1,%1,%1};"
                         :: "r"(r_h1 + i * 16), "f"(0.f) : "memory");
        asm volatile("mbarrier.arrive.release.cluster.shared::cluster.b64 _, [%0];"
                     :: "r"(r_b1) : "memory");
    }

    unsigned par0 = 0u, par1 = 0u;

    // prefetch gate term for step 0 (phase-2 threads)
    const int gcol2 = (tid >> 5) * 256 + (int)rank * 32 + (tid & 31);
    float gt = (tid < 128) ? g_G[gcol2] : 0.f;

    for (int t = 0; t < NB; t++) {
        const int rb = (t + 1) & 1;      // buffer holding h_{t-1}
        const int wb = t & 1;            // buffer receiving h_t
        const int pp = t & 1;            // s_part parity

        { // wait for all 8 source-CTA pushes of h_{t-1}
            const unsigned a = smem_u32(&s_mbar[rb]);
            const unsigned ph = rb ? par1 : par0;
            unsigned done;
            asm volatile(
                "{\n\t.reg .pred p;\n\t"
                "mbarrier.try_wait.parity.acquire.cluster.shared::cta.b64 p, [%1], %2;\n\t"
                "selp.b32 %0, 1, 0, p;\n\t}"
                : "=r"(done) : "r"(a), "r"(ph) : "memory");
            if (!done) {
                asm volatile(
                    "{\n\t.reg .pred P1;\n\t"
                    "WLB_%=:\n\t"
                    "mbarrier.try_wait.parity.acquire.cluster.shared::cta.b64 P1, [%0], %1, 0x989680;\n\t"
                    "@P1 bra.uni WDB_%=;\n\t"
                    "bra.uni WLB_%=;\n\t"
                    "WDB_%=:\n\t}"
                    :: "r"(a), "r"(ph) : "memory");
            }
            if (rb) par1 ^= 1u; else par0 ^= 1u;
        }

        // ---- GEMV phase 1: 4 cols x 16 k per thread, packed f32x2 ----
        {
            const unsigned long long* hp =
                (const unsigned long long*)&s_hb[rb][k0];
            unsigned long long a0 = 0ULL, a1 = 0ULL, a2 = 0ULL, a3 = 0ULL;
            #pragma unroll
            for (int p = 0; p < 8; p++) {
                const unsigned long long h2 = hp[p];
                a0 = fma2u(wv[0][p], h2, a0);
                a1 = fma2u(wv[1][p], h2, a1);
                a2 = fma2u(wv[2][p], h2, a2);
                a3 = fma2u(wv[3][p], h2, a3);
            }
            float2 f0, f1, f2, f3;
            asm("mov.b64 {%0,%1}, %2;" : "=f"(f0.x), "=f"(f0.y) : "l"(a0));
            asm("mov.b64 {%0,%1}, %2;" : "=f"(f1.x), "=f"(f1.y) : "l"(a1));
            asm("mov.b64 {%0,%1}, %2;" : "=f"(f2.x), "=f"(f2.y) : "l"(a2));
            asm("mov.b64 {%0,%1}, %2;" : "=f"(f3.x), "=f"(f3.y) : "l"(a3));
            float4 p4;
            p4.x = f0.x + f0.y; p4.y = f1.x + f1.y;
            p4.z = f2.x + f2.y; p4.w = f3.x + f3.y;
            *(float4*)&s_part[pp][kw * 128 + g * 4] = p4;
        }
        __syncthreads();   // all 512: partials of step t visible

        // ---- phase2 + cell: warps 0-3 only; warps 4-15 go to next wait ----
        if (tid < 128) {
            float v[16];
            #pragma unroll
            for (int k2 = 0; k2 < 16; k2++)
                v[k2] = s_part[pp][k2 * 128 + tid];
            const float s =
                (((v[0] + v[1]) + (v[2] + v[3])) + ((v[4] + v[5]) + (v[6] + v[7]))) +
                (((v[8] + v[9]) + (v[10] + v[11])) + ((v[12] + v[13]) + (v[14] + v[15]))) + gt;
            s_z[tid] = s;
            if (t + 1 < NB) gt = g_G[(size_t)(t + 1) * 1024 + gcol2];

            asm volatile("bar.sync 1, 128;" ::: "memory");

            if (tid < 32) {
                const float zi = s_z[tid];
                const float zf = s_z[32 + tid];
                const float zc = s_z[64 + tid];
                const float zo = s_z[96 + tid];

                float s1 = zc, s2 = zc * zc;
                s1 += __shfl_xor_sync(0xffffffffu, s1, 1);  s2 += __shfl_xor_sync(0xffffffffu, s2, 1);
                s1 += __shfl_xor_sync(0xffffffffu, s1, 2);  s2 += __shfl_xor_sync(0xffffffffu, s2, 2);
                s1 += __shfl_xor_sync(0xffffffffu, s1, 4);  s2 += __shfl_xor_sync(0xffffffffu, s2, 4);
                float mean = s1 * 0.125f;
                float var  = s2 * 0.125f - mean * mean;
                const float ecc = zc * sigf(vl * zc) * rsqrtf(var + 1e-5f) * gl + bl;

                cst = sigf(zf) * cst + sigf(zi) * ecc;

                s1 = cst; s2 = cst * cst;
                s1 += __shfl_xor_sync(0xffffffffu, s1, 1);  s2 += __shfl_xor_sync(0xffffffffu, s2, 1);
                s1 += __shfl_xor_sync(0xffffffffu, s1, 2);  s2 += __shfl_xor_sync(0xffffffffu, s2, 2);
                s1 += __shfl_xor_sync(0xffffffffu, s1, 4);  s2 += __shfl_xor_sync(0xffffffffu, s2, 4);
                mean = s1 * 0.125f;
                var  = s2 * 0.125f - mean * mean;
                const float ecn = cst * sigf(vl * cst) * rsqrtf(var + 1e-5f) * gl + bl;

                const float h = sigf(zo) * ecn;
                s_hout[tid] = h;
                __syncwarp();

                // push h_t: lane d -> dest CTA d (8 x st.v4 + 1 release-arrive)
                if (tid < 8) {
                    const unsigned rh  = wb ? r_h1 : r_h0;
                    const unsigned rbb = wb ? r_b1 : r_b0;
                    #pragma unroll
                    for (int i = 0; i < 8; i++) {
                        const float4 hv4 = *(const float4*)&s_hout[i * 4];
                        asm volatile("st.shared::cluster.v4.f32 [%0], {%1,%2,%3,%4};"
                                     :: "r"(rh + i * 16), "f"(hv4.x), "f"(hv4.y), "f"(hv4.z), "f"(hv4.w)
                                     : "memory");
                    }
                    asm volatile("mbarrier.arrive.release.cluster.shared::cluster.b64 _, [%0];"
                                 :: "r"(rbb) : "memory");
                }
                g_H[(size_t)t * 256 + rank * 32 + tid] = h;
            }
        }
    }

    asm volatile("barrier.cluster.arrive.aligned;" ::: "memory");
    asm volatile("barrier.cluster.wait.aligned;"   ::: "memory");
}

// ===== Kernel C: dense_0 + evonorm -> bf16 hi/lo split (g_Ah/g_Al) ==========
__global__ __launch_bounds__(256) void kC(
    const float* __restrict__ Wd0, const float* __restrict__ vd,
    const float* __restrict__ gd,  const float* __restrict__ bd)
{
    __shared__ float sm1[16 * 256];
    __shared__ float sm2[16 * 256];
    const int tid = threadIdx.x;
    const int r0  = blockIdx.x * 16;

    const float4* src = (const float4*)(g_H + (size_t)r0 * 256);
    for (int i = tid; i < 1024; i += 256)
        ((float4*)sm1)[i] = src[i];
    __syncthreads();

    const int j = tid;
    float acc[16];
    #pragma unroll
    for (int r = 0; r < 16; r++) acc[r] = 0.f;
    for (int k4 = 0; k4 < 64; k4++) {
        const int k = k4 * 4;
        const float w0 = Wd0[(k+0)*256 + j];
        const float w1 = Wd0[(k+1)*256 + j];
        const float w2 = Wd0[(k+2)*256 + j];
        const float w3 = Wd0[(k+3)*256 + j];
        #pragma unroll
        for (int r = 0; r < 16; r++) {
            const float4 x = *(const float4*)&sm1[r * 256 + k];
            acc[r] += x.x*w0 + x.y*w1 + x.z*w2 + x.w*w3;
        }
    }
    #pragma unroll
    for (int r = 0; r < 16; r++) sm2[r * 256 + j] = acc[r];
    __syncthreads();

    const float v = vd[j], g = gd[j], bb = bd[j];
    for (int r = 0; r < 16; r++) {
        const float* row = &sm2[r * 256 + (j & ~7)];
        float s1 = 0.f, s2 = 0.f;
        #pragma unroll
        for (int e = 0; e < 8; e++) { float t = row[e]; s1 += t; s2 += t * t; }
        const float mean = s1 * 0.125f;
        const float var  = s2 * 0.125f - mean * mean;
        const float x = sm2[r * 256 + j];
        const float y = x * sigf(v * x) * rsqrtf(var + 1e-5f) * g + bb;
        const __nv_bfloat16 hi = __float2bfloat16(y);
        const __nv_bfloat16 lo = __float2bfloat16(y - __bfloat162float(hi));
        g_Ah[(size_t)(r0 + r) * 256 + j] = hi;
        g_Al[(size_t)(r0 + r) * 256 + j] = lo;
    }
}

// ===== Kernel D: HMMA bf16 3-split GEMM, 128x128 tile, 2-stage pipeline =====
// Stage (64 KB): Ah@0, Al@16K, Bh@32K, Bl@48K. Two stages = 128 KB, 1 CTA/SM.
// Grid: x = 16 row tiles (fastest) so concurrent CTAs share B col-slices in L2.
#define KD_STAGE 65536
#define KD_SMEM  (2 * KD_STAGE)

__device__ __forceinline__ void kd_load(uint32_t stage, int m0, int n0,
                                        int koff, int tid)
{
    #pragma unroll
    for (int sp = 0; sp < 2; sp++) {
        const __nv_bfloat16* gA = sp ? g_Al : g_Ah;
        const uint32_t db = stage + sp * 16384u;
        #pragma unroll
        for (int i = 0; i < 4; i++) {
            const int g2 = tid + i * 256;
            const int row = g2 >> 3, j = g2 & 7;
            CP_ASYNC16(db + SWZ(row * 128 + j * 16),
                       gA + (size_t)(m0 + row) * 256 + koff + j * 8);
        }
    }
    #pragma unroll
    for (int sp = 0; sp < 2; sp++) {
        const __nv_bfloat16* gB = sp ? g_Bl : g_Bh;
        const uint32_t db = stage + 32768u + sp * 16384u;
        #pragma unroll
        for (int i = 0; i < 4; i++) {
            const int g2 = tid + i * 256;
            const int row = g2 >> 3, j = g2 & 7;
            CP_ASYNC16(db + SWZ(row * 128 + j * 16),
                       gB + (size_t)(n0 + row) * 256 + koff + j * 8);
        }
    }
    CP_COMMIT();
}

__device__ __forceinline__ void kd_compute(uint32_t stage,
                                           uint32_t a_row, uint32_t a_kb,
                                           uint32_t b_row, uint32_t b_kb,
                                           float acc[4][4][4])
{
    #pragma unroll
    for (int split = 0; split < 3; split++) {
        const uint32_t Abase = stage + (split == 2 ? 16384u : 0u);
        const uint32_t Bbase = stage + 32768u + (split == 1 ? 16384u : 0u);
        #pragma unroll
        for (int ks = 0; ks < 4; ks++) {
            const uint32_t kk2 = (uint32_t)ks * 32;
            uint32_t af[4][4];
            #pragma unroll
            for (int mb = 0; mb < 4; mb++) {
                const uint32_t addr = Abase + SWZ((a_row + mb * 16) * 128 + kk2 + a_kb);
                LDSM_X4(af[mb][0], af[mb][1], af[mb][2], af[mb][3], addr);
            }
            uint32_t bfr[2][4];
            #pragma unroll
            for (int nb2 = 0; nb2 < 2; nb2++) {
                const uint32_t addr = Bbase + SWZ((b_row + nb2 * 16) * 128 + kk2 + b_kb);
                LDSM_X4(bfr[nb2][0], bfr[nb2][1], bfr[nb2][2], bfr[nb2][3], addr);
            }
            #pragma unroll
            for (int mb = 0; mb < 4; mb++) {
                MMA16816(acc[mb][0], af[mb], bfr[0][0], bfr[0][1]);
                MMA16816(acc[mb][1], af[mb], bfr[0][2], bfr[0][3]);
                MMA16816(acc[mb][2], af[mb], bfr[1][0], bfr[1][1]);
                MMA16816(acc[mb][3], af[mb], bfr[1][2], bfr[1][3]);
            }
        }
    }
}

__global__ void __launch_bounds__(256)
kD(const float* __restrict__ bout, float* __restrict__ out)
{
    extern __shared__ __align__(1024) char smem[];
    const uint32_t ST = smem_u32(smem);
    const int tid = threadIdx.x;
    const int wid = tid >> 5, lane = tid & 31;
    const int warp_m = wid & 1;
    const int warp_n = wid >> 1;
    const int m0 = blockIdx.x * 128;   // 16 row tiles (fastest-varying)
    const int n0 = blockIdx.y * 128;   // 516 col tiles

    const uint32_t a_row = warp_m * 64 + (lane & 15);
    const uint32_t a_kb  = (uint32_t)(lane >> 4) * 16;
    const uint32_t b_row = warp_n * 32 + (lane & 7) + ((lane >> 4) & 1) * 8;
    const uint32_t b_kb  = (uint32_t)((lane >> 3) & 1) * 16;

    float acc[4][4][4];
    #pragma unroll
    for (int i = 0; i < 4; i++)
        #pragma unroll
        for (int j = 0; j < 4; j++)
            #pragma unroll
            for (int q = 0; q < 4; q++) acc[i][j][q] = 0.f;

    const uint32_t S0 = ST;
    const uint32_t S1 = ST + KD_STAGE;

    // Pipeline: G0=chunk0->S0, G1=chunk1->S1, G2=chunk2->S0, G3=chunk3->S1.
    // wait_group 1 before consuming chunk k guarantees its group is complete.
    kd_load(S0, m0, n0, 0,   tid);
    kd_load(S1, m0, n0, 64,  tid);
    CP_WAIT1();  __syncthreads();              // G0 done
    kd_compute(S0, a_row, a_kb, b_row, b_kb, acc);
    __syncthreads();                           // S0 free
    kd_load(S0, m0, n0, 128, tid);             // G2
    CP_WAIT1();  __syncthreads();              // G1 done (G2 may be pending)
    kd_compute(S1, a_row, a_kb, b_row, b_kb, acc);
    __syncthreads();                           // S1 free
    kd_load(S1, m0, n0, 192, tid);             // G3
    CP_WAIT0();  __syncthreads();              // G2+G3 done
    kd_compute(S0, a_row, a_kb, b_row, b_kb, acc);
    kd_compute(S1, a_row, a_kb, b_row, b_kb, acc);

    // ---- epilogue: direct float2 stores + bias ----
    #pragma unroll
    for (int nb = 0; nb < 4; nb++) {
        const int col = n0 + warp_n * 32 + nb * 8 + (lane & 3) * 2;
        const float2 bb = *(const float2*)&bout[col];
        #pragma unroll
        for (int mb = 0; mb < 4; mb++) {
            const int row = m0 + warp_m * 64 + mb * 16 + (lane >> 2);
            float2 v0, v1;
            v0.x = acc[mb][nb][0] + bb.x;  v0.y = acc[mb][nb][1] + bb.y;
            v1.x = acc[mb][nb][2] + bb.x;  v1.y = acc[mb][nb][3] + bb.y;
            *(float2*)&out[(size_t)row * NPAR + col]       = v0;
            *(float2*)&out[(size_t)(row + 8) * NPAR + col] = v1;
        }
    }
}

// ============================================================================
extern "C" void kernel_launch(void* const* d_in, const int* in_sizes, int n_in,
                              void* d_out, int out_size)
{
    const float* actions = (const float*)d_in[0];
    const float* obs     = (const float*)d_in[1];
    const float* Wci     = (const float*)d_in[2];
    const float* vci     = (const float*)d_in[3];
    const float* gci     = (const float*)d_in[4];
    const float* bci     = (const float*)d_in[5];
    const float* Wcl     = (const float*)d_in[6];
    const float* bcl     = (const float*)d_in[7];
    const float* Win     = (const float*)d_in[8];
    const float* vin     = (const float*)d_in[9];
    const float* gin     = (const float*)d_in[10];
    const float* bin     = (const float*)d_in[11];
    const float* Wk      = (const float*)d_in[12];
    const float* Wr      = (const float*)d_in[13];
    const float* vl      = (const float*)d_in[14];
    const float* gl      = (const float*)d_in[15];
    const float* bl      = (const float*)d_in[16];
    const float* Wd0     = (const float*)d_in[17];
    const float* vd0     = (const float*)d_in[18];
    const float* gd0     = (const float*)d_in[19];
    const float* bd0     = (const float*)d_in[20];
    const float* Wout    = (const float*)d_in[21];
    const float* bout    = (const float*)d_in[22];
    float* out = (float*)d_out;

    kWA<<<KWA_NW + 128, 256>>>(Wout, actions, obs, Wci, vci, gci, bci, Wcl, bcl,
                               Win, vin, gin, bin, Wk);
    kB<<<8, 512>>>(Wr, vl, gl, bl);
    kC<<<128, 256>>>(Wd0, vd0, gd0, bd0);

    cudaFuncSetAttribute(kD, cudaFuncAttributeMaxDynamicSharedMemorySize, KD_SMEM);
    dim3 gD(NB / 128, NPAR / 128);   // x = row tiles (16), y = col tiles (516)
    kD<<<gD, 256, KD_SMEM>>>(bout, out);
}

// round 14
// speedup vs baseline: 2.2514x; 1.0160x over previous
#include <cuda_runtime.h>
#include <cuda_bf16.h>
#include <cstdint>

#define NB     2048
#define NPAR   66048

// Scratch (device globals; allocation is forbidden)
__device__ __align__(16) float g_G [NB * 1024];            // X@Wk precomputed gates
__device__ __align__(16) float g_H [NB * 256];             // LSTM hidden outputs
__device__ __align__(16) __nv_bfloat16 g_Ah[NB * 256];     // X3 hi (bf16 split)
__device__ __align__(16) __nv_bfloat16 g_Al[NB * 256];     // X3 lo
__device__ __align__(16) __nv_bfloat16 g_Bh[(size_t)NPAR * 256]; // W^T hi, K-major [n][k]
__device__ __align__(16) __nv_bfloat16 g_Bl[(size_t)NPAR * 256]; // W^T lo

__device__ __forceinline__ float sigf(float x) {
    return __frcp_rn(1.0f + __expf(-x));
}

__device__ __forceinline__ float2 fma2(float2 a, float2 b, float2 c) {
    unsigned long long A, Bv, C, D;
    asm("mov.b64 %0, {%1,%2};" : "=l"(A)  : "f"(a.x), "f"(a.y));
    asm("mov.b64 %0, {%1,%2};" : "=l"(Bv) : "f"(b.x), "f"(b.y));
    asm("mov.b64 %0, {%1,%2};" : "=l"(C)  : "f"(c.x), "f"(c.y));
    asm("fma.rn.f32x2 %0, %1, %2, %3;" : "=l"(D) : "l"(A), "l"(Bv), "l"(C));
    float2 r;
    asm("mov.b64 {%0,%1}, %2;" : "=f"(r.x), "=f"(r.y) : "l"(D));
    return r;
}

// mov-free packed dual FMA: all operands already u64 register pairs
__device__ __forceinline__ unsigned long long fma2u(
    unsigned long long a, unsigned long long b, unsigned long long c) {
    unsigned long long d;
    asm("fma.rn.f32x2 %0, %1, %2, %3;" : "=l"(d) : "l"(a), "l"(b), "l"(c));
    return d;
}

__device__ __forceinline__ unsigned smem_u32(const void* p) {
    unsigned a;
    asm("{ .reg .u64 t; cvta.to.shared.u64 t, %1; cvt.u32.u64 %0, t; }" : "=r"(a) : "l"(p));
    return a;
}

// ---- async-copy / HMMA helpers ---------------------------------------------
#define SWZ(x) ((x) ^ (((x) >> 3) & 0x70))

#define CP_ASYNC16(dst, src) \
    asm volatile("cp.async.cg.shared.global [%0], [%1], 16;" :: "r"(dst), "l"(src) : "memory")
#define CP_COMMIT()  asm volatile("cp.async.commit_group;" ::: "memory")
#define CP_WAIT1()   asm volatile("cp.async.wait_group 1;" ::: "memory")
#define CP_WAIT0()   asm volatile("cp.async.wait_group 0;" ::: "memory")

#define LDSM_X4(r0, r1, r2, r3, addr) \
    asm volatile("ldmatrix.sync.aligned.m8n8.x4.shared.b16 {%0,%1,%2,%3}, [%4];" \
                 : "=r"(r0), "=r"(r1), "=r"(r2), "=r"(r3) : "r"(addr))

#define MMA16816(d, a, b0, b1) \
    asm volatile("mma.sync.aligned.m16n8k16.row.col.f32.bf16.bf16.f32 " \
                 "{%0,%1,%2,%3}, {%4,%5,%6,%7}, {%8,%9}, {%0,%1,%2,%3};" \
                 : "+f"((d)[0]), "+f"((d)[1]), "+f"((d)[2]), "+f"((d)[3]) \
                 : "r"((a)[0]), "r"((a)[1]), "r"((a)[2]), "r"((a)[3]), \
                   "r"(b0), "r"(b1))

// ===== Kernel WA: fused kW (blocks 0..2063) + kA (blocks 2064..2191) ========
#define KWA_NW (NPAR / 32)   // 2064

__global__ __launch_bounds__(256) void kWA(
    const float* __restrict__ Wout,
    const float* __restrict__ actions, const float* __restrict__ obs,
    const float* __restrict__ Wci, const float* __restrict__ vci,
    const float* __restrict__ gci, const float* __restrict__ bci,
    const float* __restrict__ Wcl, const float* __restrict__ bcl,
    const float* __restrict__ Win, const float* __restrict__ vin,
    const float* __restrict__ gin, const float* __restrict__ bin,
    const float* __restrict__ Wk)
{
    __shared__ float sm1[16 * 256];
    __shared__ float sm2[16 * 256];
    const int tid = threadIdx.x;

    if (blockIdx.x < KWA_NW) {
        // ------- kW part: transpose+split a 256k x 32n block -------
        float* sm = sm1;
        const int n0 = blockIdx.x * 32;
        #pragma unroll 4
        for (int it = 0; it < 32; it++) {
            const int idx = it * 256 + tid;
            const int k = idx >> 5, j = idx & 31;
            sm[j * 256 + (k ^ j)] = Wout[(size_t)k * NPAR + n0 + j];
        }
        __syncthreads();
        const int j  = tid & 31;
        const int kq = tid >> 5;
        __nv_bfloat16* ph = g_Bh + (size_t)(n0 + j) * 256 + kq * 32;
        __nv_bfloat16* pl = g_Bl + (size_t)(n0 + j) * 256 + kq * 32;
        #pragma unroll
        for (int kk = 0; kk < 32; kk++) {
            const float w = sm[j * 256 + ((kq * 32 + kk) ^ j)];
            const __nv_bfloat16 hi = __float2bfloat16(w);
            const __nv_bfloat16 lo = __float2bfloat16(w - __bfloat162float(hi));
            ph[kk] = hi;
            pl[kk] = lo;
        }
        return;
    }

    // ------- kA part -------
    const int r0 = (blockIdx.x - KWA_NW) * 16;

    { // t1 = actions @ Wci -> sm1[16][64]
        const int j = tid & 63, rr = tid >> 6;
        #pragma unroll
        for (int q = 0; q < 4; q++) {
            const int r = rr + q * 4;
            float acc = 0.f;
            #pragma unroll
            for (int k = 0; k < 16; k++)
                acc += actions[(r0 + r) * 16 + k] * Wci[k * 64 + j];
            sm1[r * 64 + j] = acc;
        }
    }
    __syncthreads();
    { // evonorm(groups=8) -> sm2[16][64]
        const int j = tid & 63, rr = tid >> 6;
        const float v = vci[j], g = gci[j], bb = bci[j];
        #pragma unroll
        for (int q = 0; q < 4; q++) {
            const int r = rr + q * 4;
            const float* row = &sm1[r * 64 + (j & ~7)];
            float s1 = 0.f, s2 = 0.f;
            #pragma unroll
            for (int e = 0; e < 8; e++) { float t = row[e]; s1 += t; s2 += t * t; }
            const float mean = s1 * 0.125f;
            const float var  = s2 * 0.125f - mean * mean;
            const float x = sm1[r * 64 + j];
            sm2[r * 64 + j] = x * sigf(v * x) * rsqrtf(var + 1e-5f) * g + bb;
        }
    }
    __syncthreads();
    { // x = a1 @ Wcl + bcl + obs -> sm1[16][64]
        const int j = tid & 63, rr = tid >> 6;
        const float bj = bcl[j];
        float acc[4];
        #pragma unroll
        for (int q = 0; q < 4; q++)
            acc[q] = bj + obs[(r0 + rr + q * 4) * 64 + j];
        for (int k = 0; k < 64; k++) {
            const float w = Wcl[k * 64 + j];
            #pragma unroll
            for (int q = 0; q < 4; q++)
                acc[q] += sm2[(rr + q * 4) * 64 + k] * w;
        }
        #pragma unroll
        for (int q = 0; q < 4; q++)
            sm1[(rr + q * 4) * 64 + j] = acc[q];
    }
    __syncthreads();
    { // t2 = x @ Win -> sm2[16][256]
        const int j = tid;
        float acc[16];
        #pragma unroll
        for (int r = 0; r < 16; r++) acc[r] = 0.f;
        for (int k = 0; k < 64; k++) {
            const float w = Win[k * 256 + j];
            #pragma unroll
            for (int r = 0; r < 16; r++) acc[r] += sm1[r * 64 + k] * w;
        }
        #pragma unroll
        for (int r = 0; r < 16; r++) sm2[r * 256 + j] = acc[r];
    }
    __syncthreads();
    { // evonorm(group size 8) -> sm1[16][256]
        const int j = tid;
        const float v = vin[j], g = gin[j], bb = bin[j];
        for (int r = 0; r < 16; r++) {
            const float* row = &sm2[r * 256 + (j & ~7)];
            float s1 = 0.f, s2 = 0.f;
            #pragma unroll
            for (int e = 0; e < 8; e++) { float t = row[e]; s1 += t; s2 += t * t; }
            const float mean = s1 * 0.125f;
            const float var  = s2 * 0.125f - mean * mean;
            const float x = sm2[r * 256 + j];
            sm1[r * 256 + j] = x * sigf(v * x) * rsqrtf(var + 1e-5f) * g + bb;
        }
    }
    __syncthreads();
    { // G = x_in @ Wk  (thread: 4 cols x 16 rows)
        const int c0 = tid * 4;
        float2 acc[16][2];
        #pragma unroll
        for (int r = 0; r < 16; r++) { acc[r][0] = make_float2(0.f,0.f); acc[r][1] = make_float2(0.f,0.f); }
        for (int k = 0; k < 256; k++) {
            const float4 w4 = *(const float4*)&Wk[k * 1024 + c0];
            const float2 wa = make_float2(w4.x, w4.y);
            const float2 wb = make_float2(w4.z, w4.w);
            #pragma unroll
            for (int r = 0; r < 16; r++) {
                const float x = sm1[r * 256 + k];
                const float2 xx = make_float2(x, x);
                acc[r][0] = fma2(wa, xx, acc[r][0]);
                acc[r][1] = fma2(wb, xx, acc[r][1]);
            }
        }
        #pragma unroll
        for (int r = 0; r < 16; r++) {
            float4 o;
            o.x = acc[r][0].x; o.y = acc[r][0].y; o.z = acc[r][1].x; o.w = acc[r][1].y;
            *(float4*)&g_G[(size_t)(r0 + r) * 1024 + c0] = o;
        }
    }
}

// ===== Kernel B: sequential LSTM, 8-CTA cluster =============================
__global__ void __launch_bounds__(512, 1) __cluster_dims__(8, 1, 1)
kB(const float* __restrict__ Wr, const float* __restrict__ vl_,
   const float* __restrict__ gl_, const float* __restrict__ bl_)
{
    __shared__ __align__(16) float s_hb[2][256];        // h buffers (remote-written)
    __shared__ __align__(16) float s_part[2][16 * 128]; // GEMV partials, 2x8KB
    __shared__ __align__(16) float s_z[128];
    __shared__ __align__(16) float s_hout[32];
    __shared__ __align__(8)  unsigned long long s_mbar[2];

    const int tid = threadIdx.x;
    unsigned rank;
    asm("mov.u32 %0, %%cluster_ctarank;" : "=r"(rank));

    const int g   = tid & 31;        // col-group: cols [g*4, g*4+4)
    const int kw  = tid >> 5;        // k-window:  k    [kw*16, kw*16+16)
    const int gg  = g >> 3;          // gate 0..3
    const int cc0 = (g & 7) * 4;     // channel base within this CTA's 32
    const int gcol0 = gg * 256 + (int)rank * 32 + cc0;   // global col of c=0
    const int k0    = kw * 16;

    // register-resident weights, packed as (k, k+1) pairs per column: u64
    unsigned long long wv[4][8];
    #pragma unroll
    for (int p = 0; p < 8; p++) {
        #pragma unroll
        for (int c = 0; c < 4; c++) {
            const float w0 = Wr[(size_t)(k0 + 2*p)     * 1024 + gcol0 + c];
            const float w1 = Wr[(size_t)(k0 + 2*p + 1) * 1024 + gcol0 + c];
            asm("mov.b64 %0, {%1,%2};" : "=l"(wv[c][p]) : "f"(w0), "f"(w1));
        }
    }

    // cell params for warp 0 (channel ch = rank*32 + lane)
    float vl = 0.f, gl = 0.f, bl = 0.f, cst = 0.f;
    if (tid < 32) {
        const int ch = (int)rank * 32 + tid;
        vl = vl_[ch]; gl = gl_[ch]; bl = bl_[ch];
    }

    // push addresses for warp0 lanes 0-7 (lane = dest CTA)
    unsigned r_h0 = 0, r_h1 = 0, r_b0 = 0, r_b1 = 0;
    if (tid < 8) {
        const unsigned d = (unsigned)tid;
        unsigned lh0 = smem_u32(&s_hb[0][rank * 32]);
        unsigned lh1 = smem_u32(&s_hb[1][rank * 32]);
        unsigned lb0 = smem_u32(&s_mbar[0]);
        unsigned lb1 = smem_u32(&s_mbar[1]);
        asm("mapa.shared::cluster.u32 %0, %1, %2;" : "=r"(r_h0) : "r"(lh0), "r"(d));
        asm("mapa.shared::cluster.u32 %0, %1, %2;" : "=r"(r_h1) : "r"(lh1), "r"(d));
        asm("mapa.shared::cluster.u32 %0, %1, %2;" : "=r"(r_b0) : "r"(lb0), "r"(d));
        asm("mapa.shared::cluster.u32 %0, %1, %2;" : "=r"(r_b1) : "r"(lb1), "r"(d));
    }

    if (tid == 0) {
        asm volatile("mbarrier.init.shared.b64 [%0], %1;" :: "r"(smem_u32(&s_mbar[0])), "r"(8u) : "memory");
        asm volatile("mbarrier.init.shared.b64 [%0], %1;" :: "r"(smem_u32(&s_mbar[1])), "r"(8u) : "memory");
    }
    if (tid < 256) { s_hb[0][tid] = 0.f; s_hb[1][tid] = 0.f; }
    __syncthreads();
    asm volatile("barrier.cluster.arrive.aligned;" ::: "memory");
    asm volatile("barrier.cluster.wait.aligned;"   ::: "memory");

    // initial push: zeros (h_{-1}) into buffer 1
    if (tid < 8) {
        #pragma unroll
        for (int i = 0; i < 8; i++)
            asm volatile("st.shared::cluster.v4.f32 [%0], {%1,%1,%1,%1};"
                         :: "r"(r_h1 + i * 16), "f"(0.f) : "memory");
        asm volatile("mbarrier.arrive.release.cluster.shared::cluster.b64 _, [%0];"
                     :: "r"(r_b1) : "memory");
    }

    unsigned par0 = 0u, par1 = 0u;

    // prefetch gate term for step 0 (phase-2 threads)
    const int gcol2 = (tid >> 5) * 256 + (int)rank * 32 + (tid & 31);
    float gt = (tid < 128) ? g_G[gcol2] : 0.f;

    for (int t = 0; t < NB; t++) {
        const int rb = (t + 1) & 1;      // buffer holding h_{t-1}
        const int wb = t & 1;            // buffer receiving h_t
        const int pp = t & 1;            // s_part parity

        { // wait for all 8 source-CTA pushes of h_{t-1}
            const unsigned a = smem_u32(&s_mbar[rb]);
            const unsigned ph = rb ? par1 : par0;
            unsigned done;
            asm volatile(
                "{\n\t.reg .pred p;\n\t"
                "mbarrier.try_wait.parity.acquire.cluster.shared::cta.b64 p, [%1], %2;\n\t"
                "selp.b32 %0, 1, 0, p;\n\t}"
                : "=r"(done) : "r"(a), "r"(ph) : "memory");
            if (!done) {
                asm volatile(
                    "{\n\t.reg .pred P1;\n\t"
                    "WLB_%=:\n\t"
                    "mbarrier.try_wait.parity.acquire.cluster.shared::cta.b64 P1, [%0], %1, 0x989680;\n\t"
                    "@P1 bra.uni WDB_%=;\n\t"
                    "bra.uni WLB_%=;\n\t"
                    "WDB_%=:\n\t}"
                    :: "r"(a), "r"(ph) : "memory");
            }
            if (rb) par1 ^= 1u; else par0 ^= 1u;
        }

        // ---- GEMV phase 1: 4 cols x 16 k per thread, packed f32x2 ----
        {
            const unsigned long long* hp =
                (const unsigned long long*)&s_hb[rb][k0];
            unsigned long long a0 = 0ULL, a1 = 0ULL, a2 = 0ULL, a3 = 0ULL;
            #pragma unroll
            for (int p = 0; p < 8; p++) {
                const unsigned long long h2 = hp[p];
                a0 = fma2u(wv[0][p], h2, a0);
                a1 = fma2u(wv[1][p], h2, a1);
                a2 = fma2u(wv[2][p], h2, a2);
                a3 = fma2u(wv[3][p], h2, a3);
            }
            float2 f0, f1, f2, f3;
            asm("mov.b64 {%0,%1}, %2;" : "=f"(f0.x), "=f"(f0.y) : "l"(a0));
            asm("mov.b64 {%0,%1}, %2;" : "=f"(f1.x), "=f"(f1.y) : "l"(a1));
            asm("mov.b64 {%0,%1}, %2;" : "=f"(f2.x), "=f"(f2.y) : "l"(a2));
            asm("mov.b64 {%0,%1}, %2;" : "=f"(f3.x), "=f"(f3.y) : "l"(a3));
            float4 p4;
            p4.x = f0.x + f0.y; p4.y = f1.x + f1.y;
            p4.z = f2.x + f2.y; p4.w = f3.x + f3.y;
            *(float4*)&s_part[pp][kw * 128 + g * 4] = p4;
        }
        __syncthreads();   // all 512: partials of step t visible

        // ---- phase2 + cell: warps 0-3 only; warps 4-15 go to next wait ----
        if (tid < 128) {
            float v[16];
            #pragma unroll
            for (int k2 = 0; k2 < 16; k2++)
                v[k2] = s_part[pp][k2 * 128 + tid];
            const float s =
                (((v[0] + v[1]) + (v[2] + v[3])) + ((v[4] + v[5]) + (v[6] + v[7]))) +
                (((v[8] + v[9]) + (v[10] + v[11])) + ((v[12] + v[13]) + (v[14] + v[15]))) + gt;
            s_z[tid] = s;
            if (t + 1 < NB) gt = g_G[(size_t)(t + 1) * 1024 + gcol2];

            asm volatile("bar.sync 1, 128;" ::: "memory");

            if (tid < 32) {
                const float zi = s_z[tid];
                const float zf = s_z[32 + tid];
                const float zc = s_z[64 + tid];
                const float zo = s_z[96 + tid];

                float s1 = zc, s2 = zc * zc;
                s1 += __shfl_xor_sync(0xffffffffu, s1, 1);  s2 += __shfl_xor_sync(0xffffffffu, s2, 1);
                s1 += __shfl_xor_sync(0xffffffffu, s1, 2);  s2 += __shfl_xor_sync(0xffffffffu, s2, 2);
                s1 += __shfl_xor_sync(0xffffffffu, s1, 4);  s2 += __shfl_xor_sync(0xffffffffu, s2, 4);
                float mean = s1 * 0.125f;
                float var  = s2 * 0.125f - mean * mean;
                const float ecc = zc * sigf(vl * zc) * rsqrtf(var + 1e-5f) * gl + bl;

                cst = sigf(zf) * cst + sigf(zi) * ecc;

                s1 = cst; s2 = cst * cst;
                s1 += __shfl_xor_sync(0xffffffffu, s1, 1);  s2 += __shfl_xor_sync(0xffffffffu, s2, 1);
                s1 += __shfl_xor_sync(0xffffffffu, s1, 2);  s2 += __shfl_xor_sync(0xffffffffu, s2, 2);
                s1 += __shfl_xor_sync(0xffffffffu, s1, 4);  s2 += __shfl_xor_sync(0xffffffffu, s2, 4);
                mean = s1 * 0.125f;
                var  = s2 * 0.125f - mean * mean;
                const float ecn = cst * sigf(vl * cst) * rsqrtf(var + 1e-5f) * gl + bl;

                const float h = sigf(zo) * ecn;
                s_hout[tid] = h;
                __syncwarp();

                // push h_t: lane d -> dest CTA d (8 x st.v4 + 1 release-arrive)
                if (tid < 8) {
                    const unsigned rh  = wb ? r_h1 : r_h0;
                    const unsigned rbb = wb ? r_b1 : r_b0;
                    #pragma unroll
                    for (int i = 0; i < 8; i++) {
                        const float4 hv4 = *(const float4*)&s_hout[i * 4];
                        asm volatile("st.shared::cluster.v4.f32 [%0], {%1,%2,%3,%4};"
                                     :: "r"(rh + i * 16), "f"(hv4.x), "f"(hv4.y), "f"(hv4.z), "f"(hv4.w)
                                     : "memory");
                    }
                    asm volatile("mbarrier.arrive.release.cluster.shared::cluster.b64 _, [%0];"
                                 :: "r"(rbb) : "memory");
                }
                g_H[(size_t)t * 256 + rank * 32 + tid] = h;
            }
        }
    }

    asm volatile("barrier.cluster.arrive.aligned;" ::: "memory");
    asm volatile("barrier.cluster.wait.aligned;"   ::: "memory");
}

// ===== Kernel C: dense_0 + evonorm -> bf16 hi/lo split (g_Ah/g_Al) ==========
__global__ __launch_bounds__(256) void kC(
    const float* __restrict__ Wd0, const float* __restrict__ vd,
    const float* __restrict__ gd,  const float* __restrict__ bd)
{
    __shared__ float sm1[16 * 256];
    __shared__ float sm2[16 * 256];
    const int tid = threadIdx.x;
    const int r0  = blockIdx.x * 16;

    const float4* src = (const float4*)(g_H + (size_t)r0 * 256);
    for (int i = tid; i < 1024; i += 256)
        ((float4*)sm1)[i] = src[i];
    __syncthreads();

    const int j = tid;
    float acc[16];
    #pragma unroll
    for (int r = 0; r < 16; r++) acc[r] = 0.f;
    for (int k4 = 0; k4 < 64; k4++) {
        const int k = k4 * 4;
        const float w0 = Wd0[(k+0)*256 + j];
        const float w1 = Wd0[(k+1)*256 + j];
        const float w2 = Wd0[(k+2)*256 + j];
        const float w3 = Wd0[(k+3)*256 + j];
        #pragma unroll
        for (int r = 0; r < 16; r++) {
            const float4 x = *(const float4*)&sm1[r * 256 + k];
            acc[r] += x.x*w0 + x.y*w1 + x.z*w2 + x.w*w3;
        }
    }
    #pragma unroll
    for (int r = 0; r < 16; r++) sm2[r * 256 + j] = acc[r];
    __syncthreads();

    const float v = vd[j], g = gd[j], bb = bd[j];
    for (int r = 0; r < 16; r++) {
        const float* row = &sm2[r * 256 + (j & ~7)];
        float s1 = 0.f, s2 = 0.f;
        #pragma unroll
        for (int e = 0; e < 8; e++) { float t = row[e]; s1 += t; s2 += t * t; }
        const float mean = s1 * 0.125f;
        const float var  = s2 * 0.125f - mean * mean;
        const float x = sm2[r * 256 + j];
        const float y = x * sigf(v * x) * rsqrtf(var + 1e-5f) * g + bb;
        const __nv_bfloat16 hi = __float2bfloat16(y);
        const __nv_bfloat16 lo = __float2bfloat16(y - __bfloat162float(hi));
        g_Ah[(size_t)(r0 + r) * 256 + j] = hi;
        g_Al[(size_t)(r0 + r) * 256 + j] = lo;
    }
}

// ===== Kernel D: HMMA bf16 3-split GEMM, B smem-resident, A streamed ========
// CTA owns a 128-col B slice (all K, 4 chunk-blocks of 32KB = 128KB smem) and
// computes 8 row tiles of 128 rows, streaming A chunks (32KB, double-buffered).
// Grid: x = 2 row halves, y = 516 col tiles.
#define KDB_SZ    131072               // B region: 4 chunk-blocks x 32KB
#define KDA_STAGE 32768                // A stage: Ah 16KB + Al 16KB
#define KD_SMEM   (KDB_SZ + 2 * KDA_STAGE)   // 196608

__device__ __forceinline__ void kd_loadB(uint32_t SB, int n0, int tid)
{
    #pragma unroll
    for (int c = 0; c < 4; c++) {
        #pragma unroll
        for (int sp = 0; sp < 2; sp++) {
            const __nv_bfloat16* gB = sp ? g_Bl : g_Bh;
            const uint32_t db = SB + c * 32768u + sp * 16384u;
            #pragma unroll
            for (int i = 0; i < 4; i++) {
                const int g2 = tid + i * 256;
                const int row = g2 >> 3, j = g2 & 7;
                CP_ASYNC16(db + SWZ(row * 128 + j * 16),
                           gB + (size_t)(n0 + row) * 256 + c * 64 + j * 8);
            }
        }
    }
    CP_COMMIT();
}

__device__ __forceinline__ void kd_loadA(uint32_t stage, int m0, int koff, int tid)
{
    #pragma unroll
    for (int sp = 0; sp < 2; sp++) {
        const __nv_bfloat16* gA = sp ? g_Al : g_Ah;
        const uint32_t db = stage + sp * 16384u;
        #pragma unroll
        for (int i = 0; i < 4; i++) {
            const int g2 = tid + i * 256;
            const int row = g2 >> 3, j = g2 & 7;
            CP_ASYNC16(db + SWZ(row * 128 + j * 16),
                       gA + (size_t)(m0 + row) * 256 + koff + j * 8);
        }
    }
    CP_COMMIT();
}

__device__ __forceinline__ void kd_compute(uint32_t Astage, uint32_t SB, int blk,
                                           uint32_t a_row, uint32_t a_kb,
                                           uint32_t b_row, uint32_t b_kb,
                                           float acc[4][4][4])
{
    #pragma unroll
    for (int split = 0; split < 3; split++) {
        const uint32_t Abase = Astage + (split == 2 ? 16384u : 0u);
        const uint32_t Bbase = SB + blk * 32768u + (split == 1 ? 16384u : 0u);
        #pragma unroll
        for (int ks = 0; ks < 4; ks++) {
            const uint32_t kk2 = (uint32_t)ks * 32;
            uint32_t af[4][4];
            #pragma unroll
            for (int mb = 0; mb < 4; mb++) {
                const uint32_t addr = Abase + SWZ((a_row + mb * 16) * 128 + kk2 + a_kb);
                LDSM_X4(af[mb][0], af[mb][1], af[mb][2], af[mb][3], addr);
            }
            uint32_t bfr[2][4];
            #pragma unroll
            for (int nb2 = 0; nb2 < 2; nb2++) {
                const uint32_t addr = Bbase + SWZ((b_row + nb2 * 16) * 128 + kk2 + b_kb);
                LDSM_X4(bfr[nb2][0], bfr[nb2][1], bfr[nb2][2], bfr[nb2][3], addr);
            }
            #pragma unroll
            for (int mb = 0; mb < 4; mb++) {
                MMA16816(acc[mb][0], af[mb], bfr[0][0], bfr[0][1]);
                MMA16816(acc[mb][1], af[mb], bfr[0][2], bfr[0][3]);
                MMA16816(acc[mb][2], af[mb], bfr[1][0], bfr[1][1]);
                MMA16816(acc[mb][3], af[mb], bfr[1][2], bfr[1][3]);
            }
        }
    }
}

__global__ void __launch_bounds__(256)
kD(const float* __restrict__ bout, float* __restrict__ out)
{
    extern __shared__ __align__(1024) char smem[];
    const uint32_t SB  = smem_u32(smem);
    const uint32_t SA0 = SB + KDB_SZ;
    const uint32_t SA1 = SA0 + KDA_STAGE;
    const int tid = threadIdx.x;
    const int wid = tid >> 5, lane = tid & 31;
    const int warp_m = wid & 1;
    const int warp_n = wid >> 1;
    const int n0 = blockIdx.y * 128;

    const uint32_t a_row = warp_m * 64 + (lane & 15);
    const uint32_t a_kb  = (uint32_t)(lane >> 4) * 16;
    const uint32_t b_row = warp_n * 32 + (lane & 7) + ((lane >> 4) & 1) * 8;
    const uint32_t b_kb  = (uint32_t)((lane >> 3) & 1) * 16;

    kd_loadB(SB, n0, tid);    // group B outstanding

    for (int r = 0; r < 8; r++) {
        const int m0 = (blockIdx.x * 8 + r) * 128;

        float acc[4][4][4];
        #pragma unroll
        for (int i = 0; i < 4; i++)
            #pragma unroll
            for (int j = 0; j < 4; j++)
                #pragma unroll
                for (int q = 0; q < 4; q++) acc[i][j][q] = 0.f;

        kd_loadA(SA0, m0, 0,  tid);
        kd_loadA(SA1, m0, 64, tid);
        CP_WAIT1();  __syncthreads();      // B (r==0) + A0 complete
        kd_compute(SA0, SB, 0, a_row, a_kb, b_row, b_kb, acc);
        __syncthreads();                   // SA0 free
        kd_loadA(SA0, m0, 128, tid);
        CP_WAIT1();  __syncthreads();      // A1 complete
        kd_compute(SA1, SB, 1, a_row, a_kb, b_row, b_kb, acc);
        __syncthreads();                   // SA1 free
        kd_loadA(SA1, m0, 192, tid);
        CP_WAIT1();  __syncthreads();      // A2 complete
        kd_compute(SA0, SB, 2, a_row, a_kb, b_row, b_kb, acc);
        CP_WAIT0();  __syncthreads();      // A3 complete
        kd_compute(SA1, SB, 3, a_row, a_kb, b_row, b_kb, acc);
        __syncthreads();                   // stages free for next tile

        // ---- epilogue: direct float2 stores + bias ----
        #pragma unroll
        for (int nb = 0; nb < 4; nb++) {
            const int col = n0 + warp_n * 32 + nb * 8 + (lane & 3) * 2;
            const float2 bb = *(const float2*)&bout[col];
            #pragma unroll
            for (int mb = 0; mb < 4; mb++) {
                const int row = m0 + warp_m * 64 + mb * 16 + (lane >> 2);
                float2 v0, v1;
                v0.x = acc[mb][nb][0] + bb.x;  v0.y = acc[mb][nb][1] + bb.y;
                v1.x = acc[mb][nb][2] + bb.x;  v1.y = acc[mb][nb][3] + bb.y;
                *(float2*)&out[(size_t)row * NPAR + col]       = v0;
                *(float2*)&out[(size_t)(row + 8) * NPAR + col] = v1;
            }
        }
    }
}

// ============================================================================
extern "C" void kernel_launch(void* const* d_in, const int* in_sizes, int n_in,
                              void* d_out, int out_size)
{
    const float* actions = (const float*)d_in[0];
    const float* obs     = (const float*)d_in[1];
    const float* Wci     = (const float*)d_in[2];
    const float* vci     = (const float*)d_in[3];
    const float* gci     = (const float*)d_in[4];
    const float* bci     = (const float*)d_in[5];
    const float* Wcl     = (const float*)d_in[6];
    const float* bcl     = (const float*)d_in[7];
    const float* Win     = (const float*)d_in[8];
    const float* vin     = (const float*)d_in[9];
    const float* gin     = (const float*)d_in[10];
    const float* bin     = (const float*)d_in[11];
    const float* Wk      = (const float*)d_in[12];
    const float* Wr      = (const float*)d_in[13];
    const float* vl      = (const float*)d_in[14];
    const float* gl      = (const float*)d_in[15];
    const float* bl      = (const float*)d_in[16];
    const float* Wd0     = (const float*)d_in[17];
    const float* vd0     = (const float*)d_in[18];
    const float* gd0     = (const float*)d_in[19];
    const float* bd0     = (const float*)d_in[20];
    const float* Wout    = (const float*)d_in[21];
    const float* bout    = (const float*)d_in[22];
    float* out = (float*)d_out;

    kWA<<<KWA_NW + 128, 256>>>(Wout, actions, obs, Wci, vci, gci, bci, Wcl, bcl,
                               Win, vin, gin, bin, Wk);
    kB<<<8, 512>>>(Wr, vl, gl, bl);
    kC<<<128, 256>>>(Wd0, vd0, gd0, bd0);

    cudaFuncSetAttribute(kD, cudaFuncAttributeMaxDynamicSharedMemorySize, KD_SMEM);
    dim3 gD(2, NPAR / 128);   // x = row halves, y = col tiles (516)
    kD<<<gD, 256, KD_SMEM>>>(bout, out);
}